// round 1
// baseline (speedup 1.0000x reference)
#include <cuda_runtime.h>
#include <math.h>

#define N_NODES 2000
#define NUM_KP 500
#define DESC 256
#define NVK 64
#define VLAD_DIM (DESC*NVK)        // 16384
#define H0D (NUM_KP*2)             // 1000
#define H1D NUM_KP                 // 500
#define NODE_D 128
#define EDGE_D 32
#define N_EDGES 64000
#define E_EXT (N_EDGES + N_NODES)  // 66000
#define DEPTH 3

// ---------------- scratch (device globals; no runtime allocation) ----------
__device__ float    g_vlad[(size_t)N_NODES * VLAD_DIM];   // 131 MB
__device__ float    g_h0[N_NODES * H0D];
__device__ float    g_h1[N_NODES * H1D];
__device__ float    g_x[N_NODES * NODE_D];
__device__ float    g_h[N_NODES * NODE_D];
__device__ float    g_es[N_NODES];
__device__ float    g_ed[N_NODES];
__device__ float    g_eval[E_EXT];
__device__ float    g_ex[E_EXT];
__device__ unsigned g_emax[N_NODES];
__device__ float    g_den[N_NODES];
__device__ float    g_aggr[N_NODES * NODE_D];
__device__ float    g_ef2[N_EDGES * EDGE_D];

// monotonic float <-> uint mapping for atomicMax on floats (handles negatives)
__device__ __forceinline__ unsigned fkey(float f) {
    unsigned u = __float_as_uint(f);
    return u ^ ((u >> 31) ? 0xFFFFFFFFu : 0x80000000u);
}
__device__ __forceinline__ float funkey(unsigned u) {
    return __uint_as_float(u ^ ((u & 0x80000000u) ? 0x80000000u : 0xFFFFFFFFu));
}

// ---------------------------------------------------------------------------
// Fused NetVLAD: one CTA per node. cw + vlad accumulator register-resident.
// thread t: k = t&63, dgroup = t>>6 (64 d-values each).
// ---------------------------------------------------------------------------
__global__ void __launch_bounds__(256, 1) k_netvlad(
    const float* __restrict__ feats,
    const float* __restrict__ cw,   // [256,64]
    const float* __restrict__ cb,   // [64]
    const float* __restrict__ cw2)  // [1,256,64]
{
    int b = blockIdx.x;
    int t = threadIdx.x;
    int k = t & 63;
    int dg = t >> 6;

    __shared__ float xs[DESC];
    __shared__ float part[256];
    __shared__ float act_s[64];
    __shared__ float actsum_s[64];
    __shared__ float red_s[64];

    float cwreg[64];
#pragma unroll
    for (int j = 0; j < 64; j++) cwreg[j] = cw[(dg * 64 + j) * 64 + k];
    float vreg[64];
#pragma unroll
    for (int j = 0; j < 64; j++) vreg[j] = 0.f;
    if (t < 64) actsum_s[t] = 0.f;

    float cb0 = 0.f, cb1 = 0.f;
    if (t < 32) { cb0 = cb[t]; cb1 = cb[t + 32]; }

    const float* xb = feats + (size_t)b * NUM_KP * DESC;
    __syncthreads();

    for (int n = 0; n < NUM_KP; n++) {
        float v = xb[(size_t)n * DESC + t];
        if (!isfinite(v)) v = (v != v) ? 0.f : (v > 0.f ? 3.402823466e38f : -3.402823466e38f);
        xs[t] = v;
        __syncthreads();

        float p = 0.f;
#pragma unroll
        for (int j = 0; j < 64; j++) p = fmaf(xs[dg * 64 + j], cwreg[j], p);
        part[t] = p;
        __syncthreads();

        if (t < 32) {
            float l0 = part[t]       + part[64 + t]  + part[128 + t] + part[192 + t] + cb0;
            float l1 = part[t + 32]  + part[96 + t]  + part[160 + t] + part[224 + t] + cb1;
            float m = fmaxf(l0, l1);
#pragma unroll
            for (int off = 16; off; off >>= 1) m = fmaxf(m, __shfl_xor_sync(0xFFFFFFFFu, m, off));
            float e0 = expf(l0 - m), e1 = expf(l1 - m);
            float s = e0 + e1;
#pragma unroll
            for (int off = 16; off; off >>= 1) s += __shfl_xor_sync(0xFFFFFFFFu, s, off);
            float inv = 1.f / s;
            e0 *= inv; e1 *= inv;
            act_s[t] = e0; act_s[t + 32] = e1;
            actsum_s[t] += e0; actsum_s[t + 32] += e1;
        }
        __syncthreads();

        float a = act_s[k];
#pragma unroll
        for (int j = 0; j < 64; j++) vreg[j] = fmaf(a, xs[dg * 64 + j], vreg[j]);
        __syncthreads();   // protect xs before next iteration's store
    }

    // epilogue: subtract a-term, intra-norm over D, full norm, store
    float asum = actsum_s[k];
    float n2 = 0.f;
#pragma unroll
    for (int j = 0; j < 64; j++) {
        int d = dg * 64 + j;
        float v = vreg[j] - asum * cw2[d * 64 + k];
        vreg[j] = v;
        n2 = fmaf(v, v, n2);
    }
    part[t] = n2;
    __syncthreads();
    if (t < 64) red_s[t] = sqrtf(part[t] + part[64 + t] + part[128 + t] + part[192 + t]) + 1e-12f;
    __syncthreads();
    float invc = 1.f / red_s[k];
    float tot = 0.f;
#pragma unroll
    for (int j = 0; j < 64; j++) { vreg[j] *= invc; tot = fmaf(vreg[j], vreg[j], tot); }
    part[t] = tot;
    __syncthreads();
    if (t < 32) {
        float s = 0.f;
#pragma unroll
        for (int i = 0; i < 8; i++) s += part[t + 32 * i];
#pragma unroll
        for (int off = 16; off; off >>= 1) s += __shfl_xor_sync(0xFFFFFFFFu, s, off);
        if (t == 0) red_s[0] = 1.f / (sqrtf(s) + 1e-12f);
    }
    __syncthreads();
    float invt = red_s[0];
    float* ov = g_vlad + (size_t)b * VLAD_DIM;
#pragma unroll
    for (int j = 0; j < 64; j++) ov[(dg * 64 + j) * 64 + k] = vreg[j] * invt;
}

// ---------------------------------------------------------------------------
// Generic SGEMM: C[M,N] = act(A[M,K] @ B[K,N] + bias). 64x64x16 tiles, 4x4/thr.
// act: 0 = none, 1 = relu
// ---------------------------------------------------------------------------
__global__ void __launch_bounds__(256) k_sgemm(
    const float* __restrict__ A, const float* __restrict__ B,
    const float* __restrict__ bias, float* __restrict__ C,
    int M, int N, int K, int act)
{
    __shared__ __align__(16) float As[16][64];
    __shared__ __align__(16) float Bs[16][64];

    int tid = threadIdx.x;
    int tx = tid & 15, ty = tid >> 4;
    int row0 = blockIdx.y * 64, col0 = blockIdx.x * 64;

    float c[4][4];
#pragma unroll
    for (int i = 0; i < 4; i++)
#pragma unroll
        for (int j = 0; j < 4; j++) c[i][j] = 0.f;

    int am = tid >> 2;           // 0..63
    int ak = (tid & 3) * 4;      // 0,4,8,12
    int bk = tid >> 4;           // 0..15
    int bn = (tid & 15) * 4;     // 0..60

    for (int k0 = 0; k0 < K; k0 += 16) {
        // load A tile (transposed into As[k][m])
        int arow = row0 + am;
        if (arow < M && k0 + ak + 3 < K) {
            float4 v = *reinterpret_cast<const float4*>(&A[(size_t)arow * K + k0 + ak]);
            As[ak + 0][am] = v.x; As[ak + 1][am] = v.y;
            As[ak + 2][am] = v.z; As[ak + 3][am] = v.w;
        } else {
#pragma unroll
            for (int i = 0; i < 4; i++) {
                int kk = k0 + ak + i;
                As[ak + i][am] = (arow < M && kk < K) ? A[(size_t)arow * K + kk] : 0.f;
            }
        }
        // load B tile
        int brow = k0 + bk;
        if (brow < K && col0 + bn + 3 < N) {
            float4 v = *reinterpret_cast<const float4*>(&B[(size_t)brow * N + col0 + bn]);
            *reinterpret_cast<float4*>(&Bs[bk][bn]) = v;
        } else {
#pragma unroll
            for (int i = 0; i < 4; i++) {
                int nn = col0 + bn + i;
                Bs[bk][bn + i] = (brow < K && nn < N) ? B[(size_t)brow * N + nn] : 0.f;
            }
        }
        __syncthreads();
#pragma unroll
        for (int kk = 0; kk < 16; kk++) {
            float4 av = *reinterpret_cast<const float4*>(&As[kk][ty * 4]);
            float4 bv = *reinterpret_cast<const float4*>(&Bs[kk][tx * 4]);
            float a[4] = {av.x, av.y, av.z, av.w};
            float bb[4] = {bv.x, bv.y, bv.z, bv.w};
#pragma unroll
            for (int i = 0; i < 4; i++)
#pragma unroll
                for (int j = 0; j < 4; j++) c[i][j] = fmaf(a[i], bb[j], c[i][j]);
        }
        __syncthreads();
    }

#pragma unroll
    for (int i = 0; i < 4; i++) {
        int r = row0 + ty * 4 + i;
        if (r >= M) continue;
#pragma unroll
        for (int j = 0; j < 4; j++) {
            int cc = col0 + tx * 4 + j;
            if (cc >= N) continue;
            float v = c[i][j];
            if (bias) v += bias[cc];
            if (act == 1) v = fmaxf(v, 0.f);
            C[(size_t)r * N + cc] = v;
        }
    }
}

// ---------------------------------------------------------------------------
// GAT: h = x@W, es = h . a_s, ed = h . a_d.  One CTA per node, 128 threads.
// ---------------------------------------------------------------------------
__global__ void __launch_bounds__(128) k_gat_h(
    const float* __restrict__ W, const float* __restrict__ a_s,
    const float* __restrict__ a_d)
{
    int b = blockIdx.x, t = threadIdx.x;
    __shared__ float xsm[NODE_D];
    __shared__ float rs[8];
    xsm[t] = g_x[b * NODE_D + t];
    __syncthreads();
    float acc = 0.f;
#pragma unroll 8
    for (int d = 0; d < NODE_D; d++) acc = fmaf(xsm[d], __ldg(&W[d * NODE_D + t]), acc);
    g_h[b * NODE_D + t] = acc;
    float ps = acc * __ldg(&a_s[t]);
    float pd = acc * __ldg(&a_d[t]);
#pragma unroll
    for (int off = 16; off; off >>= 1) {
        ps += __shfl_xor_sync(0xFFFFFFFFu, ps, off);
        pd += __shfl_xor_sync(0xFFFFFFFFu, pd, off);
    }
    if ((t & 31) == 0) { rs[t >> 5] = ps; rs[4 + (t >> 5)] = pd; }
    __syncthreads();
    if (t == 0) g_es[b] = rs[0] + rs[1] + rs[2] + rs[3];
    if (t == 1) g_ed[b] = rs[4] + rs[5] + rs[6] + rs[7];
}

__global__ void k_init()
{
    int i = blockIdx.x * blockDim.x + threadIdx.x;
    if (i < N_NODES) { g_emax[i] = 0u; g_den[i] = 0.f; }
    if (i < N_NODES * NODE_D) g_aggr[i] = 0.f;
}

__global__ void k_edge1(const int* __restrict__ ei)
{
    int e = blockIdx.x * blockDim.x + threadIdx.x;
    if (e >= E_EXT) return;
    int s, d;
    if (e < N_EDGES) { s = ei[e]; d = ei[N_EDGES + e]; }
    else { s = e - N_EDGES; d = s; }
    float v = g_es[s] + g_ed[d];
    v = (v > 0.f) ? v : 0.2f * v;      // leaky_relu(., 0.2)
    g_eval[e] = v;
    atomicMax(&g_emax[d], fkey(v));
}

__global__ void k_edge2(const int* __restrict__ ei)
{
    int e = blockIdx.x * blockDim.x + threadIdx.x;
    if (e >= E_EXT) return;
    int d = (e < N_EDGES) ? ei[N_EDGES + e] : (e - N_EDGES);
    float ex = expf(g_eval[e] - funkey(g_emax[d]));
    g_ex[e] = ex;
    atomicAdd(&g_den[d], ex);
}

__global__ void k_edge3(const int* __restrict__ ei)
{
    int gt = blockIdx.x * blockDim.x + threadIdx.x;
    int w = gt >> 5, lane = gt & 31;
    if (w >= E_EXT) return;
    int s, d;
    if (w < N_EDGES) { s = ei[w]; d = ei[N_EDGES + w]; }
    else { s = w - N_EDGES; d = s; }
    float alpha = g_ex[w] / g_den[d];
#pragma unroll
    for (int i = 0; i < 4; i++) {
        int c = lane + 32 * i;
        atomicAdd(&g_aggr[d * NODE_D + c], g_h[s * NODE_D + c] * alpha);
    }
}

__global__ void k_gat_fin(const float* __restrict__ b)
{
    int i = blockIdx.x * blockDim.x + threadIdx.x;
    if (i >= N_NODES * NODE_D) return;
    float v = g_aggr[i] + __ldg(&b[i & (NODE_D - 1)]);
    g_x[i] = (v > 0.f) ? v : (expf(v) - 1.f);   // elu
}

// ---------------------------------------------------------------------------
// Edge-attr MLP:  1 -> 8 -> 16 -> 32   (per-edge thread)
// ---------------------------------------------------------------------------
__global__ void __launch_bounds__(256) k_ef(
    const float* __restrict__ ea,
    const float* __restrict__ w1, const float* __restrict__ b1,
    const float* __restrict__ w2, const float* __restrict__ b2,
    const float* __restrict__ w3, const float* __restrict__ b3)
{
    __shared__ float w1s[8], b1s[8], w2s[128], b2s[16], w3s[512], b3s[32];
    int t = threadIdx.x;
    if (t < 8)   { w1s[t] = w1[t]; b1s[t] = b1[t]; }
    if (t < 128) w2s[t] = w2[t];
    if (t < 16)  b2s[t] = b2[t];
    if (t < 32)  b3s[t] = b3[t];
    for (int i = t; i < 512; i += blockDim.x) w3s[i] = w3[i];
    __syncthreads();
    int e = blockIdx.x * blockDim.x + t;
    if (e >= N_EDGES) return;
    float a = ea[e];
    float t8[8];
#pragma unroll
    for (int j = 0; j < 8; j++) t8[j] = fmaxf(fmaf(a, w1s[j], b1s[j]), 0.f);
    float t16[16];
#pragma unroll
    for (int c = 0; c < 16; c++) {
        float acc = b2s[c];
#pragma unroll
        for (int j = 0; j < 8; j++) acc = fmaf(t8[j], w2s[j * 16 + c], acc);
        t16[c] = fmaxf(acc, 0.f);
    }
#pragma unroll
    for (int c = 0; c < 32; c++) {
        float acc = b3s[c];
#pragma unroll
        for (int j = 0; j < 16; j++) acc = fmaf(t16[j], w3s[j * 32 + c], acc);
        g_ef2[e * EDGE_D + c] = acc;
    }
}

// ---------------------------------------------------------------------------
// Final: concat(x[src], x[dst], ef2) @ dp_w + dp_b -> relu(@ec_w1+b1) -> sigmoid
// Warp per edge, grid-stride.
// ---------------------------------------------------------------------------
__global__ void __launch_bounds__(128) k_final(
    const int* __restrict__ ei,
    const float* __restrict__ dp_w, const float* __restrict__ dp_b,
    const float* __restrict__ ec_w1, const float* __restrict__ ec_b1,
    const float* __restrict__ ec_w2, const float* __restrict__ ec_b2,
    float* __restrict__ out)
{
    __shared__ float dpw_s[288 * 32];
    __shared__ float ecw1_s[32 * 16];
    __shared__ float dpb_s[32];
    __shared__ float ecb1_s[16];
    __shared__ float ecw2_s[16];
    __shared__ float vec_s[4][292];
    __shared__ float o32_s[4][32];

    int tid = threadIdx.x;
    for (int i = tid; i < 288 * 32; i += 128) dpw_s[i] = dp_w[i];
    for (int i = tid; i < 512; i += 128) ecw1_s[i] = ec_w1[i];
    if (tid < 32) dpb_s[tid] = dp_b[tid];
    if (tid < 16) { ecb1_s[tid] = ec_b1[tid]; ecw2_s[tid] = ec_w2[tid]; }
    __syncthreads();

    float b2 = __ldg(ec_b2);
    int warp = tid >> 5, lane = tid & 31;
    int gw = blockIdx.x * 4 + warp;
    int nw = gridDim.x * 4;

    for (int e = gw; e < N_EDGES; e += nw) {
        int s = ei[e], d = ei[N_EDGES + e];
        const float* xsp = g_x + s * NODE_D;
        const float* xdp = g_x + d * NODE_D;
#pragma unroll
        for (int i = 0; i < 4; i++) {
            vec_s[warp][lane + 32 * i]       = xsp[lane + 32 * i];
            vec_s[warp][128 + lane + 32 * i] = xdp[lane + 32 * i];
        }
        vec_s[warp][256 + lane] = g_ef2[e * EDGE_D + lane];
        __syncwarp();

        float acc = dpb_s[lane];
#pragma unroll 4
        for (int i = 0; i < 288; i++) acc = fmaf(vec_s[warp][i], dpw_s[i * 32 + lane], acc);
        o32_s[warp][lane] = acc;
        __syncwarp();

        float hh = 0.f;
        if (lane < 16) {
            hh = ecb1_s[lane];
#pragma unroll 4
            for (int j = 0; j < 32; j++) hh = fmaf(o32_s[warp][j], ecw1_s[j * 16 + lane], hh);
            hh = fmaxf(hh, 0.f) * ecw2_s[lane];
        }
#pragma unroll
        for (int off = 8; off; off >>= 1) hh += __shfl_xor_sync(0xFFFFFFFFu, hh, off);
        if (lane == 0) out[e] = 1.f / (1.f + expf(-(hh + b2)));
        __syncwarp();
    }
}

// ---------------------------------------------------------------------------
extern "C" void kernel_launch(void* const* d_in, const int* in_sizes, int n_in,
                              void* d_out, int out_size)
{
    (void)in_sizes; (void)n_in; (void)out_size;
    const float* node_feats = (const float*)d_in[0];
    const float* edge_attr  = (const float*)d_in[1];
    const float* nv_cw      = (const float*)d_in[2];
    const float* nv_cb      = (const float*)d_in[3];
    const float* nv_cw2     = (const float*)d_in[4];
    const float* nv_hw      = (const float*)d_in[5];
    const float* ne_w1      = (const float*)d_in[6];
    const float* ne_b1      = (const float*)d_in[7];
    const float* ne_w2      = (const float*)d_in[8];
    const float* ne_b2      = (const float*)d_in[9];
    const float* ee_w1      = (const float*)d_in[10];
    const float* ee_b1      = (const float*)d_in[11];
    const float* ee_w2      = (const float*)d_in[12];
    const float* ee_b2      = (const float*)d_in[13];
    const float* ee_w3      = (const float*)d_in[14];
    const float* ee_b3      = (const float*)d_in[15];
    const float* gat_w      = (const float*)d_in[16];
    const float* gat_as     = (const float*)d_in[17];
    const float* gat_ad     = (const float*)d_in[18];
    const float* gat_b      = (const float*)d_in[19];
    const float* dp_w       = (const float*)d_in[20];
    const float* dp_b       = (const float*)d_in[21];
    const float* ec_w1      = (const float*)d_in[22];
    const float* ec_b1      = (const float*)d_in[23];
    const float* ec_w2      = (const float*)d_in[24];
    const float* ec_b2      = (const float*)d_in[25];
    const int*   edge_index = (const int*)d_in[26];
    float* out = (float*)d_out;

    float *p_vlad, *p_h0, *p_h1, *p_x;
    cudaGetSymbolAddress((void**)&p_vlad, g_vlad);
    cudaGetSymbolAddress((void**)&p_h0, g_h0);
    cudaGetSymbolAddress((void**)&p_h1, g_h1);
    cudaGetSymbolAddress((void**)&p_x, g_x);

    // 1) fused NetVLAD -> g_vlad
    k_netvlad<<<N_NODES, 256>>>(node_feats, nv_cw, nv_cb, nv_cw2);

    // 2) hidden GEMM: h0 = vlad @ nv_hw     [2000,16384]x[16384,1000]
    {
        dim3 g((H0D + 63) / 64, (N_NODES + 63) / 64);
        k_sgemm<<<g, 256>>>(p_vlad, nv_hw, nullptr, p_h0, N_NODES, H0D, VLAD_DIM, 0);
    }
    // 3) h1 = relu(h0 @ ne_w1 + b1)         [2000,1000]x[1000,500]
    {
        dim3 g((H1D + 63) / 64, (N_NODES + 63) / 64);
        k_sgemm<<<g, 256>>>(p_h0, ne_w1, ne_b1, p_h1, N_NODES, H1D, H0D, 1);
    }
    // 4) x = h1 @ ne_w2 + b2                [2000,500]x[500,128]
    {
        dim3 g((NODE_D + 63) / 64, (N_NODES + 63) / 64);
        k_sgemm<<<g, 256>>>(p_h1, ne_w2, ne_b2, p_x, N_NODES, NODE_D, H1D, 0);
    }

    // 5) edge-attr MLP (independent)
    k_ef<<<(N_EDGES + 255) / 256, 256>>>(edge_attr, ee_w1, ee_b1, ee_w2, ee_b2, ee_w3, ee_b3);

    // 6) 3 GAT layers
    for (int l = 0; l < DEPTH; l++) {
        k_gat_h<<<N_NODES, 128>>>(gat_w + l * NODE_D * NODE_D,
                                  gat_as + l * NODE_D, gat_ad + l * NODE_D);
        k_init<<<(N_NODES * NODE_D + 255) / 256, 256>>>();
        k_edge1<<<(E_EXT + 255) / 256, 256>>>(edge_index);
        k_edge2<<<(E_EXT + 255) / 256, 256>>>(edge_index);
        k_edge3<<<((E_EXT * 32) + 255) / 256, 256>>>(edge_index);
        k_gat_fin<<<(N_NODES * NODE_D + 255) / 256, 256>>>(gat_b + l * NODE_D);
    }

    // 7) fused edge classifier -> out
    k_final<<<512, 128>>>(edge_index, dp_w, dp_b, ec_w1, ec_b1, ec_w2, ec_b2, out);
}

// round 2
// speedup vs baseline: 1.2554x; 1.2554x over previous
#include <cuda_runtime.h>
#include <math.h>

#define N_NODES 2000
#define NUM_KP 500
#define DESC 256
#define NVK 64
#define VLAD_DIM (DESC*NVK)        // 16384
#define H0D (NUM_KP*2)             // 1000
#define H1D NUM_KP                 // 500
#define NODE_D 128
#define EDGE_D 32
#define N_EDGES 64000
#define E_EXT (N_EDGES + N_NODES)  // 66000
#define DEPTH 3

typedef unsigned long long u64;

// ---------------- scratch (device globals; no runtime allocation) ----------
__device__ float    g_vlad[(size_t)N_NODES * VLAD_DIM];   // 131 MB
__device__ float    g_h0[N_NODES * H0D];
__device__ float    g_h1[N_NODES * H1D];
__device__ float    g_x[N_NODES * NODE_D];
__device__ float    g_h[N_NODES * NODE_D];
__device__ float    g_es[N_NODES];
__device__ float    g_ed[N_NODES];
__device__ float    g_eval[E_EXT];
__device__ float    g_ex[E_EXT];
__device__ unsigned g_emax[N_NODES];
__device__ float    g_den[N_NODES];
__device__ float    g_aggr[N_NODES * NODE_D];
__device__ float    g_ef2[N_EDGES * EDGE_D];

// ---------------- packed f32x2 helpers (Blackwell FFMA2) -------------------
__device__ __forceinline__ u64 fma2(u64 a, u64 b, u64 c) {
    u64 d;
    asm("fma.rn.f32x2 %0, %1, %2, %3;" : "=l"(d) : "l"(a), "l"(b), "l"(c));
    return d;
}
__device__ __forceinline__ u64 pack2(float x, float y) {
    u64 d;
    asm("mov.b64 %0, {%1, %2};" : "=l"(d) : "f"(x), "f"(y));
    return d;
}
__device__ __forceinline__ float2 unpack2(u64 v) {
    float2 f;
    asm("mov.b64 {%0, %1}, %2;" : "=f"(f.x), "=f"(f.y) : "l"(v));
    return f;
}

// monotonic float <-> uint mapping for atomicMax on floats (handles negatives)
__device__ __forceinline__ unsigned fkey(float f) {
    unsigned u = __float_as_uint(f);
    return u ^ ((u >> 31) ? 0xFFFFFFFFu : 0x80000000u);
}
__device__ __forceinline__ float funkey(unsigned u) {
    return __uint_as_float(u ^ ((u & 0x80000000u) ? 0x80000000u : 0xFFFFFFFFu));
}

__device__ __forceinline__ float sanit(float v) {
    if (!isfinite(v)) v = (v != v) ? 0.f : (v > 0.f ? 3.402823466e38f : -3.402823466e38f);
    return v;
}

// ---------------------------------------------------------------------------
// Fused NetVLAD with FFMA2: one CTA per node. 256 threads: k = t&63, dg = t>>6.
// ---------------------------------------------------------------------------
__global__ void __launch_bounds__(256, 1) k_netvlad(
    const float* __restrict__ feats,
    const float* __restrict__ cw,   // [256,64]
    const float* __restrict__ cb,   // [64]
    const float* __restrict__ cw2)  // [1,256,64]
{
    int b = blockIdx.x;
    int t = threadIdx.x;
    int k = t & 63;
    int dg = t >> 6;

    __shared__ __align__(16) float xs[2][DESC];
    __shared__ float part[256];
    __shared__ float act_s[64];
    __shared__ float actsum_s[64];
    __shared__ float red_s[64];

    // packed cluster weights: pairs over adjacent d
    u64 cwp[32];
#pragma unroll
    for (int j = 0; j < 32; j++)
        cwp[j] = pack2(cw[(dg * 64 + 2 * j) * 64 + k], cw[(dg * 64 + 2 * j + 1) * 64 + k]);
    u64 vacc[32];
#pragma unroll
    for (int j = 0; j < 32; j++) vacc[j] = 0ull;
    if (t < 64) actsum_s[t] = 0.f;

    float cb0 = 0.f, cb1 = 0.f;
    if (t < 32) { cb0 = cb[t]; cb1 = cb[t + 32]; }

    const float* xb = feats + (size_t)b * NUM_KP * DESC;
    float r = sanit(xb[t]);

    for (int n = 0; n < NUM_KP; n++) {
        int nb = n & 1;
        xs[nb][t] = r;
        __syncthreads();                       // xs[nb] ready (also fences part reuse)
        if (n + 1 < NUM_KP) r = sanit(xb[(size_t)(n + 1) * DESC + t]);  // prefetch

        const u64* x64 = (const u64*)(xs[nb] + dg * 64);
        u64 q0 = 0ull, q1 = 0ull, q2 = 0ull, q3 = 0ull;
#pragma unroll
        for (int j = 0; j < 32; j += 4) {
            q0 = fma2(x64[j + 0], cwp[j + 0], q0);
            q1 = fma2(x64[j + 1], cwp[j + 1], q1);
            q2 = fma2(x64[j + 2], cwp[j + 2], q2);
            q3 = fma2(x64[j + 3], cwp[j + 3], q3);
        }
        float2 f0 = unpack2(q0), f1 = unpack2(q1), f2 = unpack2(q2), f3 = unpack2(q3);
        part[t] = (f0.x + f0.y) + (f1.x + f1.y) + (f2.x + f2.y) + (f3.x + f3.y);
        __syncthreads();                       // part ready

        if (t < 32) {
            float l0 = part[t]       + part[64 + t]  + part[128 + t] + part[192 + t] + cb0;
            float l1 = part[t + 32]  + part[96 + t]  + part[160 + t] + part[224 + t] + cb1;
            float m = fmaxf(l0, l1);
#pragma unroll
            for (int off = 16; off; off >>= 1) m = fmaxf(m, __shfl_xor_sync(0xFFFFFFFFu, m, off));
            float e0 = expf(l0 - m), e1 = expf(l1 - m);
            float s = e0 + e1;
#pragma unroll
            for (int off = 16; off; off >>= 1) s += __shfl_xor_sync(0xFFFFFFFFu, s, off);
            float inv = 1.f / s;
            e0 *= inv; e1 *= inv;
            act_s[t] = e0; act_s[t + 32] = e1;
            actsum_s[t] += e0; actsum_s[t + 32] += e1;
        }
        __syncthreads();                       // act ready

        u64 ad = pack2(act_s[k], act_s[k]);
#pragma unroll
        for (int j = 0; j < 32; j++) vacc[j] = fma2(ad, x64[j], vacc[j]);
        // no trailing barrier: next iter writes xs[1-nb]; part/act rewrites are
        // fenced by the two barriers above (all threads pass bar2(n+1) only
        // after finishing this vlad phase).
    }

    // epilogue: subtract a-term, intra-norm over D, full norm, store
    float asum = actsum_s[k];
    float n2 = 0.f;
#pragma unroll
    for (int j = 0; j < 32; j++) {
        int d = dg * 64 + 2 * j;
        float2 v = unpack2(vacc[j]);
        v.x -= asum * cw2[d * 64 + k];
        v.y -= asum * cw2[(d + 1) * 64 + k];
        n2 = fmaf(v.x, v.x, fmaf(v.y, v.y, n2));
        vacc[j] = pack2(v.x, v.y);
    }
    part[t] = n2;
    __syncthreads();
    if (t < 64) red_s[t] = sqrtf(part[t] + part[64 + t] + part[128 + t] + part[192 + t]) + 1e-12f;
    __syncthreads();
    float invc = 1.f / red_s[k];
    float tot = 0.f;
#pragma unroll
    for (int j = 0; j < 32; j++) {
        float2 v = unpack2(vacc[j]);
        v.x *= invc; v.y *= invc;
        tot = fmaf(v.x, v.x, fmaf(v.y, v.y, tot));
        vacc[j] = pack2(v.x, v.y);
    }
    part[t] = tot;
    __syncthreads();
    if (t < 32) {
        float s = 0.f;
#pragma unroll
        for (int i = 0; i < 8; i++) s += part[t + 32 * i];
#pragma unroll
        for (int off = 16; off; off >>= 1) s += __shfl_xor_sync(0xFFFFFFFFu, s, off);
        if (t == 0) red_s[0] = 1.f / (sqrtf(s) + 1e-12f);
    }
    __syncthreads();
    float invt = red_s[0];
    float* ov = g_vlad + (size_t)b * VLAD_DIM;
#pragma unroll
    for (int j = 0; j < 32; j++) {
        int d = dg * 64 + 2 * j;
        float2 v = unpack2(vacc[j]);
        ov[d * 64 + k]       = v.x * invt;
        ov[(d + 1) * 64 + k] = v.y * invt;
    }
}

// ---------------------------------------------------------------------------
// Big SGEMM: 128x128x16 tiles, 256 threads, 8x8 microtile, FFMA2 math,
// register-prefetch pipeline. act: 0=none, 1=relu.
// ---------------------------------------------------------------------------
__device__ __forceinline__ float4 ld_guard(const float* P, int r, int c, int R, int C) {
    float4 v = {0.f, 0.f, 0.f, 0.f};
    if (r < R) {
        if (c + 3 < C) {
            v = *reinterpret_cast<const float4*>(&P[(size_t)r * C + c]);
        } else {
            if (c + 0 < C) v.x = P[(size_t)r * C + c + 0];
            if (c + 1 < C) v.y = P[(size_t)r * C + c + 1];
            if (c + 2 < C) v.z = P[(size_t)r * C + c + 2];
            if (c + 3 < C) v.w = P[(size_t)r * C + c + 3];
        }
    }
    return v;
}

__global__ void __launch_bounds__(256) k_sgemm128(
    const float* __restrict__ A, const float* __restrict__ B,
    const float* __restrict__ bias, float* __restrict__ C,
    int M, int N, int K, int act)
{
    __shared__ __align__(16) float As[16][132];   // k-major, padded
    __shared__ __align__(16) float Bs[16][128];

    int tid = threadIdx.x;
    int tx = tid & 15;        // n group
    int ty = tid >> 4;        // m group
    int row0 = blockIdx.y * 128, col0 = blockIdx.x * 128;

    u64 acc[8][4];
#pragma unroll
    for (int i = 0; i < 8; i++)
#pragma unroll
        for (int j = 0; j < 4; j++) acc[i][j] = 0ull;

    int a_r = tid >> 2;           // 0..63
    int a_c = (tid & 3) * 4;
    int b_k = tid >> 5;           // 0..7
    int b_c = (tid & 31) * 4;

    // prologue load
    float4 aR0 = ld_guard(A, row0 + a_r,      a_c, M, K);
    float4 aR1 = ld_guard(A, row0 + a_r + 64, a_c, M, K);
    float4 bR0 = ld_guard(B, b_k,     col0 + b_c, K, N);
    float4 bR1 = ld_guard(B, b_k + 8, col0 + b_c, K, N);

    for (int k0 = 0; k0 < K; k0 += 16) {
        // store staged regs into smem (A transposed to k-major)
        As[a_c + 0][a_r]      = aR0.x;  As[a_c + 1][a_r]      = aR0.y;
        As[a_c + 2][a_r]      = aR0.z;  As[a_c + 3][a_r]      = aR0.w;
        As[a_c + 0][a_r + 64] = aR1.x;  As[a_c + 1][a_r + 64] = aR1.y;
        As[a_c + 2][a_r + 64] = aR1.z;  As[a_c + 3][a_r + 64] = aR1.w;
        *reinterpret_cast<float4*>(&Bs[b_k][b_c])     = bR0;
        *reinterpret_cast<float4*>(&Bs[b_k + 8][b_c]) = bR1;
        __syncthreads();

        if (k0 + 16 < K) {      // prefetch next tile while computing
            aR0 = ld_guard(A, row0 + a_r,      k0 + 16 + a_c, M, K);
            aR1 = ld_guard(A, row0 + a_r + 64, k0 + 16 + a_c, M, K);
            bR0 = ld_guard(B, k0 + 16 + b_k,     col0 + b_c, K, N);
            bR1 = ld_guard(B, k0 + 16 + b_k + 8, col0 + b_c, K, N);
        }

#pragma unroll
        for (int kk = 0; kk < 16; kk++) {
            float4 av0 = *reinterpret_cast<const float4*>(&As[kk][ty * 4]);
            float4 av1 = *reinterpret_cast<const float4*>(&As[kk][64 + ty * 4]);
            const u64* brow = reinterpret_cast<const u64*>(&Bs[kk][0]);
            u64 b0 = brow[tx * 2];
            u64 b1 = brow[tx * 2 + 1];
            u64 b2 = brow[32 + tx * 2];
            u64 b3 = brow[32 + tx * 2 + 1];
            float a[8] = {av0.x, av0.y, av0.z, av0.w, av1.x, av1.y, av1.z, av1.w};
#pragma unroll
            for (int i = 0; i < 8; i++) {
                u64 ad = pack2(a[i], a[i]);
                acc[i][0] = fma2(ad, b0, acc[i][0]);
                acc[i][1] = fma2(ad, b1, acc[i][1]);
                acc[i][2] = fma2(ad, b2, acc[i][2]);
                acc[i][3] = fma2(ad, b3, acc[i][3]);
            }
        }
        __syncthreads();
    }

    // epilogue
#pragma unroll
    for (int i = 0; i < 8; i++) {
        int r = row0 + ty * 4 + (i & 3) + (i >> 2) * 64;
        if (r >= M) continue;
#pragma unroll
        for (int jp = 0; jp < 4; jp++) {
            int c0 = col0 + (jp >> 1) * 64 + tx * 4 + (jp & 1) * 2;
            float2 v = unpack2(acc[i][jp]);
            if (c0 < N) {
                float x = v.x + (bias ? bias[c0] : 0.f);
                if (act == 1) x = fmaxf(x, 0.f);
                C[(size_t)r * N + c0] = x;
            }
            if (c0 + 1 < N) {
                float y = v.y + (bias ? bias[c0 + 1] : 0.f);
                if (act == 1) y = fmaxf(y, 0.f);
                C[(size_t)r * N + c0 + 1] = y;
            }
        }
    }
}

// ---------------------------------------------------------------------------
// Small SGEMM (64x64x16, 4x4/thr) — kept for the tiny GEMM.
// ---------------------------------------------------------------------------
__global__ void __launch_bounds__(256) k_sgemm(
    const float* __restrict__ A, const float* __restrict__ B,
    const float* __restrict__ bias, float* __restrict__ C,
    int M, int N, int K, int act)
{
    __shared__ __align__(16) float As[16][64];
    __shared__ __align__(16) float Bs[16][64];

    int tid = threadIdx.x;
    int tx = tid & 15, ty = tid >> 4;
    int row0 = blockIdx.y * 64, col0 = blockIdx.x * 64;

    float c[4][4];
#pragma unroll
    for (int i = 0; i < 4; i++)
#pragma unroll
        for (int j = 0; j < 4; j++) c[i][j] = 0.f;

    int am = tid >> 2;
    int ak = (tid & 3) * 4;
    int bk = tid >> 4;
    int bn = (tid & 15) * 4;

    for (int k0 = 0; k0 < K; k0 += 16) {
        int arow = row0 + am;
        if (arow < M && k0 + ak + 3 < K) {
            float4 v = *reinterpret_cast<const float4*>(&A[(size_t)arow * K + k0 + ak]);
            As[ak + 0][am] = v.x; As[ak + 1][am] = v.y;
            As[ak + 2][am] = v.z; As[ak + 3][am] = v.w;
        } else {
#pragma unroll
            for (int i = 0; i < 4; i++) {
                int kk = k0 + ak + i;
                As[ak + i][am] = (arow < M && kk < K) ? A[(size_t)arow * K + kk] : 0.f;
            }
        }
        int brow = k0 + bk;
        if (brow < K && col0 + bn + 3 < N) {
            float4 v = *reinterpret_cast<const float4*>(&B[(size_t)brow * N + col0 + bn]);
            *reinterpret_cast<float4*>(&Bs[bk][bn]) = v;
        } else {
#pragma unroll
            for (int i = 0; i < 4; i++) {
                int nn = col0 + bn + i;
                Bs[bk][bn + i] = (brow < K && nn < N) ? B[(size_t)brow * N + nn] : 0.f;
            }
        }
        __syncthreads();
#pragma unroll
        for (int kk = 0; kk < 16; kk++) {
            float4 av = *reinterpret_cast<const float4*>(&As[kk][ty * 4]);
            float4 bv = *reinterpret_cast<const float4*>(&Bs[kk][tx * 4]);
            float a[4] = {av.x, av.y, av.z, av.w};
            float bb[4] = {bv.x, bv.y, bv.z, bv.w};
#pragma unroll
            for (int i = 0; i < 4; i++)
#pragma unroll
                for (int j = 0; j < 4; j++) c[i][j] = fmaf(a[i], bb[j], c[i][j]);
        }
        __syncthreads();
    }

#pragma unroll
    for (int i = 0; i < 4; i++) {
        int r = row0 + ty * 4 + i;
        if (r >= M) continue;
#pragma unroll
        for (int j = 0; j < 4; j++) {
            int cc = col0 + tx * 4 + j;
            if (cc >= N) continue;
            float v = c[i][j];
            if (bias) v += bias[cc];
            if (act == 1) v = fmaxf(v, 0.f);
            C[(size_t)r * N + cc] = v;
        }
    }
}

// ---------------------------------------------------------------------------
// GAT: h = x@W, es = h . a_s, ed = h . a_d.  One CTA per node, 128 threads.
// ---------------------------------------------------------------------------
__global__ void __launch_bounds__(128) k_gat_h(
    const float* __restrict__ W, const float* __restrict__ a_s,
    const float* __restrict__ a_d)
{
    int b = blockIdx.x, t = threadIdx.x;
    __shared__ float xsm[NODE_D];
    __shared__ float rs[8];
    xsm[t] = g_x[b * NODE_D + t];
    __syncthreads();
    float acc = 0.f;
#pragma unroll 8
    for (int d = 0; d < NODE_D; d++) acc = fmaf(xsm[d], __ldg(&W[d * NODE_D + t]), acc);
    g_h[b * NODE_D + t] = acc;
    float ps = acc * __ldg(&a_s[t]);
    float pd = acc * __ldg(&a_d[t]);
#pragma unroll
    for (int off = 16; off; off >>= 1) {
        ps += __shfl_xor_sync(0xFFFFFFFFu, ps, off);
        pd += __shfl_xor_sync(0xFFFFFFFFu, pd, off);
    }
    if ((t & 31) == 0) { rs[t >> 5] = ps; rs[4 + (t >> 5)] = pd; }
    __syncthreads();
    if (t == 0) g_es[b] = rs[0] + rs[1] + rs[2] + rs[3];
    if (t == 1) g_ed[b] = rs[4] + rs[5] + rs[6] + rs[7];
}

__global__ void k_init()
{
    int i = blockIdx.x * blockDim.x + threadIdx.x;
    if (i < N_NODES) { g_emax[i] = 0u; g_den[i] = 0.f; }
    if (i < N_NODES * NODE_D) g_aggr[i] = 0.f;
}

__global__ void k_edge1(const int* __restrict__ ei)
{
    int e = blockIdx.x * blockDim.x + threadIdx.x;
    if (e >= E_EXT) return;
    int s, d;
    if (e < N_EDGES) { s = ei[e]; d = ei[N_EDGES + e]; }
    else { s = e - N_EDGES; d = s; }
    float v = g_es[s] + g_ed[d];
    v = (v > 0.f) ? v : 0.2f * v;      // leaky_relu(., 0.2)
    g_eval[e] = v;
    atomicMax(&g_emax[d], fkey(v));
}

__global__ void k_edge2(const int* __restrict__ ei)
{
    int e = blockIdx.x * blockDim.x + threadIdx.x;
    if (e >= E_EXT) return;
    int d = (e < N_EDGES) ? ei[N_EDGES + e] : (e - N_EDGES);
    float ex = expf(g_eval[e] - funkey(g_emax[d]));
    g_ex[e] = ex;
    atomicAdd(&g_den[d], ex);
}

__global__ void k_edge3(const int* __restrict__ ei)
{
    int gt = blockIdx.x * blockDim.x + threadIdx.x;
    int w = gt >> 5, lane = gt & 31;
    if (w >= E_EXT) return;
    int s, d;
    if (w < N_EDGES) { s = ei[w]; d = ei[N_EDGES + w]; }
    else { s = w - N_EDGES; d = s; }
    float alpha = g_ex[w] / g_den[d];
#pragma unroll
    for (int i = 0; i < 4; i++) {
        int c = lane + 32 * i;
        atomicAdd(&g_aggr[d * NODE_D + c], g_h[s * NODE_D + c] * alpha);
    }
}

__global__ void k_gat_fin(const float* __restrict__ b)
{
    int i = blockIdx.x * blockDim.x + threadIdx.x;
    if (i >= N_NODES * NODE_D) return;
    float v = g_aggr[i] + __ldg(&b[i & (NODE_D - 1)]);
    g_x[i] = (v > 0.f) ? v : (expf(v) - 1.f);   // elu
}

// ---------------------------------------------------------------------------
// Edge-attr MLP:  1 -> 8 -> 16 -> 32   (per-edge thread)
// ---------------------------------------------------------------------------
__global__ void __launch_bounds__(256) k_ef(
    const float* __restrict__ ea,
    const float* __restrict__ w1, const float* __restrict__ b1,
    const float* __restrict__ w2, const float* __restrict__ b2,
    const float* __restrict__ w3, const float* __restrict__ b3)
{
    __shared__ float w1s[8], b1s[8], w2s[128], b2s[16], w3s[512], b3s[32];
    int t = threadIdx.x;
    if (t < 8)   { w1s[t] = w1[t]; b1s[t] = b1[t]; }
    if (t < 128) w2s[t] = w2[t];
    if (t < 16)  b2s[t] = b2[t];
    if (t < 32)  b3s[t] = b3[t];
    for (int i = t; i < 512; i += blockDim.x) w3s[i] = w3[i];
    __syncthreads();
    int e = blockIdx.x * blockDim.x + t;
    if (e >= N_EDGES) return;
    float a = ea[e];
    float t8[8];
#pragma unroll
    for (int j = 0; j < 8; j++) t8[j] = fmaxf(fmaf(a, w1s[j], b1s[j]), 0.f);
    float t16[16];
#pragma unroll
    for (int c = 0; c < 16; c++) {
        float acc = b2s[c];
#pragma unroll
        for (int j = 0; j < 8; j++) acc = fmaf(t8[j], w2s[j * 16 + c], acc);
        t16[c] = fmaxf(acc, 0.f);
    }
#pragma unroll
    for (int c = 0; c < 32; c++) {
        float acc = b3s[c];
#pragma unroll
        for (int j = 0; j < 16; j++) acc = fmaf(t16[j], w3s[j * 32 + c], acc);
        g_ef2[e * EDGE_D + c] = acc;
    }
}

// ---------------------------------------------------------------------------
// Final: concat(x[src], x[dst], ef2) @ dp_w + dp_b -> relu(@ec_w1+b1) -> sigmoid
// ---------------------------------------------------------------------------
__global__ void __launch_bounds__(128) k_final(
    const int* __restrict__ ei,
    const float* __restrict__ dp_w, const float* __restrict__ dp_b,
    const float* __restrict__ ec_w1, const float* __restrict__ ec_b1,
    const float* __restrict__ ec_w2, const float* __restrict__ ec_b2,
    float* __restrict__ out)
{
    __shared__ float dpw_s[288 * 32];
    __shared__ float ecw1_s[32 * 16];
    __shared__ float dpb_s[32];
    __shared__ float ecb1_s[16];
    __shared__ float ecw2_s[16];
    __shared__ float vec_s[4][292];
    __shared__ float o32_s[4][32];

    int tid = threadIdx.x;
    for (int i = tid; i < 288 * 32; i += 128) dpw_s[i] = dp_w[i];
    for (int i = tid; i < 512; i += 128) ecw1_s[i] = ec_w1[i];
    if (tid < 32) dpb_s[tid] = dp_b[tid];
    if (tid < 16) { ecb1_s[tid] = ec_b1[tid]; ecw2_s[tid] = ec_w2[tid]; }
    __syncthreads();

    float b2 = __ldg(ec_b2);
    int warp = tid >> 5, lane = tid & 31;
    int gw = blockIdx.x * 4 + warp;
    int nw = gridDim.x * 4;

    for (int e = gw; e < N_EDGES; e += nw) {
        int s = ei[e], d = ei[N_EDGES + e];
        const float* xsp = g_x + s * NODE_D;
        const float* xdp = g_x + d * NODE_D;
#pragma unroll
        for (int i = 0; i < 4; i++) {
            vec_s[warp][lane + 32 * i]       = xsp[lane + 32 * i];
            vec_s[warp][128 + lane + 32 * i] = xdp[lane + 32 * i];
        }
        vec_s[warp][256 + lane] = g_ef2[e * EDGE_D + lane];
        __syncwarp();

        float acc = dpb_s[lane];
#pragma unroll 4
        for (int i = 0; i < 288; i++) acc = fmaf(vec_s[warp][i], dpw_s[i * 32 + lane], acc);
        o32_s[warp][lane] = acc;
        __syncwarp();

        float hh = 0.f;
        if (lane < 16) {
            hh = ecb1_s[lane];
#pragma unroll 4
            for (int j = 0; j < 32; j++) hh = fmaf(o32_s[warp][j], ecw1_s[j * 16 + lane], hh);
            hh = fmaxf(hh, 0.f) * ecw2_s[lane];
        }
#pragma unroll
        for (int off = 8; off; off >>= 1) hh += __shfl_xor_sync(0xFFFFFFFFu, hh, off);
        if (lane == 0) out[e] = 1.f / (1.f + expf(-(hh + b2)));
        __syncwarp();
    }
}

// ---------------------------------------------------------------------------
extern "C" void kernel_launch(void* const* d_in, const int* in_sizes, int n_in,
                              void* d_out, int out_size)
{
    (void)in_sizes; (void)n_in; (void)out_size;
    const float* node_feats = (const float*)d_in[0];
    const float* edge_attr  = (const float*)d_in[1];
    const float* nv_cw      = (const float*)d_in[2];
    const float* nv_cb      = (const float*)d_in[3];
    const float* nv_cw2     = (const float*)d_in[4];
    const float* nv_hw      = (const float*)d_in[5];
    const float* ne_w1      = (const float*)d_in[6];
    const float* ne_b1      = (const float*)d_in[7];
    const float* ne_w2      = (const float*)d_in[8];
    const float* ne_b2      = (const float*)d_in[9];
    const float* ee_w1      = (const float*)d_in[10];
    const float* ee_b1      = (const float*)d_in[11];
    const float* ee_w2      = (const float*)d_in[12];
    const float* ee_b2      = (const float*)d_in[13];
    const float* ee_w3      = (const float*)d_in[14];
    const float* ee_b3      = (const float*)d_in[15];
    const float* gat_w      = (const float*)d_in[16];
    const float* gat_as     = (const float*)d_in[17];
    const float* gat_ad     = (const float*)d_in[18];
    const float* gat_b      = (const float*)d_in[19];
    const float* dp_w       = (const float*)d_in[20];
    const float* dp_b       = (const float*)d_in[21];
    const float* ec_w1      = (const float*)d_in[22];
    const float* ec_b1      = (const float*)d_in[23];
    const float* ec_w2      = (const float*)d_in[24];
    const float* ec_b2      = (const float*)d_in[25];
    const int*   edge_index = (const int*)d_in[26];
    float* out = (float*)d_out;

    float *p_vlad, *p_h0, *p_h1, *p_x;
    cudaGetSymbolAddress((void**)&p_vlad, g_vlad);
    cudaGetSymbolAddress((void**)&p_h0, g_h0);
    cudaGetSymbolAddress((void**)&p_h1, g_h1);
    cudaGetSymbolAddress((void**)&p_x, g_x);

    // 1) fused NetVLAD -> g_vlad
    k_netvlad<<<N_NODES, 256>>>(node_feats, nv_cw, nv_cb, nv_cw2);

    // 2) hidden GEMM: h0 = vlad @ nv_hw     [2000,16384]x[16384,1000]
    {
        dim3 g((H0D + 127) / 128, (N_NODES + 127) / 128);
        k_sgemm128<<<g, 256>>>(p_vlad, nv_hw, nullptr, p_h0, N_NODES, H0D, VLAD_DIM, 0);
    }
    // 3) h1 = relu(h0 @ ne_w1 + b1)         [2000,1000]x[1000,500]
    {
        dim3 g((H1D + 127) / 128, (N_NODES + 127) / 128);
        k_sgemm128<<<g, 256>>>(p_h0, ne_w1, ne_b1, p_h1, N_NODES, H1D, H0D, 1);
    }
    // 4) x = h1 @ ne_w2 + b2                [2000,500]x[500,128]
    {
        dim3 g((NODE_D + 63) / 64, (N_NODES + 63) / 64);
        k_sgemm<<<g, 256>>>(p_h1, ne_w2, ne_b2, p_x, N_NODES, NODE_D, H1D, 0);
    }

    // 5) edge-attr MLP (independent)
    k_ef<<<(N_EDGES + 255) / 256, 256>>>(edge_attr, ee_w1, ee_b1, ee_w2, ee_b2, ee_w3, ee_b3);

    // 6) 3 GAT layers
    for (int l = 0; l < DEPTH; l++) {
        k_gat_h<<<N_NODES, 128>>>(gat_w + l * NODE_D * NODE_D,
                                  gat_as + l * NODE_D, gat_ad + l * NODE_D);
        k_init<<<(N_NODES * NODE_D + 255) / 256, 256>>>();
        k_edge1<<<(E_EXT + 255) / 256, 256>>>(edge_index);
        k_edge2<<<(E_EXT + 255) / 256, 256>>>(edge_index);
        k_edge3<<<((E_EXT * 32) + 255) / 256, 256>>>(edge_index);
        k_gat_fin<<<(N_NODES * NODE_D + 255) / 256, 256>>>(gat_b + l * NODE_D);
    }

    // 7) fused edge classifier -> out
    k_final<<<512, 128>>>(edge_index, dp_w, dp_b, ec_w1, ec_b1, ec_w2, ec_b2, out);
}

// round 4
// speedup vs baseline: 2.1287x; 1.6957x over previous
#include <cuda_runtime.h>
#include <cuda_bf16.h>
#include <math.h>
#include <stdint.h>

#define N_NODES 2000
#define NUM_KP 500
#define DESC 256
#define NVK 64
#define VLAD_DIM (DESC*NVK)        // 16384
#define H0D (NUM_KP*2)             // 1000
#define H1D NUM_KP                 // 500
#define NODE_D 128
#define EDGE_D 32
#define N_EDGES 64000
#define E_EXT (N_EDGES + N_NODES)  // 66000
#define DEPTH 3

#define M_PAD 2048                 // 16 tiles of 128
#define N_PAD 1024                 // 8 tiles of 128

typedef unsigned long long u64;

// ---------------- scratch (device globals; no runtime allocation) ----------
__device__ float    g_vlad[(size_t)N_NODES * VLAD_DIM];   // 131 MB
__device__ float    g_h0[N_NODES * H0D];
__device__ float    g_h1[N_NODES * H1D];
__device__ float    g_x[N_NODES * NODE_D];
__device__ float    g_h[N_NODES * NODE_D];
__device__ float    g_es[N_NODES];
__device__ float    g_ed[N_NODES];
__device__ float    g_eval[E_EXT];
__device__ float    g_ex[E_EXT];
__device__ unsigned g_emax[N_NODES];
__device__ float    g_den[N_NODES];
__device__ float    g_aggr[N_NODES * NODE_D];
__device__ float    g_ef2[N_EDGES * EDGE_D];
// split-bf16 operands for the big GEMM
__device__ __nv_bfloat16 g_Ah[(size_t)M_PAD * VLAD_DIM];  // 64 MB
__device__ __nv_bfloat16 g_Al[(size_t)M_PAD * VLAD_DIM];  // 64 MB
__device__ __nv_bfloat16 g_Bh[(size_t)N_PAD * VLAD_DIM];  // 32 MB (hw transposed)
__device__ __nv_bfloat16 g_Bl[(size_t)N_PAD * VLAD_DIM];  // 32 MB

// ---------------- packed f32x2 helpers (Blackwell FFMA2) -------------------
__device__ __forceinline__ u64 fma2(u64 a, u64 b, u64 c) {
    u64 d;
    asm("fma.rn.f32x2 %0, %1, %2, %3;" : "=l"(d) : "l"(a), "l"(b), "l"(c));
    return d;
}
__device__ __forceinline__ u64 pack2(float x, float y) {
    u64 d;
    asm("mov.b64 %0, {%1, %2};" : "=l"(d) : "f"(x), "f"(y));
    return d;
}
__device__ __forceinline__ float2 unpack2(u64 v) {
    float2 f;
    asm("mov.b64 {%0, %1}, %2;" : "=f"(f.x), "=f"(f.y) : "l"(v));
    return f;
}

// ---------------- cp.async helpers (base PTX, sm_80+) ----------------------
__device__ __forceinline__ uint32_t smem_u32(const void* p) {
    uint32_t a;
    asm("{ .reg .u64 t; cvta.to.shared.u64 t, %1; cvt.u32.u64 %0, t; }" : "=r"(a) : "l"(p));
    return a;
}
#define CP_ASYNC16(dst, src) \
    asm volatile("cp.async.cg.shared.global [%0], [%1], 16;" :: "r"(dst), "l"(src) : "memory")
#define CP_COMMIT()  asm volatile("cp.async.commit_group;" ::: "memory")
#define CP_WAIT0()   asm volatile("cp.async.wait_group 0;" ::: "memory")

__device__ __forceinline__ uint32_t lds32(uint32_t addr) {
    uint32_t v;
    asm volatile("ld.shared.b32 %0, [%1];" : "=r"(v) : "r"(addr));
    return v;
}
__device__ __forceinline__ void mma16816(float* c, const uint32_t* a, const uint32_t* b) {
    asm volatile(
        "mma.sync.aligned.m16n8k16.row.col.f32.bf16.bf16.f32 "
        "{%0,%1,%2,%3}, {%4,%5,%6,%7}, {%8,%9}, {%0,%1,%2,%3};"
        : "+f"(c[0]), "+f"(c[1]), "+f"(c[2]), "+f"(c[3])
        : "r"(a[0]), "r"(a[1]), "r"(a[2]), "r"(a[3]), "r"(b[0]), "r"(b[1]));
}

// float <-> ordered-uint for atomicMax on floats
__device__ __forceinline__ unsigned fkey(float f) {
    unsigned u = __float_as_uint(f);
    return u ^ ((u >> 31) ? 0xFFFFFFFFu : 0x80000000u);
}
__device__ __forceinline__ float funkey(unsigned u) {
    return __uint_as_float(u ^ ((u & 0x80000000u) ? 0x80000000u : 0xFFFFFFFFu));
}
__device__ __forceinline__ float sanit(float v) {
    if (!isfinite(v)) v = (v != v) ? 0.f : (v > 0.f ? 3.402823466e38f : -3.402823466e38f);
    return v;
}

// ---------------------------------------------------------------------------
// Fused NetVLAD, 2 keypoints per iteration. One CTA per node, 256 threads.
// ---------------------------------------------------------------------------
__global__ void __launch_bounds__(256, 1) k_netvlad(
    const float* __restrict__ feats,
    const float* __restrict__ cw,   // [256,64]
    const float* __restrict__ cb,   // [64]
    const float* __restrict__ cw2)  // [1,256,64]
{
    int b = blockIdx.x;
    int t = threadIdx.x;
    int k = t & 63;
    int dg = t >> 6;

    __shared__ __align__(16) float xs[2][2][DESC];
    __shared__ float part2[2][256];
    __shared__ float act2[2][64];
    __shared__ float asumA[64], asumB[64];
    __shared__ float red_s[64];

    u64 cwp[32];
#pragma unroll
    for (int j = 0; j < 32; j++)
        cwp[j] = pack2(cw[(dg * 64 + 2 * j) * 64 + k], cw[(dg * 64 + 2 * j + 1) * 64 + k]);
    u64 vacc[32];
#pragma unroll
    for (int j = 0; j < 32; j++) vacc[j] = 0ull;
    if (t < 64) { asumA[t] = 0.f; asumB[t] = 0.f; }

    float cb0 = 0.f, cb1 = 0.f;
    if (t < 64) { int tt = t & 31; cb0 = cb[tt]; cb1 = cb[tt + 32]; }

    const float* xb = feats + (size_t)b * NUM_KP * DESC;
    float r0 = sanit(xb[t]);
    float r1 = sanit(xb[DESC + t]);

    for (int pi = 0; pi < NUM_KP / 2; pi++) {
        int p = pi & 1;
        xs[p][0][t] = r0;
        xs[p][1][t] = r1;
        __syncthreads();
        if (pi + 1 < NUM_KP / 2) {
            r0 = sanit(xb[(size_t)(2 * pi + 2) * DESC + t]);
            r1 = sanit(xb[(size_t)(2 * pi + 3) * DESC + t]);
        }

        const u64* x0 = (const u64*)(xs[p][0] + dg * 64);
        const u64* x1 = (const u64*)(xs[p][1] + dg * 64);
        u64 q0 = 0, q1 = 0, s0 = 0, s1 = 0;
#pragma unroll
        for (int j = 0; j < 32; j += 2) {
            q0 = fma2(x0[j], cwp[j], q0);     q1 = fma2(x0[j + 1], cwp[j + 1], q1);
            s0 = fma2(x1[j], cwp[j], s0);     s1 = fma2(x1[j + 1], cwp[j + 1], s1);
        }
        float2 f0 = unpack2(q0), f1 = unpack2(q1), g0 = unpack2(s0), g1 = unpack2(s1);
        part2[0][t] = (f0.x + f0.y) + (f1.x + f1.y);
        part2[1][t] = (g0.x + g0.y) + (g1.x + g1.y);
        __syncthreads();

        if (t < 64) {
            int w = t >> 5, tt = t & 31;
            const float* pp = part2[w];
            float l0 = pp[tt]      + pp[64 + tt]  + pp[128 + tt] + pp[192 + tt] + cb0;
            float l1 = pp[tt + 32] + pp[96 + tt]  + pp[160 + tt] + pp[224 + tt] + cb1;
            float m = fmaxf(l0, l1);
#pragma unroll
            for (int off = 16; off; off >>= 1) m = fmaxf(m, __shfl_xor_sync(0xFFFFFFFFu, m, off));
            float e0 = __expf(l0 - m), e1 = __expf(l1 - m);
            float ss = e0 + e1;
#pragma unroll
            for (int off = 16; off; off >>= 1) ss += __shfl_xor_sync(0xFFFFFFFFu, ss, off);
            float inv = 1.f / ss;
            e0 *= inv; e1 *= inv;
            act2[w][tt] = e0; act2[w][tt + 32] = e1;
            if (w == 0) { asumA[tt] += e0; asumA[tt + 32] += e1; }
            else        { asumB[tt] += e0; asumB[tt + 32] += e1; }
        }
        __syncthreads();

        u64 ad0 = pack2(act2[0][k], act2[0][k]);
        u64 ad1 = pack2(act2[1][k], act2[1][k]);
#pragma unroll
        for (int j = 0; j < 32; j++) {
            vacc[j] = fma2(ad0, x0[j], vacc[j]);
            vacc[j] = fma2(ad1, x1[j], vacc[j]);
        }
    }

    // epilogue: subtract a-term, intra-norm over D, full norm, store
    float asum = asumA[k] + asumB[k];
    float* part = part2[0];
    float n2 = 0.f;
#pragma unroll
    for (int j = 0; j < 32; j++) {
        int d = dg * 64 + 2 * j;
        float2 v = unpack2(vacc[j]);
        v.x -= asum * cw2[d * 64 + k];
        v.y -= asum * cw2[(d + 1) * 64 + k];
        n2 = fmaf(v.x, v.x, fmaf(v.y, v.y, n2));
        vacc[j] = pack2(v.x, v.y);
    }
    part[t] = n2;
    __syncthreads();
    if (t < 64) red_s[t] = sqrtf(part[t] + part[64 + t] + part[128 + t] + part[192 + t]) + 1e-12f;
    __syncthreads();
    float invc = 1.f / red_s[k];
    float tot = 0.f;
#pragma unroll
    for (int j = 0; j < 32; j++) {
        float2 v = unpack2(vacc[j]);
        v.x *= invc; v.y *= invc;
        tot = fmaf(v.x, v.x, fmaf(v.y, v.y, tot));
        vacc[j] = pack2(v.x, v.y);
    }
    __syncthreads();
    part[t] = tot;
    __syncthreads();
    if (t < 32) {
        float s = 0.f;
#pragma unroll
        for (int i = 0; i < 8; i++) s += part[t + 32 * i];
#pragma unroll
        for (int off = 16; off; off >>= 1) s += __shfl_xor_sync(0xFFFFFFFFu, s, off);
        if (t == 0) red_s[0] = 1.f / (sqrtf(s) + 1e-12f);
    }
    __syncthreads();
    float invt = red_s[0];
    float* ov = g_vlad + (size_t)b * VLAD_DIM;
#pragma unroll
    for (int j = 0; j < 32; j++) {
        int d = dg * 64 + 2 * j;
        float2 v = unpack2(vacc[j]);
        ov[d * 64 + k]       = v.x * invt;
        ov[(d + 1) * 64 + k] = v.y * invt;
    }
}

// ---------------------------------------------------------------------------
// Conversion: vlad fp32 -> (hi, lo) bf16, rows padded to 2048 with zeros.
// ---------------------------------------------------------------------------
__global__ void __launch_bounds__(256) k_cvtA(const float* __restrict__ V)
{
    size_t i4 = (size_t)blockIdx.x * blockDim.x + threadIdx.x;
    size_t tot = (size_t)M_PAD * VLAD_DIM / 4;
    if (i4 >= tot) return;
    size_t base = i4 * 4;
    size_t row = base / VLAD_DIM;
    float4 v = make_float4(0.f, 0.f, 0.f, 0.f);
    if (row < N_NODES) v = *(const float4*)(V + base);
    __nv_bfloat16 h0 = __float2bfloat16(v.x), h1 = __float2bfloat16(v.y);
    __nv_bfloat16 h2 = __float2bfloat16(v.z), h3 = __float2bfloat16(v.w);
    __nv_bfloat16 l0 = __float2bfloat16(v.x - __bfloat162float(h0));
    __nv_bfloat16 l1 = __float2bfloat16(v.y - __bfloat162float(h1));
    __nv_bfloat16 l2 = __float2bfloat16(v.z - __bfloat162float(h2));
    __nv_bfloat16 l3 = __float2bfloat16(v.w - __bfloat162float(h3));
    *(__nv_bfloat162*)(g_Ah + base)     = __nv_bfloat162(h0, h1);
    *(__nv_bfloat162*)(g_Ah + base + 2) = __nv_bfloat162(h2, h3);
    *(__nv_bfloat162*)(g_Al + base)     = __nv_bfloat162(l0, l1);
    *(__nv_bfloat162*)(g_Al + base + 2) = __nv_bfloat162(l2, l3);
}

// ---------------------------------------------------------------------------
// Conversion + transpose: hw [16384, 1000] -> Bt (hi,lo) [1024, 16384] bf16.
// ---------------------------------------------------------------------------
__global__ void __launch_bounds__(256) k_cvtB(const float* __restrict__ HW)
{
    __shared__ float sm[32][33];
    int k0 = blockIdx.x * 32;   // K dimension
    int n0 = blockIdx.y * 32;   // N dimension (padded)
    int tx = threadIdx.x & 31;
    int ty = threadIdx.x >> 5;  // 0..7
#pragma unroll
    for (int i = 0; i < 4; i++) {
        int kk = ty + i * 8;            // k-local
        int n = n0 + tx;
        float v = (n < H0D) ? HW[(size_t)(k0 + kk) * H0D + n] : 0.f;
        sm[kk][tx] = v;
    }
    __syncthreads();
#pragma unroll
    for (int i = 0; i < 4; i++) {
        int nn = ty + i * 8;            // n-local
        float v = sm[tx][nn];
        __nv_bfloat16 h = __float2bfloat16(v);
        __nv_bfloat16 l = __float2bfloat16(v - __bfloat162float(h));
        size_t o = (size_t)(n0 + nn) * VLAD_DIM + k0 + tx;
        g_Bh[o] = h;
        g_Bl[o] = l;
    }
}

// ---------------------------------------------------------------------------
// Split-bf16 HMMA GEMM via mma.sync (base PTX): C = Ah@Bh' + Ah@Bl' + Al@Bh'.
// CTA tile 128x128, K-block 64, cp.async double buffer, 8 warps (4M x 2N),
// warp tile 32x64 (2 m16 x 8 n8 fragments).
// ---------------------------------------------------------------------------
#define KBLK 64
#define NKB (VLAD_DIM / KBLK)        // 256
#define SPITCH 72                    // bf16 elements per smem row (64 + 8 pad)
#define SPB (SPITCH * 2)             // 144 bytes
#define TILE_B (128 * SPB)           // 18432 bytes per operand tile
#define STAGE_B (4 * TILE_B)         // 73728
#define MMA_SMEM_TOTAL (2 * STAGE_B) // 147456

__global__ void __launch_bounds__(256, 1) k_mma_g1(
    const __nv_bfloat16* __restrict__ Ah, const __nv_bfloat16* __restrict__ Al,
    const __nv_bfloat16* __restrict__ Bh, const __nv_bfloat16* __restrict__ Bl,
    float* __restrict__ C, int M, int N)
{
    extern __shared__ __align__(16) char smem[];
    uint32_t sb = smem_u32(smem);
    int tid = threadIdx.x;
    int wid = tid >> 5, lane = tid & 31;
    int wm = wid & 3;                 // 0..3  (M groups of 32)
    int wn = wid >> 2;                // 0..1  (N groups of 64)
    int m0 = blockIdx.y * 128;
    int n0 = blockIdx.x * 128;

    const __nv_bfloat16* srcs[4] = {
        Ah + (size_t)m0 * VLAD_DIM, Al + (size_t)m0 * VLAD_DIM,
        Bh + (size_t)n0 * VLAD_DIM, Bl + (size_t)n0 * VLAD_DIM };

    int lrow = tid >> 3;              // 0..31
    int lchk = tid & 7;               // 0..7 (16B chunks per 128B row)

    float acc[2][8][4];
#pragma unroll
    for (int i = 0; i < 2; i++)
#pragma unroll
        for (int j = 0; j < 8; j++)
#pragma unroll
            for (int q = 0; q < 4; q++) acc[i][j][q] = 0.f;

    // ---- stage load helper (issues 16 cp.async per thread) ----
    auto load_stage = [&](int s, int kb) {
        uint32_t sd = sb + s * STAGE_B;
        size_t kOff = (size_t)kb * KBLK;
#pragma unroll
        for (int v = 0; v < 4; v++) {
            const __nv_bfloat16* g = srcs[v] + kOff;
#pragma unroll
            for (int p = 0; p < 4; p++) {
                int r = lrow + p * 32;
                uint32_t d = sd + v * TILE_B + r * SPB + lchk * 16;
                const void* sptr = (const char*)(g + (size_t)r * VLAD_DIM) + lchk * 16;
                CP_ASYNC16(d, sptr);
            }
        }
        CP_COMMIT();
    };

    load_stage(0, 0);

    int lr = lane >> 2;               // 0..7
    int lc = (lane & 3) * 2;          // 0,2,4,6

    for (int kb = 0; kb < NKB; kb++) {
        int s = kb & 1;
        CP_WAIT0();
        __syncthreads();              // stage s ready; prev compute done by all
        if (kb + 1 < NKB) load_stage(s ^ 1, kb + 1);

        uint32_t sAh = sb + s * STAGE_B;
        uint32_t sAl = sAh + TILE_B;
        uint32_t sBh = sAh + 2 * TILE_B;
        uint32_t sBl = sAh + 3 * TILE_B;

#pragma unroll
        for (int ks = 0; ks < 4; ks++) {
            int kl = ks * 16;
            uint32_t ah[2][4], al_[2][4];
#pragma unroll
            for (int mt = 0; mt < 2; mt++) {
                uint32_t base = (uint32_t)((wm * 32 + mt * 16 + lr) * SPB + (kl + lc) * 2);
                ah[mt][0]  = lds32(sAh + base);
                ah[mt][1]  = lds32(sAh + base + 8 * SPB);
                ah[mt][2]  = lds32(sAh + base + 16);
                ah[mt][3]  = lds32(sAh + base + 8 * SPB + 16);
                al_[mt][0] = lds32(sAl + base);
                al_[mt][1] = lds32(sAl + base + 8 * SPB);
                al_[mt][2] = lds32(sAl + base + 16);
                al_[mt][3] = lds32(sAl + base + 8 * SPB + 16);
            }
            uint32_t bh[8][2], bl_[8][2];
#pragma unroll
            for (int nt = 0; nt < 8; nt++) {
                uint32_t base = (uint32_t)((wn * 64 + nt * 8 + lr) * SPB + (kl + lc) * 2);
                bh[nt][0]  = lds32(sBh + base);
                bh[nt][1]  = lds32(sBh + base + 16);
                bl_[nt][0] = lds32(sBl + base);
                bl_[nt][1] = lds32(sBl + base + 16);
            }
#pragma unroll
            for (int mt = 0; mt < 2; mt++)
#pragma unroll
                for (int nt = 0; nt < 8; nt++) {
                    mma16816(acc[mt][nt], ah[mt], bh[nt]);
                    mma16816(acc[mt][nt], ah[mt], bl_[nt]);
                    mma16816(acc[mt][nt], al_[mt], bh[nt]);
                }
        }
        // top-of-loop syncthreads (after CP_WAIT0) fences stage reuse
    }

    // epilogue: c0:(r,c) c1:(r,c+1) c2:(r+8,c) c3:(r+8,c+1)
#pragma unroll
    for (int mt = 0; mt < 2; mt++) {
#pragma unroll
        for (int nt = 0; nt < 8; nt++) {
            int r = m0 + wm * 32 + mt * 16 + lr;
            int c = n0 + wn * 64 + nt * 8 + lc;
            if (r < M) {
                if (c < N)     C[(size_t)r * N + c]     = acc[mt][nt][0];
                if (c + 1 < N) C[(size_t)r * N + c + 1] = acc[mt][nt][1];
            }
            if (r + 8 < M) {
                if (c < N)     C[(size_t)(r + 8) * N + c]     = acc[mt][nt][2];
                if (c + 1 < N) C[(size_t)(r + 8) * N + c + 1] = acc[mt][nt][3];
            }
        }
    }
}

// ---------------------------------------------------------------------------
// FFMA2 SGEMM 128x128x16 (G2). act: 0=none, 1=relu.
// ---------------------------------------------------------------------------
__device__ __forceinline__ float4 ld_guard(const float* P, int r, int c, int R, int C) {
    float4 v = {0.f, 0.f, 0.f, 0.f};
    if (r < R) {
        if (c + 3 < C) {
            v = *reinterpret_cast<const float4*>(&P[(size_t)r * C + c]);
        } else {
            if (c + 0 < C) v.x = P[(size_t)r * C + c + 0];
            if (c + 1 < C) v.y = P[(size_t)r * C + c + 1];
            if (c + 2 < C) v.z = P[(size_t)r * C + c + 2];
            if (c + 3 < C) v.w = P[(size_t)r * C + c + 3];
        }
    }
    return v;
}

__global__ void __launch_bounds__(256) k_sgemm128(
    const float* __restrict__ A, const float* __restrict__ B,
    const float* __restrict__ bias, float* __restrict__ C,
    int M, int N, int K, int act)
{
    __shared__ __align__(16) float As[16][132];
    __shared__ __align__(16) float Bs[16][128];

    int tid = threadIdx.x;
    int tx = tid & 15;
    int ty = tid >> 4;
    int row0 = blockIdx.y * 128, col0 = blockIdx.x * 128;

    u64 acc[8][4];
#pragma unroll
    for (int i = 0; i < 8; i++)
#pragma unroll
        for (int j = 0; j < 4; j++) acc[i][j] = 0ull;

    int a_r = tid >> 2;
    int a_c = (tid & 3) * 4;
    int b_k = tid >> 5;
    int b_c = (tid & 31) * 4;

    float4 aR0 = ld_guard(A, row0 + a_r,      a_c, M, K);
    float4 aR1 = ld_guard(A, row0 + a_r + 64, a_c, M, K);
    float4 bR0 = ld_guard(B, b_k,     col0 + b_c, K, N);
    float4 bR1 = ld_guard(B, b_k + 8, col0 + b_c, K, N);

    for (int k0 = 0; k0 < K; k0 += 16) {
        As[a_c + 0][a_r]      = aR0.x;  As[a_c + 1][a_r]      = aR0.y;
        As[a_c + 2][a_r]      = aR0.z;  As[a_c + 3][a_r]      = aR0.w;
        As[a_c + 0][a_r + 64] = aR1.x;  As[a_c + 1][a_r + 64] = aR1.y;
        As[a_c + 2][a_r + 64] = aR1.z;  As[a_c + 3][a_r + 64] = aR1.w;
        *reinterpret_cast<float4*>(&Bs[b_k][b_c])     = bR0;
        *reinterpret_cast<float4*>(&Bs[b_k + 8][b_c]) = bR1;
        __syncthreads();

        if (k0 + 16 < K) {
            aR0 = ld_guard(A, row0 + a_r,      k0 + 16 + a_c, M, K);
            aR1 = ld_guard(A, row0 + a_r + 64, k0 + 16 + a_c, M, K);
            bR0 = ld_guard(B, k0 + 16 + b_k,     col0 + b_c, K, N);
            bR1 = ld_guard(B, k0 + 16 + b_k + 8, col0 + b_c, K, N);
        }

#pragma unroll
        for (int kk = 0; kk < 16; kk++) {
            float4 av0 = *reinterpret_cast<const float4*>(&As[kk][ty * 4]);
            float4 av1 = *reinterpret_cast<const float4*>(&As[kk][64 + ty * 4]);
            const u64* brow = reinterpret_cast<const u64*>(&Bs[kk][0]);
            u64 b0 = brow[tx * 2];
            u64 b1 = brow[tx * 2 + 1];
            u64 b2 = brow[32 + tx * 2];
            u64 b3 = brow[32 + tx * 2 + 1];
            float a[8] = {av0.x, av0.y, av0.z, av0.w, av1.x, av1.y, av1.z, av1.w};
#pragma unroll
            for (int i = 0; i < 8; i++) {
                u64 ad = pack2(a[i], a[i]);
                acc[i][0] = fma2(ad, b0, acc[i][0]);
                acc[i][1] = fma2(ad, b1, acc[i][1]);
                acc[i][2] = fma2(ad, b2, acc[i][2]);
                acc[i][3] = fma2(ad, b3, acc[i][3]);
            }
        }
        __syncthreads();
    }

#pragma unroll
    for (int i = 0; i < 8; i++) {
        int r = row0 + ty * 4 + (i & 3) + (i >> 2) * 64;
        if (r >= M) continue;
#pragma unroll
        for (int jp = 0; jp < 4; jp++) {
            int c0 = col0 + (jp >> 1) * 64 + tx * 4 + (jp & 1) * 2;
            float2 v = unpack2(acc[i][jp]);
            if (c0 < N) {
                float x = v.x + (bias ? bias[c0] : 0.f);
                if (act == 1) x = fmaxf(x, 0.f);
                C[(size_t)r * N + c0] = x;
            }
            if (c0 + 1 < N) {
                float y = v.y + (bias ? bias[c0 + 1] : 0.f);
                if (act == 1) y = fmaxf(y, 0.f);
                C[(size_t)r * N + c0 + 1] = y;
            }
        }
    }
}

// ---------------------------------------------------------------------------
// Small SGEMM (64x64x16) for G3.
// ---------------------------------------------------------------------------
__global__ void __launch_bounds__(256) k_sgemm(
    const float* __restrict__ A, const float* __restrict__ B,
    const float* __restrict__ bias, float* __restrict__ C,
    int M, int N, int K, int act)
{
    __shared__ __align__(16) float As[16][64];
    __shared__ __align__(16) float Bs[16][64];

    int tid = threadIdx.x;
    int tx = tid & 15, ty = tid >> 4;
    int row0 = blockIdx.y * 64, col0 = blockIdx.x * 64;

    float c[4][4];
#pragma unroll
    for (int i = 0; i < 4; i++)
#pragma unroll
        for (int j = 0; j < 4; j++) c[i][j] = 0.f;

    int am = tid >> 2;
    int ak = (tid & 3) * 4;
    int bk = tid >> 4;
    int bn = (tid & 15) * 4;

    for (int k0 = 0; k0 < K; k0 += 16) {
        int arow = row0 + am;
        if (arow < M && k0 + ak + 3 < K) {
            float4 v = *reinterpret_cast<const float4*>(&A[(size_t)arow * K + k0 + ak]);
            As[ak + 0][am] = v.x; As[ak + 1][am] = v.y;
            As[ak + 2][am] = v.z; As[ak + 3][am] = v.w;
        } else {
#pragma unroll
            for (int i = 0; i < 4; i++) {
                int kk = k0 + ak + i;
                As[ak + i][am] = (arow < M && kk < K) ? A[(size_t)arow * K + kk] : 0.f;
            }
        }
        int brow = k0 + bk;
        if (brow < K && col0 + bn + 3 < N) {
            float4 v = *reinterpret_cast<const float4*>(&B[(size_t)brow * N + col0 + bn]);
            *reinterpret_cast<float4*>(&Bs[bk][bn]) = v;
        } else {
#pragma unroll
            for (int i = 0; i < 4; i++) {
                int nn = col0 + bn + i;
                Bs[bk][bn + i] = (brow < K && nn < N) ? B[(size_t)brow * N + nn] : 0.f;
            }
        }
        __syncthreads();
#pragma unroll
        for (int kk = 0; kk < 16; kk++) {
            float4 av = *reinterpret_cast<const float4*>(&As[kk][ty * 4]);
            float4 bv = *reinterpret_cast<const float4*>(&Bs[kk][tx * 4]);
            float a[4] = {av.x, av.y, av.z, av.w};
            float bb[4] = {bv.x, bv.y, bv.z, bv.w};
#pragma unroll
            for (int i = 0; i < 4; i++)
#pragma unroll
                for (int j = 0; j < 4; j++) c[i][j] = fmaf(a[i], bb[j], c[i][j]);
        }
        __syncthreads();
    }

#pragma unroll
    for (int i = 0; i < 4; i++) {
        int r = row0 + ty * 4 + i;
        if (r >= M) continue;
#pragma unroll
        for (int j = 0; j < 4; j++) {
            int cc = col0 + tx * 4 + j;
            if (cc >= N) continue;
            float v = c[i][j];
            if (bias) v += bias[cc];
            if (act == 1) v = fmaxf(v, 0.f);
            C[(size_t)r * N + cc] = v;
        }
    }
}

// ---------------------------------------------------------------------------
// GAT kernels
// ---------------------------------------------------------------------------
__global__ void __launch_bounds__(128) k_gat_h(
    const float* __restrict__ W, const float* __restrict__ a_s,
    const float* __restrict__ a_d)
{
    int b = blockIdx.x, t = threadIdx.x;
    __shared__ float xsm[NODE_D];
    __shared__ float rs[8];
    xsm[t] = g_x[b * NODE_D + t];
    __syncthreads();
    float acc = 0.f;
#pragma unroll 8
    for (int d = 0; d < NODE_D; d++) acc = fmaf(xsm[d], __ldg(&W[d * NODE_D + t]), acc);
    g_h[b * NODE_D + t] = acc;
    float ps = acc * __ldg(&a_s[t]);
    float pd = acc * __ldg(&a_d[t]);
#pragma unroll
    for (int off = 16; off; off >>= 1) {
        ps += __shfl_xor_sync(0xFFFFFFFFu, ps, off);
        pd += __shfl_xor_sync(0xFFFFFFFFu, pd, off);
    }
    if ((t & 31) == 0) { rs[t >> 5] = ps; rs[4 + (t >> 5)] = pd; }
    __syncthreads();
    if (t == 0) g_es[b] = rs[0] + rs[1] + rs[2] + rs[3];
    if (t == 1) g_ed[b] = rs[4] + rs[5] + rs[6] + rs[7];
}

__global__ void k_init()
{
    int i = blockIdx.x * blockDim.x + threadIdx.x;
    if (i < N_NODES) { g_emax[i] = 0u; g_den[i] = 0.f; }
    if (i < N_NODES * NODE_D) g_aggr[i] = 0.f;
}

__global__ void k_edge1(const int* __restrict__ ei)
{
    int e = blockIdx.x * blockDim.x + threadIdx.x;
    if (e >= E_EXT) return;
    int s, d;
    if (e < N_EDGES) { s = ei[e]; d = ei[N_EDGES + e]; }
    else { s = e - N_EDGES; d = s; }
    float v = g_es[s] + g_ed[d];
    v = (v > 0.f) ? v : 0.2f * v;
    g_eval[e] = v;
    atomicMax(&g_emax[d], fkey(v));
}

__global__ void k_edge2(const int* __restrict__ ei)
{
    int e = blockIdx.x * blockDim.x + threadIdx.x;
    if (e >= E_EXT) return;
    int d = (e < N_EDGES) ? ei[N_EDGES + e] : (e - N_EDGES);
    float ex = __expf(g_eval[e] - funkey(g_emax[d]));
    g_ex[e] = ex;
    atomicAdd(&g_den[d], ex);
}

__global__ void k_edge3(const int* __restrict__ ei)
{
    int gt = blockIdx.x * blockDim.x + threadIdx.x;
    int w = gt >> 5, lane = gt & 31;
    if (w >= E_EXT) return;
    int s, d;
    if (w < N_EDGES) { s = ei[w]; d = ei[N_EDGES + w]; }
    else { s = w - N_EDGES; d = s; }
    float alpha = g_ex[w] / g_den[d];
#pragma unroll
    for (int i = 0; i < 4; i++) {
        int c = lane + 32 * i;
        atomicAdd(&g_aggr[d * NODE_D + c], g_h[s * NODE_D + c] * alpha);
    }
}

__global__ void k_gat_fin(const float* __restrict__ b)
{
    int i = blockIdx.x * blockDim.x + threadIdx.x;
    if (i >= N_NODES * NODE_D) return;
    float v = g_aggr[i] + __ldg(&b[i & (NODE_D - 1)]);
    g_x[i] = (v > 0.f) ? v : (__expf(v) - 1.f);
}

// ---------------------------------------------------------------------------
// Edge-attr MLP: 1 -> 8 -> 16 -> 32
// ---------------------------------------------------------------------------
__global__ void __launch_bounds__(256) k_ef(
    const float* __restrict__ ea,
    const float* __restrict__ w1, const float* __restrict__ b1,
    const float* __restrict__ w2, const float* __restrict__ b2,
    const float* __restrict__ w3, const float* __restrict__ b3)
{
    __shared__ float w1s[8], b1s[8], w2s[128], b2s[16], w3s[512], b3s[32];
    int t = threadIdx.x;
    if (t < 8)   { w1s[t] = w1[t]; b1s[t] = b1[t]; }
    if (t < 128) w2s[t] = w2[t];
    if (t < 16)  b2s[t] = b2[t];
    if (t < 32)  b3s[t] = b3[t];
    for (int i = t; i < 512; i += blockDim.x) w3s[i] = w3[i];
    __syncthreads();
    int e = blockIdx.x * blockDim.x + t;
    if (e >= N_EDGES) return;
    float a = ea[e];
    float t8[8];
#pragma unroll
    for (int j = 0; j < 8; j++) t8[j] = fmaxf(fmaf(a, w1s[j], b1s[j]), 0.f);
    float t16[16];
#pragma unroll
    for (int c = 0; c < 16; c++) {
        float acc = b2s[c];
#pragma unroll
        for (int j = 0; j < 8; j++) acc = fmaf(t8[j], w2s[j * 16 + c], acc);
        t16[c] = fmaxf(acc, 0.f);
    }
#pragma unroll
    for (int c = 0; c < 32; c++) {
        float acc = b3s[c];
#pragma unroll
        for (int j = 0; j < 16; j++) acc = fmaf(t16[j], w3s[j * 32 + c], acc);
        g_ef2[e * EDGE_D + c] = acc;
    }
}

// ---------------------------------------------------------------------------
// Final fused edge classifier.
// ---------------------------------------------------------------------------
__global__ void __launch_bounds__(128) k_final(
    const int* __restrict__ ei,
    const float* __restrict__ dp_w, const float* __restrict__ dp_b,
    const float* __restrict__ ec_w1, const float* __restrict__ ec_b1,
    const float* __restrict__ ec_w2, const float* __restrict__ ec_b2,
    float* __restrict__ out)
{
    __shared__ float dpw_s[288 * 32];
    __shared__ float ecw1_s[32 * 16];
    __shared__ float dpb_s[32];
    __shared__ float ecb1_s[16];
    __shared__ float ecw2_s[16];
    __shared__ float vec_s[4][292];
    __shared__ float o32_s[4][32];

    int tid = threadIdx.x;
    for (int i = tid; i < 288 * 32; i += 128) dpw_s[i] = dp_w[i];
    for (int i = tid; i < 512; i += 128) ecw1_s[i] = ec_w1[i];
    if (tid < 32) dpb_s[tid] = dp_b[tid];
    if (tid < 16) { ecb1_s[tid] = ec_b1[tid]; ecw2_s[tid] = ec_w2[tid]; }
    __syncthreads();

    float b2 = __ldg(ec_b2);
    int warp = tid >> 5, lane = tid & 31;
    int gw = blockIdx.x * 4 + warp;
    int nw = gridDim.x * 4;

    for (int e = gw; e < N_EDGES; e += nw) {
        int s = ei[e], d = ei[N_EDGES + e];
        const float* xsp = g_x + s * NODE_D;
        const float* xdp = g_x + d * NODE_D;
#pragma unroll
        for (int i = 0; i < 4; i++) {
            vec_s[warp][lane + 32 * i]       = xsp[lane + 32 * i];
            vec_s[warp][128 + lane + 32 * i] = xdp[lane + 32 * i];
        }
        vec_s[warp][256 + lane] = g_ef2[e * EDGE_D + lane];
        __syncwarp();

        float acc = dpb_s[lane];
#pragma unroll 4
        for (int i = 0; i < 288; i++) acc = fmaf(vec_s[warp][i], dpw_s[i * 32 + lane], acc);
        o32_s[warp][lane] = acc;
        __syncwarp();

        float hh = 0.f;
        if (lane < 16) {
            hh = ecb1_s[lane];
#pragma unroll 4
            for (int j = 0; j < 32; j++) hh = fmaf(o32_s[warp][j], ecw1_s[j * 16 + lane], hh);
            hh = fmaxf(hh, 0.f) * ecw2_s[lane];
        }
#pragma unroll
        for (int off = 8; off; off >>= 1) hh += __shfl_xor_sync(0xFFFFFFFFu, hh, off);
        if (lane == 0) out[e] = 1.f / (1.f + __expf(-(hh + b2)));
        __syncwarp();
    }
}

// ---------------------------------------------------------------------------
extern "C" void kernel_launch(void* const* d_in, const int* in_sizes, int n_in,
                              void* d_out, int out_size)
{
    (void)in_sizes; (void)n_in; (void)out_size;
    const float* node_feats = (const float*)d_in[0];
    const float* edge_attr  = (const float*)d_in[1];
    const float* nv_cw      = (const float*)d_in[2];
    const float* nv_cb      = (const float*)d_in[3];
    const float* nv_cw2     = (const float*)d_in[4];
    const float* nv_hw      = (const float*)d_in[5];
    const float* ne_w1      = (const float*)d_in[6];
    const float* ne_b1      = (const float*)d_in[7];
    const float* ne_w2      = (const float*)d_in[8];
    const float* ne_b2      = (const float*)d_in[9];
    const float* ee_w1      = (const float*)d_in[10];
    const float* ee_b1      = (const float*)d_in[11];
    const float* ee_w2      = (const float*)d_in[12];
    const float* ee_b2      = (const float*)d_in[13];
    const float* ee_w3      = (const float*)d_in[14];
    const float* ee_b3      = (const float*)d_in[15];
    const float* gat_w      = (const float*)d_in[16];
    const float* gat_as     = (const float*)d_in[17];
    const float* gat_ad     = (const float*)d_in[18];
    const float* gat_b      = (const float*)d_in[19];
    const float* dp_w       = (const float*)d_in[20];
    const float* dp_b       = (const float*)d_in[21];
    const float* ec_w1      = (const float*)d_in[22];
    const float* ec_b1      = (const float*)d_in[23];
    const float* ec_w2      = (const float*)d_in[24];
    const float* ec_b2      = (const float*)d_in[25];
    const int*   edge_index = (const int*)d_in[26];
    float* out = (float*)d_out;

    float *p_vlad, *p_h0, *p_h1, *p_x;
    __nv_bfloat16 *p_Ah, *p_Al, *p_Bh, *p_Bl;
    cudaGetSymbolAddress((void**)&p_vlad, g_vlad);
    cudaGetSymbolAddress((void**)&p_h0, g_h0);
    cudaGetSymbolAddress((void**)&p_h1, g_h1);
    cudaGetSymbolAddress((void**)&p_x, g_x);
    cudaGetSymbolAddress((void**)&p_Ah, g_Ah);
    cudaGetSymbolAddress((void**)&p_Al, g_Al);
    cudaGetSymbolAddress((void**)&p_Bh, g_Bh);
    cudaGetSymbolAddress((void**)&p_Bl, g_Bl);

    cudaFuncSetAttribute(k_mma_g1, cudaFuncAttributeMaxDynamicSharedMemorySize,
                         MMA_SMEM_TOTAL);

    // 0) B conversion+transpose (depends only on hw)
    {
        dim3 g(VLAD_DIM / 32, N_PAD / 32);
        k_cvtB<<<g, 256>>>(nv_hw);
    }
    // 1) fused NetVLAD -> g_vlad
    k_netvlad<<<N_NODES, 256>>>(node_feats, nv_cw, nv_cb, nv_cw2);
    // 2) A split-bf16 conversion
    {
        size_t tot = (size_t)M_PAD * VLAD_DIM / 4;
        k_cvtA<<<(unsigned)((tot + 255) / 256), 256>>>(p_vlad);
    }
    // 3) HMMA GEMM: h0 = vlad @ hw   [2000,16384]x[16384,1000]
    {
        dim3 g(N_PAD / 128, M_PAD / 128);   // (8, 16)
        k_mma_g1<<<g, 256, MMA_SMEM_TOTAL>>>(p_Ah, p_Al, p_Bh, p_Bl, p_h0,
                                             N_NODES, H0D);
    }
    // 4) h1 = relu(h0 @ ne_w1 + b1)     [2000,1000]x[1000,500]
    {
        dim3 g((H1D + 127) / 128, (N_NODES + 127) / 128);
        k_sgemm128<<<g, 256>>>(p_h0, ne_w1, ne_b1, p_h1, N_NODES, H1D, H0D, 1);
    }
    // 5) x = h1 @ ne_w2 + b2            [2000,500]x[500,128]
    {
        dim3 g((NODE_D + 63) / 64, (N_NODES + 63) / 64);
        k_sgemm<<<g, 256>>>(p_h1, ne_w2, ne_b2, p_x, N_NODES, NODE_D, H1D, 0);
    }

    // 6) edge-attr MLP
    k_ef<<<(N_EDGES + 255) / 256, 256>>>(edge_attr, ee_w1, ee_b1, ee_w2, ee_b2, ee_w3, ee_b3);

    // 7) 3 GAT layers
    for (int l = 0; l < DEPTH; l++) {
        k_gat_h<<<N_NODES, 128>>>(gat_w + l * NODE_D * NODE_D,
                                  gat_as + l * NODE_D, gat_ad + l * NODE_D);
        k_init<<<(N_NODES * NODE_D + 255) / 256, 256>>>();
        k_edge1<<<(E_EXT + 255) / 256, 256>>>(edge_index);
        k_edge2<<<(E_EXT + 255) / 256, 256>>>(edge_index);
        k_edge3<<<((E_EXT * 32) + 255) / 256, 256>>>(edge_index);
        k_gat_fin<<<(N_NODES * NODE_D + 255) / 256, 256>>>(gat_b + l * NODE_D);
    }

    // 8) fused edge classifier -> out
    k_final<<<512, 128>>>(edge_index, dp_w, dp_b, ec_w1, ec_b1, ec_w2, ec_b2, out);
}

// round 5
// speedup vs baseline: 2.3301x; 1.0946x over previous
#include <cuda_runtime.h>
#include <cuda_bf16.h>
#include <math.h>
#include <stdint.h>

#define N_NODES 2000
#define NUM_KP 500
#define DESC 256
#define NVK 64
#define VLAD_DIM (DESC*NVK)        // 16384
#define H0D (NUM_KP*2)             // 1000
#define H1D NUM_KP                 // 500
#define NODE_D 128
#define EDGE_D 32
#define N_EDGES 64000
#define E_EXT (N_EDGES + N_NODES)  // 66000
#define DEPTH 3

#define M_PAD 2048                 // 16 tiles of 128
#define N_PAD 1024                 // 8 tiles of 128 (G1 N)
#define K2PAD 1024                 // G2 K padded (1000 -> 1024)
#define N2PAD 512                  // G2 N padded (500 -> 512)

typedef unsigned long long u64;

// ---------------- scratch (device globals; no runtime allocation) ----------
__device__ float    g_h1[N_NODES * H1D];
__device__ float    g_x[N_NODES * NODE_D];
__device__ float    g_h[N_NODES * NODE_D];
__device__ float    g_es[N_NODES];
__device__ float    g_ed[N_NODES];
__device__ float    g_eval[E_EXT];
__device__ float    g_ex[E_EXT];
__device__ unsigned g_emax[N_NODES];
__device__ float    g_den[N_NODES];
__device__ float    g_aggr[N_NODES * NODE_D];
__device__ float    g_ef2[N_EDGES * EDGE_D];
// split-bf16 operands (pad regions stay zero: static zero-init, never written)
__device__ __nv_bfloat16 g_Ah[(size_t)M_PAD * VLAD_DIM];   // 64 MB (vlad hi)
__device__ __nv_bfloat16 g_Al[(size_t)M_PAD * VLAD_DIM];   // 64 MB (vlad lo)
__device__ __nv_bfloat16 g_Bh[(size_t)N_PAD * VLAD_DIM];   // 32 MB (hw^T hi)
__device__ __nv_bfloat16 g_Bl[(size_t)N_PAD * VLAD_DIM];   // 32 MB (hw^T lo)
__device__ __nv_bfloat16 g_Ah2[(size_t)M_PAD * K2PAD];     // 4 MB  (h0 hi)
__device__ __nv_bfloat16 g_Al2[(size_t)M_PAD * K2PAD];     // 4 MB  (h0 lo)
__device__ __nv_bfloat16 g_Bh2[(size_t)N2PAD * K2PAD];     // 1 MB  (ne_w1^T hi)
__device__ __nv_bfloat16 g_Bl2[(size_t)N2PAD * K2PAD];     // 1 MB  (ne_w1^T lo)

// ---------------- packed f32x2 helpers (Blackwell FFMA2) -------------------
__device__ __forceinline__ u64 fma2(u64 a, u64 b, u64 c) {
    u64 d;
    asm("fma.rn.f32x2 %0, %1, %2, %3;" : "=l"(d) : "l"(a), "l"(b), "l"(c));
    return d;
}
__device__ __forceinline__ u64 pack2(float x, float y) {
    u64 d;
    asm("mov.b64 %0, {%1, %2};" : "=l"(d) : "f"(x), "f"(y));
    return d;
}
__device__ __forceinline__ float2 unpack2(u64 v) {
    float2 f;
    asm("mov.b64 {%0, %1}, %2;" : "=f"(f.x), "=f"(f.y) : "l"(v));
    return f;
}

// ---------------- cp.async / mma helpers (base PTX) ------------------------
__device__ __forceinline__ uint32_t smem_u32(const void* p) {
    uint32_t a;
    asm("{ .reg .u64 t; cvta.to.shared.u64 t, %1; cvt.u32.u64 %0, t; }" : "=r"(a) : "l"(p));
    return a;
}
#define CP_ASYNC16(dst, src) \
    asm volatile("cp.async.cg.shared.global [%0], [%1], 16;" :: "r"(dst), "l"(src) : "memory")
#define CP_COMMIT()  asm volatile("cp.async.commit_group;" ::: "memory")
#define CP_WAIT0()   asm volatile("cp.async.wait_group 0;" ::: "memory")

__device__ __forceinline__ uint32_t lds32(uint32_t addr) {
    uint32_t v;
    asm volatile("ld.shared.b32 %0, [%1];" : "=r"(v) : "r"(addr));
    return v;
}
__device__ __forceinline__ void mma16816(float* c, const uint32_t* a, const uint32_t* b) {
    asm volatile(
        "mma.sync.aligned.m16n8k16.row.col.f32.bf16.bf16.f32 "
        "{%0,%1,%2,%3}, {%4,%5,%6,%7}, {%8,%9}, {%0,%1,%2,%3};"
        : "+f"(c[0]), "+f"(c[1]), "+f"(c[2]), "+f"(c[3])
        : "r"(a[0]), "r"(a[1]), "r"(a[2]), "r"(a[3]), "r"(b[0]), "r"(b[1]));
}

// float <-> ordered-uint for atomicMax on floats
__device__ __forceinline__ unsigned fkey(float f) {
    unsigned u = __float_as_uint(f);
    return u ^ ((u >> 31) ? 0xFFFFFFFFu : 0x80000000u);
}
__device__ __forceinline__ float funkey(unsigned u) {
    return __uint_as_float(u ^ ((u & 0x80000000u) ? 0x80000000u : 0xFFFFFFFFu));
}
__device__ __forceinline__ float sanit(float v) {
    if (!isfinite(v)) v = (v != v) ? 0.f : (v > 0.f ? 3.402823466e38f : -3.402823466e38f);
    return v;
}

// ---------------------------------------------------------------------------
// Fused NetVLAD, 4 keypoints/iteration. One CTA per node, 256 threads.
// Writes split-bf16 directly into g_Ah/g_Al (G1 A operand).
// ---------------------------------------------------------------------------
__global__ void __launch_bounds__(256, 1) k_netvlad(
    const float* __restrict__ feats,
    const float* __restrict__ cw,   // [256,64]
    const float* __restrict__ cb,   // [64]
    const float* __restrict__ cw2)  // [1,256,64]
{
    int b = blockIdx.x;
    int t = threadIdx.x;
    int k = t & 63;
    int dg = t >> 6;

    __shared__ __align__(16) float xs[2][4][DESC];   // 8 KB
    __shared__ float part[4][256];                   // 4 KB
    __shared__ float act4[4][64];
    __shared__ float asum4[4][64];
    __shared__ float red_s[64];

    u64 cwp[32];
#pragma unroll
    for (int j = 0; j < 32; j++)
        cwp[j] = pack2(cw[(dg * 64 + 2 * j) * 64 + k], cw[(dg * 64 + 2 * j + 1) * 64 + k]);
    u64 vacc[32];
#pragma unroll
    for (int j = 0; j < 32; j++) vacc[j] = 0ull;
    if (t < 64) { asum4[0][t] = 0.f; asum4[1][t] = 0.f; asum4[2][t] = 0.f; asum4[3][t] = 0.f; }

    float cb0 = 0.f, cb1 = 0.f;
    if (t < 128) { int tt = t & 31; cb0 = cb[tt]; cb1 = cb[tt + 32]; }

    const float* xb = feats + (size_t)b * NUM_KP * DESC;
    float r[4];
#pragma unroll
    for (int j = 0; j < 4; j++) r[j] = sanit(xb[(size_t)j * DESC + t]);

    for (int pi = 0; pi < NUM_KP / 4; pi++) {       // 125 iterations
        int p = pi & 1;
#pragma unroll
        for (int j = 0; j < 4; j++) xs[p][j][t] = r[j];
        __syncthreads();
        if (pi + 1 < NUM_KP / 4) {
#pragma unroll
            for (int j = 0; j < 4; j++)
                r[j] = sanit(xb[(size_t)(4 * pi + 4 + j) * DESC + t]);
        }

        const u64* x0 = (const u64*)(xs[p][0] + dg * 64);
        const u64* x1 = (const u64*)(xs[p][1] + dg * 64);
        const u64* x2 = (const u64*)(xs[p][2] + dg * 64);
        const u64* x3 = (const u64*)(xs[p][3] + dg * 64);
        {
            u64 q0 = 0, q1 = 0, q2 = 0, q3 = 0;
#pragma unroll
            for (int j = 0; j < 32; j++) {
                q0 = fma2(x0[j], cwp[j], q0);
                q1 = fma2(x1[j], cwp[j], q1);
                q2 = fma2(x2[j], cwp[j], q2);
                q3 = fma2(x3[j], cwp[j], q3);
            }
            float2 f0 = unpack2(q0), f1 = unpack2(q1), f2 = unpack2(q2), f3 = unpack2(q3);
            part[0][t] = f0.x + f0.y;
            part[1][t] = f1.x + f1.y;
            part[2][t] = f2.x + f2.y;
            part[3][t] = f3.x + f3.y;
        }
        __syncthreads();

        if (t < 128) {
            int w = t >> 5, tt = t & 31;
            const float* pp = part[w];
            float l0 = pp[tt]      + pp[64 + tt] + pp[128 + tt] + pp[192 + tt] + cb0;
            float l1 = pp[tt + 32] + pp[96 + tt] + pp[160 + tt] + pp[224 + tt] + cb1;
            float m = fmaxf(l0, l1);
#pragma unroll
            for (int off = 16; off; off >>= 1) m = fmaxf(m, __shfl_xor_sync(0xFFFFFFFFu, m, off));
            float e0 = __expf(l0 - m), e1 = __expf(l1 - m);
            float ss = e0 + e1;
#pragma unroll
            for (int off = 16; off; off >>= 1) ss += __shfl_xor_sync(0xFFFFFFFFu, ss, off);
            float inv = 1.f / ss;
            e0 *= inv; e1 *= inv;
            act4[w][tt] = e0; act4[w][tt + 32] = e1;
            asum4[w][tt] += e0; asum4[w][tt + 32] += e1;
        }
        __syncthreads();

        u64 ad0 = pack2(act4[0][k], act4[0][k]);
        u64 ad1 = pack2(act4[1][k], act4[1][k]);
        u64 ad2 = pack2(act4[2][k], act4[2][k]);
        u64 ad3 = pack2(act4[3][k], act4[3][k]);
#pragma unroll
        for (int j = 0; j < 32; j++) {
            vacc[j] = fma2(ad0, x0[j], vacc[j]);
            vacc[j] = fma2(ad1, x1[j], vacc[j]);
            vacc[j] = fma2(ad2, x2[j], vacc[j]);
            vacc[j] = fma2(ad3, x3[j], vacc[j]);
        }
        // next iter writes xs[p^1]; part/act4 rewrites fenced by the 2 barriers
    }

    // epilogue: subtract a-term, intra-norm over D, full norm, split-bf16 store
    float asum = asum4[0][k] + asum4[1][k] + asum4[2][k] + asum4[3][k];
    float* pr = part[0];
    float n2 = 0.f;
#pragma unroll
    for (int j = 0; j < 32; j++) {
        int d = dg * 64 + 2 * j;
        float2 v = unpack2(vacc[j]);
        v.x -= asum * cw2[d * 64 + k];
        v.y -= asum * cw2[(d + 1) * 64 + k];
        n2 = fmaf(v.x, v.x, fmaf(v.y, v.y, n2));
        vacc[j] = pack2(v.x, v.y);
    }
    pr[t] = n2;
    __syncthreads();
    if (t < 64) red_s[t] = sqrtf(pr[t] + pr[64 + t] + pr[128 + t] + pr[192 + t]) + 1e-12f;
    __syncthreads();
    float invc = 1.f / red_s[k];
    float tot = 0.f;
#pragma unroll
    for (int j = 0; j < 32; j++) {
        float2 v = unpack2(vacc[j]);
        v.x *= invc; v.y *= invc;
        tot = fmaf(v.x, v.x, fmaf(v.y, v.y, tot));
        vacc[j] = pack2(v.x, v.y);
    }
    __syncthreads();
    pr[t] = tot;
    __syncthreads();
    if (t < 32) {
        float s = 0.f;
#pragma unroll
        for (int i = 0; i < 8; i++) s += pr[t + 32 * i];
#pragma unroll
        for (int off = 16; off; off >>= 1) s += __shfl_xor_sync(0xFFFFFFFFu, s, off);
        if (t == 0) red_s[0] = 1.f / (sqrtf(s) + 1e-12f);
    }
    __syncthreads();
    float invt = red_s[0];
    __nv_bfloat16* oh = g_Ah + (size_t)b * VLAD_DIM;
    __nv_bfloat16* ol = g_Al + (size_t)b * VLAD_DIM;
#pragma unroll
    for (int j = 0; j < 32; j++) {
        int d = dg * 64 + 2 * j;
        float2 v = unpack2(vacc[j]);
        float vx = v.x * invt, vy = v.y * invt;
        __nv_bfloat16 hx = __float2bfloat16(vx);
        __nv_bfloat16 hy = __float2bfloat16(vy);
        oh[d * 64 + k]       = hx;
        oh[(d + 1) * 64 + k] = hy;
        ol[d * 64 + k]       = __float2bfloat16(vx - __bfloat162float(hx));
        ol[(d + 1) * 64 + k] = __float2bfloat16(vy - __bfloat162float(hy));
    }
}

// ---------------------------------------------------------------------------
// Transpose + split: src[k][n] fp32 -> dh/dl[n][k] bf16 (pads zero-filled).
// grid: (Kpad/32, Npad/32), 256 threads.
// ---------------------------------------------------------------------------
__global__ void __launch_bounds__(256) k_cvt_trans(
    const float* __restrict__ src, int ldsrc, int Kreal, int Nreal,
    __nv_bfloat16* __restrict__ dh, __nv_bfloat16* __restrict__ dl, int ldd)
{
    __shared__ float sm[32][33];
    int k0 = blockIdx.x * 32;
    int n0 = blockIdx.y * 32;
    int tx = threadIdx.x & 31;
    int ty = threadIdx.x >> 5;   // 0..7
#pragma unroll
    for (int i = 0; i < 4; i++) {
        int kk = ty + i * 8;
        int n = n0 + tx;
        float v = (k0 + kk < Kreal && n < Nreal) ? src[(size_t)(k0 + kk) * ldsrc + n] : 0.f;
        sm[kk][tx] = v;
    }
    __syncthreads();
#pragma unroll
    for (int i = 0; i < 4; i++) {
        int nn = ty + i * 8;
        float v = sm[tx][nn];
        __nv_bfloat16 h = __float2bfloat16(v);
        __nv_bfloat16 l = __float2bfloat16(v - __bfloat162float(h));
        size_t o = (size_t)(n0 + nn) * ldd + k0 + tx;
        dh[o] = h;
        dl[o] = l;
    }
}

// ---------------------------------------------------------------------------
// Split-bf16 HMMA GEMM: C = A@B' (+bias, relu) where A = Ah+Al, B = Bh+Bl.
// CTA tile 128x128, K-block 64, cp.async double buffer, 8 warps (4M x 2N).
// Optional split-bf16 output (Dh/Dl, pads zeroed) for GEMM chaining.
// ---------------------------------------------------------------------------
#define KBLK 64
#define SPITCH 72                    // bf16 per smem row (64 + 8 pad)
#define SPB (SPITCH * 2)             // 144 bytes
#define TILE_B (128 * SPB)           // 18432 bytes per operand tile
#define STAGE_B (4 * TILE_B)         // 73728
#define MMA_SMEM_TOTAL (2 * STAGE_B) // 147456

__global__ void __launch_bounds__(256, 1) k_mma(
    const __nv_bfloat16* __restrict__ Ah, const __nv_bfloat16* __restrict__ Al,
    const __nv_bfloat16* __restrict__ Bh, const __nv_bfloat16* __restrict__ Bl,
    int K,                              // padded K == row stride of A/B
    float* __restrict__ C, int M, int N,
    const float* __restrict__ bias, int act,
    __nv_bfloat16* __restrict__ Dh, __nv_bfloat16* __restrict__ Dl, int ldd)
{
    extern __shared__ __align__(16) char smem[];
    uint32_t sb = smem_u32(smem);
    int tid = threadIdx.x;
    int wid = tid >> 5, lane = tid & 31;
    int wm = wid & 3;
    int wn = wid >> 2;
    int m0 = blockIdx.y * 128;
    int n0 = blockIdx.x * 128;

    const __nv_bfloat16* srcs[4] = {
        Ah + (size_t)m0 * K, Al + (size_t)m0 * K,
        Bh + (size_t)n0 * K, Bl + (size_t)n0 * K };

    int lrow = tid >> 3;
    int lchk = tid & 7;

    float acc[2][8][4];
#pragma unroll
    for (int i = 0; i < 2; i++)
#pragma unroll
        for (int j = 0; j < 8; j++)
#pragma unroll
            for (int q = 0; q < 4; q++) acc[i][j][q] = 0.f;

    auto load_stage = [&](int s, int kb) {
        uint32_t sd = sb + s * STAGE_B;
        size_t kOff = (size_t)kb * KBLK;
#pragma unroll
        for (int v = 0; v < 4; v++) {
            const __nv_bfloat16* g = srcs[v] + kOff;
#pragma unroll
            for (int p = 0; p < 4; p++) {
                int rr = lrow + p * 32;
                uint32_t d = sd + v * TILE_B + rr * SPB + lchk * 16;
                const void* sptr = (const char*)(g + (size_t)rr * K) + lchk * 16;
                CP_ASYNC16(d, sptr);
            }
        }
        CP_COMMIT();
    };

    load_stage(0, 0);

    int lr = lane >> 2;
    int lc = (lane & 3) * 2;
    int nkb = K / KBLK;

    for (int kb = 0; kb < nkb; kb++) {
        int s = kb & 1;
        CP_WAIT0();
        __syncthreads();
        if (kb + 1 < nkb) load_stage(s ^ 1, kb + 1);

        uint32_t sAh = sb + s * STAGE_B;
        uint32_t sAl = sAh + TILE_B;
        uint32_t sBh = sAh + 2 * TILE_B;
        uint32_t sBl = sAh + 3 * TILE_B;

#pragma unroll
        for (int ks = 0; ks < 4; ks++) {
            int kl = ks * 16;
            uint32_t ah[2][4], al_[2][4];
#pragma unroll
            for (int mt = 0; mt < 2; mt++) {
                uint32_t base = (uint32_t)((wm * 32 + mt * 16 + lr) * SPB + (kl + lc) * 2);
                ah[mt][0]  = lds32(sAh + base);
                ah[mt][1]  = lds32(sAh + base + 8 * SPB);
                ah[mt][2]  = lds32(sAh + base + 16);
                ah[mt][3]  = lds32(sAh + base + 8 * SPB + 16);
                al_[mt][0] = lds32(sAl + base);
                al_[mt][1] = lds32(sAl + base + 8 * SPB);
                al_[mt][2] = lds32(sAl + base + 16);
                al_[mt][3] = lds32(sAl + base + 8 * SPB + 16);
            }
            uint32_t bh[8][2], bl_[8][2];
#pragma unroll
            for (int nt = 0; nt < 8; nt++) {
                uint32_t base = (uint32_t)((wn * 64 + nt * 8 + lr) * SPB + (kl + lc) * 2);
                bh[nt][0]  = lds32(sBh + base);
                bh[nt][1]  = lds32(sBh + base + 16);
                bl_[nt][0] = lds32(sBl + base);
                bl_[nt][1] = lds32(sBl + base + 16);
            }
#pragma unroll
            for (int mt = 0; mt < 2; mt++)
#pragma unroll
                for (int nt = 0; nt < 8; nt++) {
                    mma16816(acc[mt][nt], ah[mt], bh[nt]);
                    mma16816(acc[mt][nt], ah[mt], bl_[nt]);
                    mma16816(acc[mt][nt], al_[mt], bh[nt]);
                }
        }
    }

    // epilogue
    auto emit = [&](int r, int c, float v) {
        bool in = (r < M && c < N);
        float val = 0.f;
        if (in) {
            val = v + (bias ? bias[c] : 0.f);
            if (act == 1) val = fmaxf(val, 0.f);
            if (C) C[(size_t)r * N + c] = val;
        }
        if (Dh) {
            __nv_bfloat16 h = __float2bfloat16(val);
            Dh[(size_t)r * ldd + c] = h;
            Dl[(size_t)r * ldd + c] = __float2bfloat16(val - __bfloat162float(h));
        }
    };
#pragma unroll
    for (int mt = 0; mt < 2; mt++) {
#pragma unroll
        for (int nt = 0; nt < 8; nt++) {
            int r = m0 + wm * 32 + mt * 16 + lr;
            int c = n0 + wn * 64 + nt * 8 + lc;
            emit(r,     c,     acc[mt][nt][0]);
            emit(r,     c + 1, acc[mt][nt][1]);
            emit(r + 8, c,     acc[mt][nt][2]);
            emit(r + 8, c + 1, acc[mt][nt][3]);
        }
    }
}

// ---------------------------------------------------------------------------
// Small SGEMM (64x64x16) for G3.
// ---------------------------------------------------------------------------
__global__ void __launch_bounds__(256) k_sgemm(
    const float* __restrict__ A, const float* __restrict__ B,
    const float* __restrict__ bias, float* __restrict__ C,
    int M, int N, int K, int act)
{
    __shared__ __align__(16) float As[16][64];
    __shared__ __align__(16) float Bs[16][64];

    int tid = threadIdx.x;
    int tx = tid & 15, ty = tid >> 4;
    int row0 = blockIdx.y * 64, col0 = blockIdx.x * 64;

    float c[4][4];
#pragma unroll
    for (int i = 0; i < 4; i++)
#pragma unroll
        for (int j = 0; j < 4; j++) c[i][j] = 0.f;

    int am = tid >> 2;
    int ak = (tid & 3) * 4;
    int bk = tid >> 4;
    int bn = (tid & 15) * 4;

    for (int k0 = 0; k0 < K; k0 += 16) {
        int arow = row0 + am;
        if (arow < M && k0 + ak + 3 < K) {
            float4 v = *reinterpret_cast<const float4*>(&A[(size_t)arow * K + k0 + ak]);
            As[ak + 0][am] = v.x; As[ak + 1][am] = v.y;
            As[ak + 2][am] = v.z; As[ak + 3][am] = v.w;
        } else {
#pragma unroll
            for (int i = 0; i < 4; i++) {
                int kk = k0 + ak + i;
                As[ak + i][am] = (arow < M && kk < K) ? A[(size_t)arow * K + kk] : 0.f;
            }
        }
        int brow = k0 + bk;
        if (brow < K && col0 + bn + 3 < N) {
            float4 v = *reinterpret_cast<const float4*>(&B[(size_t)brow * N + col0 + bn]);
            *reinterpret_cast<float4*>(&Bs[bk][bn]) = v;
        } else {
#pragma unroll
            for (int i = 0; i < 4; i++) {
                int nn = col0 + bn + i;
                Bs[bk][bn + i] = (brow < K && nn < N) ? B[(size_t)brow * N + nn] : 0.f;
            }
        }
        __syncthreads();
#pragma unroll
        for (int kk = 0; kk < 16; kk++) {
            float4 av = *reinterpret_cast<const float4*>(&As[kk][ty * 4]);
            float4 bv = *reinterpret_cast<const float4*>(&Bs[kk][tx * 4]);
            float a[4] = {av.x, av.y, av.z, av.w};
            float bb[4] = {bv.x, bv.y, bv.z, bv.w};
#pragma unroll
            for (int i = 0; i < 4; i++)
#pragma unroll
                for (int j = 0; j < 4; j++) c[i][j] = fmaf(a[i], bb[j], c[i][j]);
        }
        __syncthreads();
    }

#pragma unroll
    for (int i = 0; i < 4; i++) {
        int r = row0 + ty * 4 + i;
        if (r >= M) continue;
#pragma unroll
        for (int j = 0; j < 4; j++) {
            int cc = col0 + tx * 4 + j;
            if (cc >= N) continue;
            float v = c[i][j];
            if (bias) v += bias[cc];
            if (act == 1) v = fmaxf(v, 0.f);
            C[(size_t)r * N + cc] = v;
        }
    }
}

// ---------------------------------------------------------------------------
// GAT kernels
// ---------------------------------------------------------------------------
__global__ void __launch_bounds__(128) k_gat_h(
    const float* __restrict__ W, const float* __restrict__ a_s,
    const float* __restrict__ a_d)
{
    int b = blockIdx.x, t = threadIdx.x;
    __shared__ float xsm[NODE_D];
    __shared__ float rs[8];
    xsm[t] = g_x[b * NODE_D + t];
    __syncthreads();
    float acc = 0.f;
#pragma unroll 8
    for (int d = 0; d < NODE_D; d++) acc = fmaf(xsm[d], __ldg(&W[d * NODE_D + t]), acc);
    g_h[b * NODE_D + t] = acc;
    float ps = acc * __ldg(&a_s[t]);
    float pd = acc * __ldg(&a_d[t]);
#pragma unroll
    for (int off = 16; off; off >>= 1) {
        ps += __shfl_xor_sync(0xFFFFFFFFu, ps, off);
        pd += __shfl_xor_sync(0xFFFFFFFFu, pd, off);
    }
    if ((t & 31) == 0) { rs[t >> 5] = ps; rs[4 + (t >> 5)] = pd; }
    __syncthreads();
    if (t == 0) g_es[b] = rs[0] + rs[1] + rs[2] + rs[3];
    if (t == 1) g_ed[b] = rs[4] + rs[5] + rs[6] + rs[7];
}

__global__ void k_init()
{
    int i = blockIdx.x * blockDim.x + threadIdx.x;
    if (i < N_NODES) { g_emax[i] = 0u; g_den[i] = 0.f; }
    if (i < N_NODES * NODE_D) g_aggr[i] = 0.f;
}

__global__ void k_edge1(const int* __restrict__ ei)
{
    int e = blockIdx.x * blockDim.x + threadIdx.x;
    if (e >= E_EXT) return;
    int s, d;
    if (e < N_EDGES) { s = ei[e]; d = ei[N_EDGES + e]; }
    else { s = e - N_EDGES; d = s; }
    float v = g_es[s] + g_ed[d];
    v = (v > 0.f) ? v : 0.2f * v;
    g_eval[e] = v;
    atomicMax(&g_emax[d], fkey(v));
}

__global__ void k_edge2(const int* __restrict__ ei)
{
    int e = blockIdx.x * blockDim.x + threadIdx.x;
    if (e >= E_EXT) return;
    int d = (e < N_EDGES) ? ei[N_EDGES + e] : (e - N_EDGES);
    float ex = __expf(g_eval[e] - funkey(g_emax[d]));
    g_ex[e] = ex;
    atomicAdd(&g_den[d], ex);
}

__global__ void k_edge3(const int* __restrict__ ei)
{
    int gt = blockIdx.x * blockDim.x + threadIdx.x;
    int w = gt >> 5, lane = gt & 31;
    if (w >= E_EXT) return;
    int s, d;
    if (w < N_EDGES) { s = ei[w]; d = ei[N_EDGES + w]; }
    else { s = w - N_EDGES; d = s; }
    float alpha = g_ex[w] / g_den[d];
#pragma unroll
    for (int i = 0; i < 4; i++) {
        int c = lane + 32 * i;
        atomicAdd(&g_aggr[d * NODE_D + c], g_h[s * NODE_D + c] * alpha);
    }
}

__global__ void k_gat_fin(const float* __restrict__ b)
{
    int i = blockIdx.x * blockDim.x + threadIdx.x;
    if (i >= N_NODES * NODE_D) return;
    float v = g_aggr[i] + __ldg(&b[i & (NODE_D - 1)]);
    g_x[i] = (v > 0.f) ? v : (__expf(v) - 1.f);
}

// ---------------------------------------------------------------------------
// Edge-attr MLP: 1 -> 8 -> 16 -> 32
// ---------------------------------------------------------------------------
__global__ void __launch_bounds__(256) k_ef(
    const float* __restrict__ ea,
    const float* __restrict__ w1, const float* __restrict__ b1,
    const float* __restrict__ w2, const float* __restrict__ b2,
    const float* __restrict__ w3, const float* __restrict__ b3)
{
    __shared__ float w1s[8], b1s[8], w2s[128], b2s[16], w3s[512], b3s[32];
    int t = threadIdx.x;
    if (t < 8)   { w1s[t] = w1[t]; b1s[t] = b1[t]; }
    if (t < 128) w2s[t] = w2[t];
    if (t < 16)  b2s[t] = b2[t];
    if (t < 32)  b3s[t] = b3[t];
    for (int i = t; i < 512; i += blockDim.x) w3s[i] = w3[i];
    __syncthreads();
    int e = blockIdx.x * blockDim.x + t;
    if (e >= N_EDGES) return;
    float a = ea[e];
    float t8[8];
#pragma unroll
    for (int j = 0; j < 8; j++) t8[j] = fmaxf(fmaf(a, w1s[j], b1s[j]), 0.f);
    float t16[16];
#pragma unroll
    for (int c = 0; c < 16; c++) {
        float acc = b2s[c];
#pragma unroll
        for (int j = 0; j < 8; j++) acc = fmaf(t8[j], w2s[j * 16 + c], acc);
        t16[c] = fmaxf(acc, 0.f);
    }
#pragma unroll
    for (int c = 0; c < 32; c++) {
        float acc = b3s[c];
#pragma unroll
        for (int j = 0; j < 16; j++) acc = fmaf(t16[j], w3s[j * 32 + c], acc);
        g_ef2[e * EDGE_D + c] = acc;
    }
}

// ---------------------------------------------------------------------------
// Final fused edge classifier.
// ---------------------------------------------------------------------------
__global__ void __launch_bounds__(128) k_final(
    const int* __restrict__ ei,
    const float* __restrict__ dp_w, const float* __restrict__ dp_b,
    const float* __restrict__ ec_w1, const float* __restrict__ ec_b1,
    const float* __restrict__ ec_w2, const float* __restrict__ ec_b2,
    float* __restrict__ out)
{
    __shared__ float dpw_s[288 * 32];
    __shared__ float ecw1_s[32 * 16];
    __shared__ float dpb_s[32];
    __shared__ float ecb1_s[16];
    __shared__ float ecw2_s[16];
    __shared__ float vec_s[4][292];
    __shared__ float o32_s[4][32];

    int tid = threadIdx.x;
    for (int i = tid; i < 288 * 32; i += 128) dpw_s[i] = dp_w[i];
    for (int i = tid; i < 512; i += 128) ecw1_s[i] = ec_w1[i];
    if (tid < 32) dpb_s[tid] = dp_b[tid];
    if (tid < 16) { ecb1_s[tid] = ec_b1[tid]; ecw2_s[tid] = ec_w2[tid]; }
    __syncthreads();

    float b2 = __ldg(ec_b2);
    int warp = tid >> 5, lane = tid & 31;
    int gw = blockIdx.x * 4 + warp;
    int nw = gridDim.x * 4;

    for (int e = gw; e < N_EDGES; e += nw) {
        int s = ei[e], d = ei[N_EDGES + e];
        const float* xsp = g_x + s * NODE_D;
        const float* xdp = g_x + d * NODE_D;
#pragma unroll
        for (int i = 0; i < 4; i++) {
            vec_s[warp][lane + 32 * i]       = xsp[lane + 32 * i];
            vec_s[warp][128 + lane + 32 * i] = xdp[lane + 32 * i];
        }
        vec_s[warp][256 + lane] = g_ef2[e * EDGE_D + lane];
        __syncwarp();

        float acc = dpb_s[lane];
#pragma unroll 4
        for (int i = 0; i < 288; i++) acc = fmaf(vec_s[warp][i], dpw_s[i * 32 + lane], acc);
        o32_s[warp][lane] = acc;
        __syncwarp();

        float hh = 0.f;
        if (lane < 16) {
            hh = ecb1_s[lane];
#pragma unroll 4
            for (int j = 0; j < 32; j++) hh = fmaf(o32_s[warp][j], ecw1_s[j * 16 + lane], hh);
            hh = fmaxf(hh, 0.f) * ecw2_s[lane];
        }
#pragma unroll
        for (int off = 8; off; off >>= 1) hh += __shfl_xor_sync(0xFFFFFFFFu, hh, off);
        if (lane == 0) out[e] = 1.f / (1.f + __expf(-(hh + b2)));
        __syncwarp();
    }
}

// ---------------------------------------------------------------------------
extern "C" void kernel_launch(void* const* d_in, const int* in_sizes, int n_in,
                              void* d_out, int out_size)
{
    (void)in_sizes; (void)n_in; (void)out_size;
    const float* node_feats = (const float*)d_in[0];
    const float* edge_attr  = (const float*)d_in[1];
    const float* nv_cw      = (const float*)d_in[2];
    const float* nv_cb      = (const float*)d_in[3];
    const float* nv_cw2     = (const float*)d_in[4];
    const float* nv_hw      = (const float*)d_in[5];
    const float* ne_w1      = (const float*)d_in[6];
    const float* ne_b1      = (const float*)d_in[7];
    const float* ne_w2      = (const float*)d_in[8];
    const float* ne_b2      = (const float*)d_in[9];
    const float* ee_w1      = (const float*)d_in[10];
    const float* ee_b1      = (const float*)d_in[11];
    const float* ee_w2      = (const float*)d_in[12];
    const float* ee_b2      = (const float*)d_in[13];
    const float* ee_w3      = (const float*)d_in[14];
    const float* ee_b3      = (const float*)d_in[15];
    const float* gat_w      = (const float*)d_in[16];
    const float* gat_as     = (const float*)d_in[17];
    const float* gat_ad     = (const float*)d_in[18];
    const float* gat_b      = (const float*)d_in[19];
    const float* dp_w       = (const float*)d_in[20];
    const float* dp_b       = (const float*)d_in[21];
    const float* ec_w1      = (const float*)d_in[22];
    const float* ec_b1      = (const float*)d_in[23];
    const float* ec_w2      = (const float*)d_in[24];
    const float* ec_b2      = (const float*)d_in[25];
    const int*   edge_index = (const int*)d_in[26];
    float* out = (float*)d_out;

    float *p_h1, *p_x;
    __nv_bfloat16 *p_Ah, *p_Al, *p_Bh, *p_Bl, *p_Ah2, *p_Al2, *p_Bh2, *p_Bl2;
    cudaGetSymbolAddress((void**)&p_h1, g_h1);
    cudaGetSymbolAddress((void**)&p_x, g_x);
    cudaGetSymbolAddress((void**)&p_Ah, g_Ah);
    cudaGetSymbolAddress((void**)&p_Al, g_Al);
    cudaGetSymbolAddress((void**)&p_Bh, g_Bh);
    cudaGetSymbolAddress((void**)&p_Bl, g_Bl);
    cudaGetSymbolAddress((void**)&p_Ah2, g_Ah2);
    cudaGetSymbolAddress((void**)&p_Al2, g_Al2);
    cudaGetSymbolAddress((void**)&p_Bh2, g_Bh2);
    cudaGetSymbolAddress((void**)&p_Bl2, g_Bl2);

    cudaFuncSetAttribute(k_mma, cudaFuncAttributeMaxDynamicSharedMemorySize,
                         MMA_SMEM_TOTAL);

    // 0) B operand conversions (transpose + split)
    {
        dim3 g(VLAD_DIM / 32, N_PAD / 32);       // hw  -> g_Bh/g_Bl
        k_cvt_trans<<<g, 256>>>(nv_hw, H0D, VLAD_DIM, H0D, p_Bh, p_Bl, VLAD_DIM);
    }
    {
        dim3 g(K2PAD / 32, N2PAD / 32);          // ne_w1 -> g_Bh2/g_Bl2
        k_cvt_trans<<<g, 256>>>(ne_w1, H1D, H0D, H1D, p_Bh2, p_Bl2, K2PAD);
    }
    // 1) fused NetVLAD -> g_Ah/g_Al (split bf16 direct)
    k_netvlad<<<N_NODES, 256>>>(node_feats, nv_cw, nv_cb, nv_cw2);

    // 2) G1 HMMA: h0 = vlad @ hw, emitted as split-bf16 A operand of G2
    {
        dim3 g(N_PAD / 128, M_PAD / 128);        // (8, 16)
        k_mma<<<g, 256, MMA_SMEM_TOTAL>>>(p_Ah, p_Al, p_Bh, p_Bl, VLAD_DIM,
                                          nullptr, N_NODES, H0D, nullptr, 0,
                                          p_Ah2, p_Al2, K2PAD);
    }
    // 3) G2 HMMA: h1 = relu(h0 @ ne_w1 + b1)
    {
        dim3 g(N2PAD / 128, M_PAD / 128);        // (4, 16)
        k_mma<<<g, 256, MMA_SMEM_TOTAL>>>(p_Ah2, p_Al2, p_Bh2, p_Bl2, K2PAD,
                                          p_h1, N_NODES, H1D, ne_b1, 1,
                                          nullptr, nullptr, 0);
    }
    // 4) G3: x = h1 @ ne_w2 + b2
    {
        dim3 g((NODE_D + 63) / 64, (N_NODES + 63) / 64);
        k_sgemm<<<g, 256>>>(p_h1, ne_w2, ne_b2, p_x, N_NODES, NODE_D, H1D, 0);
    }

    // 5) edge-attr MLP
    k_ef<<<(N_EDGES + 255) / 256, 256>>>(edge_attr, ee_w1, ee_b1, ee_w2, ee_b2, ee_w3, ee_b3);

    // 6) 3 GAT layers
    for (int l = 0; l < DEPTH; l++) {
        k_gat_h<<<N_NODES, 128>>>(gat_w + l * NODE_D * NODE_D,
                                  gat_as + l * NODE_D, gat_ad + l * NODE_D);
        k_init<<<(N_NODES * NODE_D + 255) / 256, 256>>>();
        k_edge1<<<(E_EXT + 255) / 256, 256>>>(edge_index);
        k_edge2<<<(E_EXT + 255) / 256, 256>>>(edge_index);
        k_edge3<<<((E_EXT * 32) + 255) / 256, 256>>>(edge_index);
        k_gat_fin<<<(N_NODES * NODE_D + 255) / 256, 256>>>(gat_b + l * NODE_D);
    }

    // 7) fused edge classifier -> out
    k_final<<<512, 128>>>(edge_index, dp_w, dp_b, ec_w1, ec_b1, ec_w2, ec_b2, out);
}

// round 6
// speedup vs baseline: 2.4291x; 1.0425x over previous
#include <cuda_runtime.h>
#include <cuda_bf16.h>
#include <math.h>
#include <stdint.h>

#define N_NODES 2000
#define NUM_KP 500
#define KP_PAD 512
#define DESC 256
#define NVK 64
#define VLAD_DIM (DESC*NVK)        // 16384
#define H0D (NUM_KP*2)             // 1000
#define H1D NUM_KP                 // 500
#define NODE_D 128
#define EDGE_D 32
#define N_EDGES 64000
#define E_EXT (N_EDGES + N_NODES)  // 66000
#define DEPTH 3

#define M_PAD 2048
#define N_PAD 1024
#define K2PAD 1024
#define N2PAD 512

typedef unsigned long long u64;

// ---------------- scratch (device globals; no runtime allocation) ----------
__device__ float    g_h1[N_NODES * H1D];
__device__ float    g_x[N_NODES * NODE_D];
__device__ float    g_h[N_NODES * NODE_D];
__device__ float    g_es[N_NODES];
__device__ float    g_ed[N_NODES];
__device__ float    g_ex[E_EXT];
__device__ float    g_den[N_NODES];
__device__ float    g_aggr[N_NODES * NODE_D];
__device__ float    g_ef2[N_EDGES * EDGE_D];
__device__ float    g_asum[N_NODES * NVK];
// split-bf16 operands (pad regions stay zero: static zero-init, never written)
__device__ __nv_bfloat16 g_Ah[(size_t)M_PAD * VLAD_DIM];
__device__ __nv_bfloat16 g_Al[(size_t)M_PAD * VLAD_DIM];
__device__ __nv_bfloat16 g_Bh[(size_t)N_PAD * VLAD_DIM];
__device__ __nv_bfloat16 g_Bl[(size_t)N_PAD * VLAD_DIM];
__device__ __nv_bfloat16 g_Ah2[(size_t)M_PAD * K2PAD];
__device__ __nv_bfloat16 g_Al2[(size_t)M_PAD * K2PAD];
__device__ __nv_bfloat16 g_Bh2[(size_t)N2PAD * K2PAD];
__device__ __nv_bfloat16 g_Bl2[(size_t)N2PAD * K2PAD];
// NetVLAD intermediates
__device__ __nv_bfloat16 g_cwTh[NVK * DESC];
__device__ __nv_bfloat16 g_cwTl[NVK * DESC];
__device__ __nv_bfloat16 g_acth[(size_t)N_NODES * KP_PAD * NVK];  // 131 MB
__device__ __nv_bfloat16 g_actl[(size_t)N_NODES * KP_PAD * NVK];  // 131 MB

// ---------------- helpers ---------------------------------------------------
__device__ __forceinline__ uint32_t smem_u32(const void* p) {
    uint32_t a;
    asm("{ .reg .u64 t; cvta.to.shared.u64 t, %1; cvt.u32.u64 %0, t; }" : "=r"(a) : "l"(p));
    return a;
}
__device__ __forceinline__ uint32_t lds32(uint32_t addr) {
    uint32_t v;
    asm volatile("ld.shared.b32 %0, [%1];" : "=r"(v) : "r"(addr));
    return v;
}
__device__ __forceinline__ void mma16816(float* c, const uint32_t* a, const uint32_t* b) {
    asm volatile(
        "mma.sync.aligned.m16n8k16.row.col.f32.bf16.bf16.f32 "
        "{%0,%1,%2,%3}, {%4,%5,%6,%7}, {%8,%9}, {%0,%1,%2,%3};"
        : "+f"(c[0]), "+f"(c[1]), "+f"(c[2]), "+f"(c[3])
        : "r"(a[0]), "r"(a[1]), "r"(a[2]), "r"(a[3]), "r"(b[0]), "r"(b[1]));
}
#define CP_ASYNC16(dst, src) \
    asm volatile("cp.async.cg.shared.global [%0], [%1], 16;" :: "r"(dst), "l"(src) : "memory")
#define CP_COMMIT()  asm volatile("cp.async.commit_group;" ::: "memory")
#define CP_WAIT0()   asm volatile("cp.async.wait_group 0;" ::: "memory")

__device__ __forceinline__ float sanit(float v) {
    if (!isfinite(v)) v = (v != v) ? 0.f : (v > 0.f ? 3.402823466e38f : -3.402823466e38f);
    return v;
}

// ---------------------------------------------------------------------------
// Prep: cw [256][64] fp32 -> cw^T split-bf16 [64][256]
// ---------------------------------------------------------------------------
__global__ void k_prep_cw(const float* __restrict__ cw)
{
    int i = blockIdx.x * 256 + threadIdx.x;    // 0..16383
    int k = i >> 8, d = i & 255;
    float v = cw[d * 64 + k];
    __nv_bfloat16 h = __float2bfloat16(v);
    g_cwTh[k * 256 + d] = h;
    g_cwTl[k * 256 + d] = __float2bfloat16(v - __bfloat162float(h));
}

// ---------------------------------------------------------------------------
// NetVLAD stage 1: logits GEMM (HMMA) + softmax. Grid (8 n-blocks, 2000 nodes).
// Writes act split-bf16 [b][512][64] and accumulates g_asum[b][k].
// ---------------------------------------------------------------------------
#define A_SMEM 154624
__global__ void __launch_bounds__(256, 1) k_logits(
    const float* __restrict__ feats, const float* __restrict__ cb)
{
    extern __shared__ __align__(16) char sm[];
    int b = blockIdx.y, nb = blockIdx.x;
    int tid = threadIdx.x, lane = tid & 31, wid = tid >> 5;

    char* xh = sm;                       // [64 n][264 d] bf16 (pitch 528B)
    char* xl = sm + 33792;
    char* ch = sm + 67584;               // [64 k][264 d] bf16
    char* cl = sm + 101376;
    float* logit = (float*)(sm + 135168);// [64][68] fp32
    float* red   = (float*)(sm + 152576);// [8][64]

    // stage cw^T (pre-split)
    for (int i = tid; i < 64 * 32; i += 256) {     // uint4 = 8 bf16
        int k = i >> 5, c = i & 31;
        *(uint4*)(ch + k * 528 + c * 16) = ((const uint4*)g_cwTh)[i];
        *(uint4*)(cl + k * 528 + c * 16) = ((const uint4*)g_cwTl)[i];
    }
    // stage x block (sanitize + split), rows gn = nb*64 + row
    for (int i = tid; i < 4096; i += 256) {
        int row = i >> 6, c4 = i & 63;
        int gn = nb * 64 + row;
        float4 v = make_float4(0.f, 0.f, 0.f, 0.f);
        if (gn < NUM_KP) v = ((const float4*)feats)[((size_t)b * NUM_KP + gn) * 64 + c4];
        v.x = sanit(v.x); v.y = sanit(v.y); v.z = sanit(v.z); v.w = sanit(v.w);
        __nv_bfloat16 h0 = __float2bfloat16(v.x), h1 = __float2bfloat16(v.y);
        __nv_bfloat16 h2 = __float2bfloat16(v.z), h3 = __float2bfloat16(v.w);
        *(__nv_bfloat162*)(xh + row * 528 + c4 * 8)     = __nv_bfloat162(h0, h1);
        *(__nv_bfloat162*)(xh + row * 528 + c4 * 8 + 4) = __nv_bfloat162(h2, h3);
        *(__nv_bfloat162*)(xl + row * 528 + c4 * 8)     = __nv_bfloat162(
            __float2bfloat16(v.x - __bfloat162float(h0)),
            __float2bfloat16(v.y - __bfloat162float(h1)));
        *(__nv_bfloat162*)(xl + row * 528 + c4 * 8 + 4) = __nv_bfloat162(
            __float2bfloat16(v.z - __bfloat162float(h2)),
            __float2bfloat16(v.w - __bfloat162float(h3)));
    }
    __syncthreads();

    int wm = wid & 3, wn = wid >> 2;
    int lr = lane >> 2, lc = (lane & 3) * 2;
    uint32_t xh_s = smem_u32(xh), xl_s = smem_u32(xl);
    uint32_t ch_s = smem_u32(ch), cl_s = smem_u32(cl);

    float acc[4][4];
#pragma unroll
    for (int nt = 0; nt < 4; nt++)
#pragma unroll
        for (int q = 0; q < 4; q++) acc[nt][q] = 0.f;

#pragma unroll
    for (int ks = 0; ks < 16; ks++) {
        int kl = ks * 16;
        uint32_t abase = (uint32_t)((wm * 16 + lr) * 528 + (kl + lc) * 2);
        uint32_t a[4]  = { lds32(xh_s + abase), lds32(xh_s + abase + 4224),
                           lds32(xh_s + abase + 16), lds32(xh_s + abase + 4240) };
        uint32_t al_[4] = { lds32(xl_s + abase), lds32(xl_s + abase + 4224),
                            lds32(xl_s + abase + 16), lds32(xl_s + abase + 4240) };
#pragma unroll
        for (int nt = 0; nt < 4; nt++) {
            uint32_t bb = (uint32_t)((wn * 32 + nt * 8 + lr) * 528 + (kl + lc) * 2);
            uint32_t bhf[2] = { lds32(ch_s + bb), lds32(ch_s + bb + 16) };
            uint32_t blf[2] = { lds32(cl_s + bb), lds32(cl_s + bb + 16) };
            mma16816(acc[nt], a, bhf);
            mma16816(acc[nt], a, blf);
            mma16816(acc[nt], al_, bhf);
        }
    }
    // logits -> smem
#pragma unroll
    for (int nt = 0; nt < 4; nt++)
#pragma unroll
        for (int q = 0; q < 4; q++) {
            int row = wm * 16 + lr + ((q >> 1) * 8);
            int col = wn * 32 + nt * 8 + lc + (q & 1);
            logit[row * 68 + col] = acc[nt][q];
        }
    __syncthreads();

    // softmax: warp wid handles rows wid*8 .. +7
    float cb0 = cb[lane], cb1 = cb[lane + 32];
    float s0 = 0.f, s1 = 0.f;
#pragma unroll
    for (int rr = 0; rr < 8; rr++) {
        int row = wid * 8 + rr;
        int gn = nb * 64 + row;
        float l0 = logit[row * 68 + lane] + cb0;
        float l1 = logit[row * 68 + lane + 32] + cb1;
        float m = fmaxf(l0, l1);
#pragma unroll
        for (int off = 16; off; off >>= 1) m = fmaxf(m, __shfl_xor_sync(0xFFFFFFFFu, m, off));
        float e0 = __expf(l0 - m), e1 = __expf(l1 - m);
        float ss = e0 + e1;
#pragma unroll
        for (int off = 16; off; off >>= 1) ss += __shfl_xor_sync(0xFFFFFFFFu, ss, off);
        float inv = 1.f / ss;
        e0 *= inv; e1 *= inv;
        if (gn < NUM_KP) {
            size_t o = ((size_t)b * KP_PAD + gn) * 64;
            __nv_bfloat16 h0 = __float2bfloat16(e0), h1 = __float2bfloat16(e1);
            g_acth[o + lane]      = h0;
            g_acth[o + lane + 32] = h1;
            g_actl[o + lane]      = __float2bfloat16(e0 - __bfloat162float(h0));
            g_actl[o + lane + 32] = __float2bfloat16(e1 - __bfloat162float(h1));
            s0 += e0; s1 += e1;
        }
    }
    red[wid * 64 + lane]      = s0;
    red[wid * 64 + lane + 32] = s1;
    __syncthreads();
    if (tid < 32) {
        float t0 = 0.f, t1 = 0.f;
#pragma unroll
        for (int w = 0; w < 8; w++) { t0 += red[w * 64 + lane]; t1 += red[w * 64 + lane + 32]; }
        atomicAdd(&g_asum[b * 64 + lane], t0);
        atomicAdd(&g_asum[b * 64 + lane + 32], t1);
    }
}

// ---------------------------------------------------------------------------
// NetVLAD stage 2: vlad GEMM (HMMA) + full epilogue. One CTA per node.
// C[d=256][k=64] = sum_n x^T . act^T; subtract asum*cw2; intra+full norm;
// split-bf16 output directly into g_Ah/g_Al.
// ---------------------------------------------------------------------------
#define B_SMEM 159248
__global__ void __launch_bounds__(256, 1) k_vlad(
    const float* __restrict__ feats, const float* __restrict__ cw2)
{
    extern __shared__ __align__(16) char sm[];
    int b = blockIdx.x;
    int tid = threadIdx.x, lane = tid & 31, wid = tid >> 5;
    int wm = wid & 3, wn = wid >> 2;
    int lr = lane >> 2, lc = (lane & 3) * 2;

    float* cw2s  = (float*)sm;                 // 65536
    float* asums = (float*)(sm + 65536);       // 256
    char*  xh    = sm + 65792;                 // [256 d][72 n] bf16
    char*  xl    = sm + 102656;
    char*  bah   = sm + 139520;                // [64 k][72 n] bf16
    char*  bal   = sm + 148736;
    float* redk  = (float*)(sm + 157952);      // [64][4]
    float* invk  = (float*)(sm + 158976);      // [64]
    float* invts = (float*)(sm + 159232);

    for (int i = tid; i < 4096; i += 256)
        ((float4*)cw2s)[i] = ((const float4*)cw2)[i];
    if (tid < 64) asums[tid] = g_asum[b * 64 + tid];

    uint32_t xh_s = smem_u32(xh), xl_s = smem_u32(xl);
    uint32_t bh_s = smem_u32(bah), bl_s = smem_u32(bal);

    float acc[4][4][4];
#pragma unroll
    for (int mt = 0; mt < 4; mt++)
#pragma unroll
        for (int nt = 0; nt < 4; nt++)
#pragma unroll
            for (int q = 0; q < 4; q++) acc[mt][nt][q] = 0.f;

    for (int kb = 0; kb < 8; kb++) {
        __syncthreads();      // protect smem tiles against prior-iter readers
        int n0 = kb * 64;
        // stage x transposed: [n][d] fp32 -> xh/xl [d][72]
        for (int i = tid; i < 4096; i += 256) {
            int row = i >> 6, c4 = i & 63;
            int gn = n0 + row;
            float4 v = make_float4(0.f, 0.f, 0.f, 0.f);
            if (gn < NUM_KP) v = ((const float4*)feats)[((size_t)b * NUM_KP + gn) * 64 + c4];
            float vv[4] = { sanit(v.x), sanit(v.y), sanit(v.z), sanit(v.w) };
#pragma unroll
            for (int j = 0; j < 4; j++) {
                int d = c4 * 4 + j;
                __nv_bfloat16 h = __float2bfloat16(vv[j]);
                *(__nv_bfloat16*)(xh + (d * 72 + row) * 2) = h;
                *(__nv_bfloat16*)(xl + (d * 72 + row) * 2) =
                    __float2bfloat16(vv[j] - __bfloat162float(h));
            }
        }
        // stage act transposed: [n][k] bf16 -> bah/bal [k][72]
        for (int i = tid; i < 2048; i += 256) {
            int n = i >> 5, kp = i & 31;
            size_t gi = ((size_t)b * KP_PAD + n0 + n) * 32 + kp;
            uint32_t vh = ((const uint32_t*)g_acth)[gi];
            uint32_t vl = ((const uint32_t*)g_actl)[gi];
            *(unsigned short*)(bah + ((2 * kp) * 72 + n) * 2)     = (unsigned short)(vh & 0xFFFF);
            *(unsigned short*)(bah + ((2 * kp + 1) * 72 + n) * 2) = (unsigned short)(vh >> 16);
            *(unsigned short*)(bal + ((2 * kp) * 72 + n) * 2)     = (unsigned short)(vl & 0xFFFF);
            *(unsigned short*)(bal + ((2 * kp + 1) * 72 + n) * 2) = (unsigned short)(vl >> 16);
        }
        __syncthreads();

#pragma unroll
        for (int ks = 0; ks < 4; ks++) {
            int kl = ks * 16;
            uint32_t bhf[4][2], blf[4][2];
#pragma unroll
            for (int nt = 0; nt < 4; nt++) {
                uint32_t bb = (uint32_t)((wn * 32 + nt * 8 + lr) * 72 + kl + lc) * 2;
                bhf[nt][0] = lds32(bh_s + bb);  bhf[nt][1] = lds32(bh_s + bb + 16);
                blf[nt][0] = lds32(bl_s + bb);  blf[nt][1] = lds32(bl_s + bb + 16);
            }
#pragma unroll
            for (int mt = 0; mt < 4; mt++) {
                uint32_t abase = (uint32_t)((wm * 64 + mt * 16 + lr) * 72 + kl + lc) * 2;
                uint32_t a[4]  = { lds32(xh_s + abase), lds32(xh_s + abase + 1152),
                                   lds32(xh_s + abase + 16), lds32(xh_s + abase + 1168) };
                uint32_t al_[4] = { lds32(xl_s + abase), lds32(xl_s + abase + 1152),
                                    lds32(xl_s + abase + 16), lds32(xl_s + abase + 1168) };
#pragma unroll
                for (int nt = 0; nt < 4; nt++) {
                    mma16816(acc[mt][nt], a, bhf[nt]);
                    mma16816(acc[mt][nt], a, blf[nt]);
                    mma16816(acc[mt][nt], al_, bhf[nt]);
                }
            }
        }
    }

    // epilogue: v = C - asum[k]*cw2[d][k]
#pragma unroll
    for (int mt = 0; mt < 4; mt++)
#pragma unroll
        for (int nt = 0; nt < 4; nt++)
#pragma unroll
            for (int q = 0; q < 4; q++) {
                int d = wm * 64 + mt * 16 + lr + ((q >> 1) * 8);
                int k = wn * 32 + nt * 8 + lc + (q & 1);
                acc[mt][nt][q] -= asums[k] * cw2s[d * 64 + k];
            }
    // per-k sum of squares (reduce over lr via shfl, over wm via smem)
#pragma unroll
    for (int nt = 0; nt < 4; nt++) {
        float sq0 = 0.f, sq1 = 0.f;
#pragma unroll
        for (int mt = 0; mt < 4; mt++) {
            sq0 += acc[mt][nt][0] * acc[mt][nt][0] + acc[mt][nt][2] * acc[mt][nt][2];
            sq1 += acc[mt][nt][1] * acc[mt][nt][1] + acc[mt][nt][3] * acc[mt][nt][3];
        }
        sq0 += __shfl_xor_sync(0xFFFFFFFFu, sq0, 4);
        sq0 += __shfl_xor_sync(0xFFFFFFFFu, sq0, 8);
        sq0 += __shfl_xor_sync(0xFFFFFFFFu, sq0, 16);
        sq1 += __shfl_xor_sync(0xFFFFFFFFu, sq1, 4);
        sq1 += __shfl_xor_sync(0xFFFFFFFFu, sq1, 8);
        sq1 += __shfl_xor_sync(0xFFFFFFFFu, sq1, 16);
        if (lr == 0) {
            int k0 = wn * 32 + nt * 8 + lc;
            redk[k0 * 4 + wm]       = sq0;
            redk[(k0 + 1) * 4 + wm] = sq1;
        }
    }
    __syncthreads();
    if (tid < 32) {
        float s0 = redk[lane * 4] + redk[lane * 4 + 1] + redk[lane * 4 + 2] + redk[lane * 4 + 3];
        int l2 = lane + 32;
        float s1 = redk[l2 * 4] + redk[l2 * 4 + 1] + redk[l2 * 4 + 2] + redk[l2 * 4 + 3];
        float i0 = 1.f / (sqrtf(s0) + 1e-12f);
        float i1 = 1.f / (sqrtf(s1) + 1e-12f);
        invk[lane] = i0; invk[l2] = i1;
        float tt = s0 * i0 * i0 + s1 * i1 * i1;
#pragma unroll
        for (int off = 16; off; off >>= 1) tt += __shfl_xor_sync(0xFFFFFFFFu, tt, off);
        if (lane == 0) invts[0] = 1.f / (sqrtf(tt) + 1e-12f);
    }
    __syncthreads();
    float invt = invts[0];

    // split-bf16 into staging (pitch 66, conflict-free), then coalesced out
#pragma unroll
    for (int mt = 0; mt < 4; mt++)
#pragma unroll
        for (int nt = 0; nt < 4; nt++)
#pragma unroll
            for (int q = 0; q < 4; q++) {
                int d = wm * 64 + mt * 16 + lr + ((q >> 1) * 8);
                int k = wn * 32 + nt * 8 + lc + (q & 1);
                float val = acc[mt][nt][q] * invk[k] * invt;
                __nv_bfloat16 h = __float2bfloat16(val);
                *(__nv_bfloat16*)(xh + (d * 66 + k) * 2) = h;
                *(__nv_bfloat16*)(xl + (d * 66 + k) * 2) =
                    __float2bfloat16(val - __bfloat162float(h));
            }
    __syncthreads();
    for (int i = tid; i < 8192; i += 256) {
        int d = i >> 5, kp = i & 31;
        uint32_t vh = lds32(xh_s + (uint32_t)(d * 66 + kp * 2) * 2);
        uint32_t vl = lds32(xl_s + (uint32_t)(d * 66 + kp * 2) * 2);
        size_t go = (size_t)b * VLAD_DIM + d * 64 + kp * 2;
        *(uint32_t*)((char*)g_Ah + go * 2) = vh;
        *(uint32_t*)((char*)g_Al + go * 2) = vl;
    }
}

// ---------------------------------------------------------------------------
// Transpose + split: src[k][n] fp32 -> dh/dl[n][k] bf16 (pads zero-filled).
// ---------------------------------------------------------------------------
__global__ void __launch_bounds__(256) k_cvt_trans(
    const float* __restrict__ src, int ldsrc, int Kreal, int Nreal,
    __nv_bfloat16* __restrict__ dh, __nv_bfloat16* __restrict__ dl, int ldd)
{
    __shared__ float smt[32][33];
    int k0 = blockIdx.x * 32;
    int n0 = blockIdx.y * 32;
    int tx = threadIdx.x & 31;
    int ty = threadIdx.x >> 5;
#pragma unroll
    for (int i = 0; i < 4; i++) {
        int kk = ty + i * 8;
        int n = n0 + tx;
        float v = (k0 + kk < Kreal && n < Nreal) ? src[(size_t)(k0 + kk) * ldsrc + n] : 0.f;
        smt[kk][tx] = v;
    }
    __syncthreads();
#pragma unroll
    for (int i = 0; i < 4; i++) {
        int nn = ty + i * 8;
        float v = smt[tx][nn];
        __nv_bfloat16 h = __float2bfloat16(v);
        __nv_bfloat16 l = __float2bfloat16(v - __bfloat162float(h));
        size_t o = (size_t)(n0 + nn) * ldd + k0 + tx;
        dh[o] = h;
        dl[o] = l;
    }
}

// ---------------------------------------------------------------------------
// Split-bf16 HMMA GEMM (unchanged from R5, passing).
// ---------------------------------------------------------------------------
#define KBLK 64
#define SPITCH 72
#define SPB (SPITCH * 2)
#define TILE_B (128 * SPB)
#define STAGE_B (4 * TILE_B)
#define MMA_SMEM_TOTAL (2 * STAGE_B)

__global__ void __launch_bounds__(256, 1) k_mma(
    const __nv_bfloat16* __restrict__ Ah, const __nv_bfloat16* __restrict__ Al,
    const __nv_bfloat16* __restrict__ Bh, const __nv_bfloat16* __restrict__ Bl,
    int K, float* __restrict__ C, int M, int N,
    const float* __restrict__ bias, int act,
    __nv_bfloat16* __restrict__ Dh, __nv_bfloat16* __restrict__ Dl, int ldd)
{
    extern __shared__ __align__(16) char smem[];
    uint32_t sb = smem_u32(smem);
    int tid = threadIdx.x;
    int wid = tid >> 5, lane = tid & 31;
    int wm = wid & 3;
    int wn = wid >> 2;
    int m0 = blockIdx.y * 128;
    int n0 = blockIdx.x * 128;

    const __nv_bfloat16* srcs[4] = {
        Ah + (size_t)m0 * K, Al + (size_t)m0 * K,
        Bh + (size_t)n0 * K, Bl + (size_t)n0 * K };

    int lrow = tid >> 3;
    int lchk = tid & 7;

    float acc[2][8][4];
#pragma unroll
    for (int i = 0; i < 2; i++)
#pragma unroll
        for (int j = 0; j < 8; j++)
#pragma unroll
            for (int q = 0; q < 4; q++) acc[i][j][q] = 0.f;

    auto load_stage = [&](int s, int kb) {
        uint32_t sd = sb + s * STAGE_B;
        size_t kOff = (size_t)kb * KBLK;
#pragma unroll
        for (int v = 0; v < 4; v++) {
            const __nv_bfloat16* g = srcs[v] + kOff;
#pragma unroll
            for (int p = 0; p < 4; p++) {
                int rr = lrow + p * 32;
                uint32_t d = sd + v * TILE_B + rr * SPB + lchk * 16;
                const void* sptr = (const char*)(g + (size_t)rr * K) + lchk * 16;
                CP_ASYNC16(d, sptr);
            }
        }
        CP_COMMIT();
    };

    load_stage(0, 0);

    int lr = lane >> 2;
    int lc = (lane & 3) * 2;
    int nkb = K / KBLK;

    for (int kb = 0; kb < nkb; kb++) {
        int s = kb & 1;
        CP_WAIT0();
        __syncthreads();
        if (kb + 1 < nkb) load_stage(s ^ 1, kb + 1);

        uint32_t sAh = sb + s * STAGE_B;
        uint32_t sAl = sAh + TILE_B;
        uint32_t sBh = sAh + 2 * TILE_B;
        uint32_t sBl = sAh + 3 * TILE_B;

#pragma unroll
        for (int ks = 0; ks < 4; ks++) {
            int kl = ks * 16;
            uint32_t ah[2][4], al_[2][4];
#pragma unroll
            for (int mt = 0; mt < 2; mt++) {
                uint32_t base = (uint32_t)((wm * 32 + mt * 16 + lr) * SPB + (kl + lc) * 2);
                ah[mt][0]  = lds32(sAh + base);
                ah[mt][1]  = lds32(sAh + base + 8 * SPB);
                ah[mt][2]  = lds32(sAh + base + 16);
                ah[mt][3]  = lds32(sAh + base + 8 * SPB + 16);
                al_[mt][0] = lds32(sAl + base);
                al_[mt][1] = lds32(sAl + base + 8 * SPB);
                al_[mt][2] = lds32(sAl + base + 16);
                al_[mt][3] = lds32(sAl + base + 8 * SPB + 16);
            }
            uint32_t bh[8][2], bl_[8][2];
#pragma unroll
            for (int nt = 0; nt < 8; nt++) {
                uint32_t base = (uint32_t)((wn * 64 + nt * 8 + lr) * SPB + (kl + lc) * 2);
                bh[nt][0]  = lds32(sBh + base);
                bh[nt][1]  = lds32(sBh + base + 16);
                bl_[nt][0] = lds32(sBl + base);
                bl_[nt][1] = lds32(sBl + base + 16);
            }
#pragma unroll
            for (int mt = 0; mt < 2; mt++)
#pragma unroll
                for (int nt = 0; nt < 8; nt++) {
                    mma16816(acc[mt][nt], ah[mt], bh[nt]);
                    mma16816(acc[mt][nt], ah[mt], bl_[nt]);
                    mma16816(acc[mt][nt], al_[mt], bh[nt]);
                }
        }
    }

    auto emit = [&](int r, int c, float v) {
        bool in = (r < M && c < N);
        float val = 0.f;
        if (in) {
            val = v + (bias ? bias[c] : 0.f);
            if (act == 1) val = fmaxf(val, 0.f);
            if (C) C[(size_t)r * N + c] = val;
        }
        if (Dh) {
            __nv_bfloat16 h = __float2bfloat16(val);
            Dh[(size_t)r * ldd + c] = h;
            Dl[(size_t)r * ldd + c] = __float2bfloat16(val - __bfloat162float(h));
        }
    };
#pragma unroll
    for (int mt = 0; mt < 2; mt++) {
#pragma unroll
        for (int nt = 0; nt < 8; nt++) {
            int r = m0 + wm * 32 + mt * 16 + lr;
            int c = n0 + wn * 64 + nt * 8 + lc;
            emit(r,     c,     acc[mt][nt][0]);
            emit(r,     c + 1, acc[mt][nt][1]);
            emit(r + 8, c,     acc[mt][nt][2]);
            emit(r + 8, c + 1, acc[mt][nt][3]);
        }
    }
}

// ---------------------------------------------------------------------------
// Small SGEMM (64x64x16) for G3.
// ---------------------------------------------------------------------------
__global__ void __launch_bounds__(256) k_sgemm(
    const float* __restrict__ A, const float* __restrict__ B,
    const float* __restrict__ bias, float* __restrict__ C,
    int M, int N, int K, int act)
{
    __shared__ __align__(16) float As[16][64];
    __shared__ __align__(16) float Bs[16][64];

    int tid = threadIdx.x;
    int tx = tid & 15, ty = tid >> 4;
    int row0 = blockIdx.y * 64, col0 = blockIdx.x * 64;

    float c[4][4];
#pragma unroll
    for (int i = 0; i < 4; i++)
#pragma unroll
        for (int j = 0; j < 4; j++) c[i][j] = 0.f;

    int am = tid >> 2;
    int ak = (tid & 3) * 4;
    int bk = tid >> 4;
    int bn = (tid & 15) * 4;

    for (int k0 = 0; k0 < K; k0 += 16) {
        int arow = row0 + am;
        if (arow < M && k0 + ak + 3 < K) {
            float4 v = *reinterpret_cast<const float4*>(&A[(size_t)arow * K + k0 + ak]);
            As[ak + 0][am] = v.x; As[ak + 1][am] = v.y;
            As[ak + 2][am] = v.z; As[ak + 3][am] = v.w;
        } else {
#pragma unroll
            for (int i = 0; i < 4; i++) {
                int kk = k0 + ak + i;
                As[ak + i][am] = (arow < M && kk < K) ? A[(size_t)arow * K + kk] : 0.f;
            }
        }
        int brow = k0 + bk;
        if (brow < K && col0 + bn + 3 < N) {
            float4 v = *reinterpret_cast<const float4*>(&B[(size_t)brow * N + col0 + bn]);
            *reinterpret_cast<float4*>(&Bs[bk][bn]) = v;
        } else {
#pragma unroll
            for (int i = 0; i < 4; i++) {
                int nn = col0 + bn + i;
                Bs[bk][bn + i] = (brow < K && nn < N) ? B[(size_t)brow * N + nn] : 0.f;
            }
        }
        __syncthreads();
#pragma unroll
        for (int kk = 0; kk < 16; kk++) {
            float4 av = *reinterpret_cast<const float4*>(&As[kk][ty * 4]);
            float4 bv = *reinterpret_cast<const float4*>(&Bs[kk][tx * 4]);
            float a[4] = {av.x, av.y, av.z, av.w};
            float bb[4] = {bv.x, bv.y, bv.z, bv.w};
#pragma unroll
            for (int i = 0; i < 4; i++)
#pragma unroll
                for (int j = 0; j < 4; j++) c[i][j] = fmaf(a[i], bb[j], c[i][j]);
        }
        __syncthreads();
    }

#pragma unroll
    for (int i = 0; i < 4; i++) {
        int r = row0 + ty * 4 + i;
        if (r >= M) continue;
#pragma unroll
        for (int j = 0; j < 4; j++) {
            int cc = col0 + tx * 4 + j;
            if (cc >= N) continue;
            float v = c[i][j];
            if (bias) v += bias[cc];
            if (act == 1) v = fmaxf(v, 0.f);
            C[(size_t)r * N + cc] = v;
        }
    }
}

// ---------------------------------------------------------------------------
// GAT kernels
// ---------------------------------------------------------------------------
__global__ void __launch_bounds__(128) k_gat_h(
    const float* __restrict__ W, const float* __restrict__ a_s,
    const float* __restrict__ a_d)
{
    int b = blockIdx.x, t = threadIdx.x;
    __shared__ float xsm[NODE_D];
    __shared__ float rs[8];
    xsm[t] = g_x[b * NODE_D + t];
    __syncthreads();
    float acc = 0.f;
#pragma unroll 8
    for (int d = 0; d < NODE_D; d++) acc = fmaf(xsm[d], __ldg(&W[d * NODE_D + t]), acc);
    g_h[b * NODE_D + t] = acc;
    float ps = acc * __ldg(&a_s[t]);
    float pd = acc * __ldg(&a_d[t]);
#pragma unroll
    for (int off = 16; off; off >>= 1) {
        ps += __shfl_xor_sync(0xFFFFFFFFu, ps, off);
        pd += __shfl_xor_sync(0xFFFFFFFFu, pd, off);
    }
    if ((t & 31) == 0) { rs[t >> 5] = ps; rs[4 + (t >> 5)] = pd; }
    __syncthreads();
    if (t == 0) g_es[b] = rs[0] + rs[1] + rs[2] + rs[3];
    if (t == 1) g_ed[b] = rs[4] + rs[5] + rs[6] + rs[7];
}

__global__ void k_init()
{
    int i = blockIdx.x * blockDim.x + threadIdx.x;
    if (i < N_NODES) g_den[i] = 0.f;
    if (i < N_NODES * NODE_D) g_aggr[i] = 0.f;
}

// fused: e -> leaky -> exp -> den  (no max subtraction; alpha identical)
__global__ void k_edge12(const int* __restrict__ ei)
{
    int e = blockIdx.x * blockDim.x + threadIdx.x;
    if (e >= E_EXT) return;
    int s, d;
    if (e < N_EDGES) { s = ei[e]; d = ei[N_EDGES + e]; }
    else { s = e - N_EDGES; d = s; }
    float v = g_es[s] + g_ed[d];
    v = (v > 0.f) ? v : 0.2f * v;
    float ex = __expf(v);
    g_ex[e] = ex;
    atomicAdd(&g_den[d], ex);
}

__global__ void k_edge3(const int* __restrict__ ei)
{
    int gt = blockIdx.x * blockDim.x + threadIdx.x;
    int w = gt >> 5, lane = gt & 31;
    if (w >= E_EXT) return;
    int s, d;
    if (w < N_EDGES) { s = ei[w]; d = ei[N_EDGES + w]; }
    else { s = w - N_EDGES; d = s; }
    float alpha = g_ex[w] / g_den[d];
#pragma unroll
    for (int i = 0; i < 4; i++) {
        int c = lane + 32 * i;
        atomicAdd(&g_aggr[d * NODE_D + c], g_h[s * NODE_D + c] * alpha);
    }
}

__global__ void k_gat_fin(const float* __restrict__ b)
{
    int i = blockIdx.x * blockDim.x + threadIdx.x;
    if (i >= N_NODES * NODE_D) return;
    float v = g_aggr[i] + __ldg(&b[i & (NODE_D - 1)]);
    g_x[i] = (v > 0.f) ? v : (__expf(v) - 1.f);
}

// ---------------------------------------------------------------------------
// Edge-attr MLP: 1 -> 8 -> 16 -> 32
// ---------------------------------------------------------------------------
__global__ void __launch_bounds__(256) k_ef(
    const float* __restrict__ ea,
    const float* __restrict__ w1, const float* __restrict__ b1,
    const float* __restrict__ w2, const float* __restrict__ b2,
    const float* __restrict__ w3, const float* __restrict__ b3)
{
    __shared__ float w1s[8], b1s[8], w2s[128], b2s[16], w3s[512], b3s[32];
    int t = threadIdx.x;
    if (t < 8)   { w1s[t] = w1[t]; b1s[t] = b1[t]; }
    if (t < 128) w2s[t] = w2[t];
    if (t < 16)  b2s[t] = b2[t];
    if (t < 32)  b3s[t] = b3[t];
    for (int i = t; i < 512; i += blockDim.x) w3s[i] = w3[i];
    __syncthreads();
    int e = blockIdx.x * blockDim.x + t;
    if (e >= N_EDGES) return;
    float a = ea[e];
    float t8[8];
#pragma unroll
    for (int j = 0; j < 8; j++) t8[j] = fmaxf(fmaf(a, w1s[j], b1s[j]), 0.f);
    float t16[16];
#pragma unroll
    for (int c = 0; c < 16; c++) {
        float acc = b2s[c];
#pragma unroll
        for (int j = 0; j < 8; j++) acc = fmaf(t8[j], w2s[j * 16 + c], acc);
        t16[c] = fmaxf(acc, 0.f);
    }
#pragma unroll
    for (int c = 0; c < 32; c++) {
        float acc = b3s[c];
#pragma unroll
        for (int j = 0; j < 16; j++) acc = fmaf(t16[j], w3s[j * 32 + c], acc);
        g_ef2[e * EDGE_D + c] = acc;
    }
}

// ---------------------------------------------------------------------------
// Final fused edge classifier.
// ---------------------------------------------------------------------------
__global__ void __launch_bounds__(128) k_final(
    const int* __restrict__ ei,
    const float* __restrict__ dp_w, const float* __restrict__ dp_b,
    const float* __restrict__ ec_w1, const float* __restrict__ ec_b1,
    const float* __restrict__ ec_w2, const float* __restrict__ ec_b2,
    float* __restrict__ out)
{
    __shared__ float dpw_s[288 * 32];
    __shared__ float ecw1_s[32 * 16];
    __shared__ float dpb_s[32];
    __shared__ float ecb1_s[16];
    __shared__ float ecw2_s[16];
    __shared__ float vec_s[4][292];
    __shared__ float o32_s[4][32];

    int tid = threadIdx.x;
    for (int i = tid; i < 288 * 32; i += 128) dpw_s[i] = dp_w[i];
    for (int i = tid; i < 512; i += 128) ecw1_s[i] = ec_w1[i];
    if (tid < 32) dpb_s[tid] = dp_b[tid];
    if (tid < 16) { ecb1_s[tid] = ec_b1[tid]; ecw2_s[tid] = ec_w2[tid]; }
    __syncthreads();

    float b2 = __ldg(ec_b2);
    int warp = tid >> 5, lane = tid & 31;
    int gw = blockIdx.x * 4 + warp;
    int nw = gridDim.x * 4;

    for (int e = gw; e < N_EDGES; e += nw) {
        int s = ei[e], d = ei[N_EDGES + e];
        const float* xsp = g_x + s * NODE_D;
        const float* xdp = g_x + d * NODE_D;
#pragma unroll
        for (int i = 0; i < 4; i++) {
            vec_s[warp][lane + 32 * i]       = xsp[lane + 32 * i];
            vec_s[warp][128 + lane + 32 * i] = xdp[lane + 32 * i];
        }
        vec_s[warp][256 + lane] = g_ef2[e * EDGE_D + lane];
        __syncwarp();

        float acc = dpb_s[lane];
#pragma unroll 4
        for (int i = 0; i < 288; i++) acc = fmaf(vec_s[warp][i], dpw_s[i * 32 + lane], acc);
        o32_s[warp][lane] = acc;
        __syncwarp();

        float hh = 0.f;
        if (lane < 16) {
            hh = ecb1_s[lane];
#pragma unroll 4
            for (int j = 0; j < 32; j++) hh = fmaf(o32_s[warp][j], ecw1_s[j * 16 + lane], hh);
            hh = fmaxf(hh, 0.f) * ecw2_s[lane];
        }
#pragma unroll
        for (int off = 8; off; off >>= 1) hh += __shfl_xor_sync(0xFFFFFFFFu, hh, off);
        if (lane == 0) out[e] = 1.f / (1.f + __expf(-(hh + b2)));
        __syncwarp();
    }
}

// ---------------------------------------------------------------------------
extern "C" void kernel_launch(void* const* d_in, const int* in_sizes, int n_in,
                              void* d_out, int out_size)
{
    (void)in_sizes; (void)n_in; (void)out_size;
    const float* node_feats = (const float*)d_in[0];
    const float* edge_attr  = (const float*)d_in[1];
    const float* nv_cw      = (const float*)d_in[2];
    const float* nv_cb      = (const float*)d_in[3];
    const float* nv_cw2     = (const float*)d_in[4];
    const float* nv_hw      = (const float*)d_in[5];
    const float* ne_w1      = (const float*)d_in[6];
    const float* ne_b1      = (const float*)d_in[7];
    const float* ne_w2      = (const float*)d_in[8];
    const float* ne_b2      = (const float*)d_in[9];
    const float* ee_w1      = (const float*)d_in[10];
    const float* ee_b1      = (const float*)d_in[11];
    const float* ee_w2      = (const float*)d_in[12];
    const float* ee_b2      = (const float*)d_in[13];
    const float* ee_w3      = (const float*)d_in[14];
    const float* ee_b3      = (const float*)d_in[15];
    const float* gat_w      = (const float*)d_in[16];
    const float* gat_as     = (const float*)d_in[17];
    const float* gat_ad     = (const float*)d_in[18];
    const float* gat_b      = (const float*)d_in[19];
    const float* dp_w       = (const float*)d_in[20];
    const float* dp_b       = (const float*)d_in[21];
    const float* ec_w1      = (const float*)d_in[22];
    const float* ec_b1      = (const float*)d_in[23];
    const float* ec_w2      = (const float*)d_in[24];
    const float* ec_b2      = (const float*)d_in[25];
    const int*   edge_index = (const int*)d_in[26];
    float* out = (float*)d_out;

    float *p_h1, *p_x, *p_asum;
    __nv_bfloat16 *p_Ah, *p_Al, *p_Bh, *p_Bl, *p_Ah2, *p_Al2, *p_Bh2, *p_Bl2;
    cudaGetSymbolAddress((void**)&p_h1, g_h1);
    cudaGetSymbolAddress((void**)&p_x, g_x);
    cudaGetSymbolAddress((void**)&p_asum, g_asum);
    cudaGetSymbolAddress((void**)&p_Ah, g_Ah);
    cudaGetSymbolAddress((void**)&p_Al, g_Al);
    cudaGetSymbolAddress((void**)&p_Bh, g_Bh);
    cudaGetSymbolAddress((void**)&p_Bl, g_Bl);
    cudaGetSymbolAddress((void**)&p_Ah2, g_Ah2);
    cudaGetSymbolAddress((void**)&p_Al2, g_Al2);
    cudaGetSymbolAddress((void**)&p_Bh2, g_Bh2);
    cudaGetSymbolAddress((void**)&p_Bl2, g_Bl2);

    cudaFuncSetAttribute(k_mma, cudaFuncAttributeMaxDynamicSharedMemorySize, MMA_SMEM_TOTAL);
    cudaFuncSetAttribute(k_logits, cudaFuncAttributeMaxDynamicSharedMemorySize, A_SMEM);
    cudaFuncSetAttribute(k_vlad, cudaFuncAttributeMaxDynamicSharedMemorySize, B_SMEM);

    // 0) prep: cw^T split, asum zero, B operands
    k_prep_cw<<<64, 256>>>(nv_cw);
    cudaMemsetAsync(p_asum, 0, (size_t)N_NODES * NVK * sizeof(float));
    {
        dim3 g(VLAD_DIM / 32, N_PAD / 32);
        k_cvt_trans<<<g, 256>>>(nv_hw, H0D, VLAD_DIM, H0D, p_Bh, p_Bl, VLAD_DIM);
    }
    {
        dim3 g(K2PAD / 32, N2PAD / 32);
        k_cvt_trans<<<g, 256>>>(ne_w1, H1D, H0D, H1D, p_Bh2, p_Bl2, K2PAD);
    }

    // 1) NetVLAD stage 1: logits + softmax -> act, asum
    {
        dim3 g(8, N_NODES);
        k_logits<<<g, 256, A_SMEM>>>(node_feats, nv_cb);
    }
    // 2) NetVLAD stage 2: vlad GEMM + norms -> g_Ah/g_Al
    k_vlad<<<N_NODES, 256, B_SMEM>>>(node_feats, nv_cw2);

    // 3) G1 HMMA: h0 = vlad @ hw -> split-bf16 A operand of G2
    {
        dim3 g(N_PAD / 128, M_PAD / 128);
        k_mma<<<g, 256, MMA_SMEM_TOTAL>>>(p_Ah, p_Al, p_Bh, p_Bl, VLAD_DIM,
                                          nullptr, N_NODES, H0D, nullptr, 0,
                                          p_Ah2, p_Al2, K2PAD);
    }
    // 4) G2 HMMA: h1 = relu(h0 @ ne_w1 + b1)
    {
        dim3 g(N2PAD / 128, M_PAD / 128);
        k_mma<<<g, 256, MMA_SMEM_TOTAL>>>(p_Ah2, p_Al2, p_Bh2, p_Bl2, K2PAD,
                                          p_h1, N_NODES, H1D, ne_b1, 1,
                                          nullptr, nullptr, 0);
    }
    // 5) G3: x = h1 @ ne_w2 + b2
    {
        dim3 g((NODE_D + 63) / 64, (N_NODES + 63) / 64);
        k_sgemm<<<g, 256>>>(p_h1, ne_w2, ne_b2, p_x, N_NODES, NODE_D, H1D, 0);
    }

    // 6) edge-attr MLP
    k_ef<<<(N_EDGES + 255) / 256, 256>>>(edge_attr, ee_w1, ee_b1, ee_w2, ee_b2, ee_w3, ee_b3);

    // 7) 3 GAT layers
    for (int l = 0; l < DEPTH; l++) {
        k_gat_h<<<N_NODES, 128>>>(gat_w + l * NODE_D * NODE_D,
                                  gat_as + l * NODE_D, gat_ad + l * NODE_D);
        k_init<<<(N_NODES * NODE_D + 255) / 256, 256>>>();
        k_edge12<<<(E_EXT + 255) / 256, 256>>>(edge_index);
        k_edge3<<<((E_EXT * 32) + 255) / 256, 256>>>(edge_index);
        k_gat_fin<<<(N_NODES * NODE_D + 255) / 256, 256>>>(gat_b + l * NODE_D);
    }

    // 8) fused edge classifier -> out
    k_final<<<512, 128>>>(edge_index, dp_w, dp_b, ec_w1, ec_b1, ec_w2, ec_b2, out);
}

// round 8
// speedup vs baseline: 3.5162x; 1.4475x over previous
#include <cuda_runtime.h>
#include <cuda_bf16.h>
#include <math.h>
#include <stdint.h>

#define N_NODES 2000
#define NUM_KP 500
#define DESC 256
#define NVK 64
#define VLAD_DIM (DESC*NVK)        // 16384
#define H0D (NUM_KP*2)             // 1000
#define H1D NUM_KP                 // 500
#define NODE_D 128
#define EDGE_D 32
#define N_EDGES 64000
#define E_EXT (N_EDGES + N_NODES)  // 66000
#define DEPTH 3

#define M_PAD 2048
#define N_PAD 1024
#define K2PAD 1024
#define N2PAD 512

typedef unsigned long long u64;

// ---------------- scratch (device globals; no runtime allocation) ----------
__device__ float    g_h1[N_NODES * H1D];
__device__ float    g_x[N_NODES * NODE_D];
__device__ float    g_h[N_NODES * NODE_D];
__device__ float    g_es[N_NODES];
__device__ float    g_ed[N_NODES];
__device__ float    g_ex[E_EXT];
__device__ float    g_den[N_NODES];
__device__ float    g_aggr[N_NODES * NODE_D];
__device__ float    g_ef2[N_EDGES * EDGE_D];
// split-bf16 operands (pad regions stay zero: static zero-init, never written)
__device__ __nv_bfloat16 g_Ah[(size_t)M_PAD * VLAD_DIM];
__device__ __nv_bfloat16 g_Al[(size_t)M_PAD * VLAD_DIM];
__device__ __nv_bfloat16 g_Bh[(size_t)N_PAD * VLAD_DIM];
__device__ __nv_bfloat16 g_Bl[(size_t)N_PAD * VLAD_DIM];
__device__ __nv_bfloat16 g_Ah2[(size_t)M_PAD * K2PAD];
__device__ __nv_bfloat16 g_Al2[(size_t)M_PAD * K2PAD];
__device__ __nv_bfloat16 g_Bh2[(size_t)N2PAD * K2PAD];
__device__ __nv_bfloat16 g_Bl2[(size_t)N2PAD * K2PAD];
__device__ __nv_bfloat16 g_cwTh[NVK * DESC];
__device__ __nv_bfloat16 g_cwTl[NVK * DESC];

// ---------------- helpers ---------------------------------------------------
__device__ __forceinline__ uint32_t smem_u32(const void* p) {
    uint32_t a;
    asm("{ .reg .u64 t; cvta.to.shared.u64 t, %1; cvt.u32.u64 %0, t; }" : "=r"(a) : "l"(p));
    return a;
}
__device__ __forceinline__ uint32_t lds32(uint32_t addr) {
    uint32_t v;
    asm volatile("ld.shared.b32 %0, [%1];" : "=r"(v) : "r"(addr));
    return v;
}
__device__ __forceinline__ void mma16816(float* c, const uint32_t* a, const uint32_t* b) {
    asm volatile(
        "mma.sync.aligned.m16n8k16.row.col.f32.bf16.bf16.f32 "
        "{%0,%1,%2,%3}, {%4,%5,%6,%7}, {%8,%9}, {%0,%1,%2,%3};"
        : "+f"(c[0]), "+f"(c[1]), "+f"(c[2]), "+f"(c[3])
        : "r"(a[0]), "r"(a[1]), "r"(a[2]), "r"(a[3]), "r"(b[0]), "r"(b[1]));
}
#define CP_ASYNC16(dst, src) \
    asm volatile("cp.async.cg.shared.global [%0], [%1], 16;" :: "r"(dst), "l"(src) : "memory")
#define CP_COMMIT()  asm volatile("cp.async.commit_group;" ::: "memory")
#define CP_WAIT0()   asm volatile("cp.async.wait_group 0;" ::: "memory")

__device__ __forceinline__ float sanit(float v) {
    if (!isfinite(v)) v = (v != v) ? 0.f : (v > 0.f ? 3.402823466e38f : -3.402823466e38f);
    return v;
}

// ---------------------------------------------------------------------------
// Prep: cw [256][64] fp32 -> cw^T split-bf16 [64][256]
// ---------------------------------------------------------------------------
__global__ void k_prep_cw(const float* __restrict__ cw)
{
    int i = blockIdx.x * 256 + threadIdx.x;    // 0..16383
    int k = i >> 8, d = i & 255;
    float v = cw[d * 64 + k];
    __nv_bfloat16 h = __float2bfloat16(v);
    g_cwTh[k * 256 + d] = h;
    g_cwTl[k * 256 + d] = __float2bfloat16(v - __bfloat162float(h));
}

// ---------------------------------------------------------------------------
// FUSED NetVLAD: one CTA per node. 8 blocks of 64 keypoints:
//   stage x (both layouts) -> logits HMMA -> softmax (act stays in smem)
//   -> vlad HMMA accumulate in regs. Epilogue: -asum*cw2, norms, split-bf16
//   directly into g_Ah/g_Al. feats read once; act never leaves smem.
// smem pitches: row-major regions 528B (16B multiple: uint4-safe);
//               transposed regions 136B.
// ---------------------------------------------------------------------------
#define O_CWH 0          // cwT hi [64 k][264 d] bf16 (pitch 528B), 33792B
#define O_CWL 33792
#define O_XH  67584      // x hi [64 n][264 d], 33792B
#define O_XL  101376
#define O_XTH 135168     // xT hi [256 d][68 n] (pitch 136B), 34816B
#define O_XTL 169984
#define O_LOG 204800     // logits [64][68] f32 (17408B); reused as act after
#define O_ACTH 204800    // actT hi [64 k][68 n] bf16 (8704B)
#define O_ACTL 213504    // actT lo (8704B)
#define O_RED 222208     // [8][64] f32 (2048B)
#define O_ASUM 224256    // [64] f32
#define O_REDK 224512    // [64][4] f32
#define O_INVK 225536    // [64] f32
#define O_INVT 225792
#define NV_SMEM 225808

__global__ void __launch_bounds__(256, 1) k_nv(
    const float* __restrict__ feats, const float* __restrict__ cb,
    const float* __restrict__ cw2)
{
    extern __shared__ __align__(16) char sm[];
    int b = blockIdx.x;
    int tid = threadIdx.x, lane = tid & 31, wid = tid >> 5;
    int wm = wid & 3, wn = wid >> 2;
    int lr = lane >> 2, lc = (lane & 3) * 2;

    uint32_t cwh_s = smem_u32(sm + O_CWH), cwl_s = smem_u32(sm + O_CWL);
    uint32_t xh_s  = smem_u32(sm + O_XH),  xl_s  = smem_u32(sm + O_XL);
    uint32_t xth_s = smem_u32(sm + O_XTH), xtl_s = smem_u32(sm + O_XTL);
    uint32_t ah_s  = smem_u32(sm + O_ACTH), al_s = smem_u32(sm + O_ACTL);
    float* logit = (float*)(sm + O_LOG);
    float* red   = (float*)(sm + O_RED);
    float* asums = (float*)(sm + O_ASUM);
    float* redk  = (float*)(sm + O_REDK);
    float* invk  = (float*)(sm + O_INVK);
    float* invts = (float*)(sm + O_INVT);

    // stage cwT once (pre-split, packed [64][256] -> pitch 264 elems / 528B)
    for (int i = tid; i < 2048; i += 256) {
        int k = i >> 5, c = i & 31;
        *(uint4*)(sm + O_CWH + k * 528 + c * 16) = ((const uint4*)g_cwTh)[i];
        *(uint4*)(sm + O_CWL + k * 528 + c * 16) = ((const uint4*)g_cwTl)[i];
    }

    float accv[4][4][4];
#pragma unroll
    for (int mt = 0; mt < 4; mt++)
#pragma unroll
        for (int nt = 0; nt < 4; nt++)
#pragma unroll
            for (int q = 0; q < 4; q++) accv[mt][nt][q] = 0.f;
    float s0 = 0.f, s1 = 0.f;                  // asum partials (k=lane, lane+32)
    float cb0 = cb[lane], cb1 = cb[lane + 32];

    for (int kb = 0; kb < 8; kb++) {
        __syncthreads();                       // protect smem vs prior readers
        int n0 = kb * 64;
        // ---- stage x: row-major (logits A side) + transposed (vlad A) ----
        for (int i = tid; i < 4096; i += 256) {
            int row = i >> 6, c4 = i & 63;
            int gn = n0 + row;
            float4 v = make_float4(0.f, 0.f, 0.f, 0.f);
            if (gn < NUM_KP) v = ((const float4*)feats)[((size_t)b * NUM_KP + gn) * 64 + c4];
            float vv[4] = { sanit(v.x), sanit(v.y), sanit(v.z), sanit(v.w) };
            __nv_bfloat16 hh[4], ll[4];
#pragma unroll
            for (int j = 0; j < 4; j++) {
                hh[j] = __float2bfloat16(vv[j]);
                ll[j] = __float2bfloat16(vv[j] - __bfloat162float(hh[j]));
            }
            char* pxh = sm + O_XH + row * 528 + c4 * 8;
            char* pxl = sm + O_XL + row * 528 + c4 * 8;
            *(__nv_bfloat162*)pxh       = __nv_bfloat162(hh[0], hh[1]);
            *(__nv_bfloat162*)(pxh + 4) = __nv_bfloat162(hh[2], hh[3]);
            *(__nv_bfloat162*)pxl       = __nv_bfloat162(ll[0], ll[1]);
            *(__nv_bfloat162*)(pxl + 4) = __nv_bfloat162(ll[2], ll[3]);
#pragma unroll
            for (int j = 0; j < 4; j++) {
                int d = c4 * 4 + j;
                *(__nv_bfloat16*)(sm + O_XTH + d * 136 + row * 2) = hh[j];
                *(__nv_bfloat16*)(sm + O_XTL + d * 136 + row * 2) = ll[j];
            }
        }
        __syncthreads();

        // ---- logits GEMM: C[n=64][k=64], K=d=256 (warp tile 16x32) ----
        float acc[4][4];
#pragma unroll
        for (int nt = 0; nt < 4; nt++)
#pragma unroll
            for (int q = 0; q < 4; q++) acc[nt][q] = 0.f;
#pragma unroll
        for (int ks = 0; ks < 16; ks++) {
            int kl = ks * 16;
            uint32_t abase = (uint32_t)((wm * 16 + lr) * 528 + (kl + lc) * 2);
            uint32_t a[4]  = { lds32(xh_s + abase), lds32(xh_s + abase + 4224),
                               lds32(xh_s + abase + 16), lds32(xh_s + abase + 4240) };
            uint32_t al_[4] = { lds32(xl_s + abase), lds32(xl_s + abase + 4224),
                                lds32(xl_s + abase + 16), lds32(xl_s + abase + 4240) };
#pragma unroll
            for (int nt = 0; nt < 4; nt++) {
                uint32_t bb = (uint32_t)((wn * 32 + nt * 8 + lr) * 528 + (kl + lc) * 2);
                uint32_t bhf[2] = { lds32(cwh_s + bb), lds32(cwh_s + bb + 16) };
                uint32_t blf[2] = { lds32(cwl_s + bb), lds32(cwl_s + bb + 16) };
                mma16816(acc[nt], a, bhf);
                mma16816(acc[nt], a, blf);
                mma16816(acc[nt], al_, bhf);
            }
        }
#pragma unroll
        for (int nt = 0; nt < 4; nt++)
#pragma unroll
            for (int q = 0; q < 4; q++) {
                int row = wm * 16 + lr + ((q >> 1) * 8);
                int col = wn * 32 + nt * 8 + lc + (q & 1);
                logit[row * 68 + col] = acc[nt][q];
            }
        __syncthreads();

        // ---- softmax: pull this warp's 8 rows to regs, then write actT ----
        float l0r[8], l1r[8];
#pragma unroll
        for (int rr = 0; rr < 8; rr++) {
            int row = wid * 8 + rr;
            l0r[rr] = logit[row * 68 + lane] + cb0;
            l1r[rr] = logit[row * 68 + lane + 32] + cb1;
        }
        __syncthreads();    // all logits read before act overwrites the region
#pragma unroll
        for (int rr = 0; rr < 8; rr++) {
            int row = wid * 8 + rr;
            int gn = n0 + row;
            float m = fmaxf(l0r[rr], l1r[rr]);
#pragma unroll
            for (int off = 16; off; off >>= 1) m = fmaxf(m, __shfl_xor_sync(0xFFFFFFFFu, m, off));
            float e0 = __expf(l0r[rr] - m), e1 = __expf(l1r[rr] - m);
            float ss = e0 + e1;
#pragma unroll
            for (int off = 16; off; off >>= 1) ss += __shfl_xor_sync(0xFFFFFFFFu, ss, off);
            float inv = 1.f / ss;
            if (gn < NUM_KP) { e0 *= inv; e1 *= inv; s0 += e0; s1 += e1; }
            else             { e0 = 0.f;  e1 = 0.f; }
            __nv_bfloat16 h0 = __float2bfloat16(e0);
            __nv_bfloat16 h1 = __float2bfloat16(e1);
            *(__nv_bfloat16*)(sm + O_ACTH + lane * 136 + row * 2)        = h0;
            *(__nv_bfloat16*)(sm + O_ACTH + (lane + 32) * 136 + row * 2) = h1;
            *(__nv_bfloat16*)(sm + O_ACTL + lane * 136 + row * 2) =
                __float2bfloat16(e0 - __bfloat162float(h0));
            *(__nv_bfloat16*)(sm + O_ACTL + (lane + 32) * 136 + row * 2) =
                __float2bfloat16(e1 - __bfloat162float(h1));
        }
        __syncthreads();

        // ---- vlad GEMM: C[d=256][k=64] += xT @ actT', K=n=64 ----
#pragma unroll
        for (int ks = 0; ks < 4; ks++) {
            int kl = ks * 16;
            uint32_t bhf[4][2], blf[4][2];
#pragma unroll
            for (int nt = 0; nt < 4; nt++) {
                uint32_t bb = (uint32_t)((wn * 32 + nt * 8 + lr) * 136 + (kl + lc) * 2);
                bhf[nt][0] = lds32(ah_s + bb);  bhf[nt][1] = lds32(ah_s + bb + 16);
                blf[nt][0] = lds32(al_s + bb);  blf[nt][1] = lds32(al_s + bb + 16);
            }
#pragma unroll
            for (int mt = 0; mt < 4; mt++) {
                uint32_t abase = (uint32_t)((wm * 64 + mt * 16 + lr) * 136 + (kl + lc) * 2);
                uint32_t a[4]  = { lds32(xth_s + abase), lds32(xth_s + abase + 1088),
                                   lds32(xth_s + abase + 16), lds32(xth_s + abase + 1104) };
                uint32_t al_[4] = { lds32(xtl_s + abase), lds32(xtl_s + abase + 1088),
                                    lds32(xtl_s + abase + 16), lds32(xtl_s + abase + 1104) };
#pragma unroll
                for (int nt = 0; nt < 4; nt++) {
                    mma16816(accv[mt][nt], a, bhf[nt]);
                    mma16816(accv[mt][nt], a, blf[nt]);
                    mma16816(accv[mt][nt], al_, bhf[nt]);
                }
            }
        }
    }

    // ---- asum reduce + cw2 load (x regions now dead) ----
    red[wid * 64 + lane]      = s0;
    red[wid * 64 + lane + 32] = s1;
    __syncthreads();
    if (tid < 32) {
        float t0 = 0.f, t1 = 0.f;
#pragma unroll
        for (int w = 0; w < 8; w++) { t0 += red[w * 64 + lane]; t1 += red[w * 64 + lane + 32]; }
        asums[lane] = t0; asums[lane + 32] = t1;
    }
    float* cw2s = (float*)(sm + O_XH);        // 64 KB, overwrites xh/xl
    for (int i = tid; i < 4096; i += 256)
        ((float4*)cw2s)[i] = ((const float4*)cw2)[i];
    __syncthreads();

    // ---- epilogue: v = C - asum[k]*cw2[d][k]; intra + total norms ----
#pragma unroll
    for (int mt = 0; mt < 4; mt++)
#pragma unroll
        for (int nt = 0; nt < 4; nt++)
#pragma unroll
            for (int q = 0; q < 4; q++) {
                int d = wm * 64 + mt * 16 + lr + ((q >> 1) * 8);
                int k = wn * 32 + nt * 8 + lc + (q & 1);
                accv[mt][nt][q] -= asums[k] * cw2s[d * 64 + k];
            }
#pragma unroll
    for (int nt = 0; nt < 4; nt++) {
        float sq0 = 0.f, sq1 = 0.f;
#pragma unroll
        for (int mt = 0; mt < 4; mt++) {
            sq0 += accv[mt][nt][0] * accv[mt][nt][0] + accv[mt][nt][2] * accv[mt][nt][2];
            sq1 += accv[mt][nt][1] * accv[mt][nt][1] + accv[mt][nt][3] * accv[mt][nt][3];
        }
        sq0 += __shfl_xor_sync(0xFFFFFFFFu, sq0, 4);
        sq0 += __shfl_xor_sync(0xFFFFFFFFu, sq0, 8);
        sq0 += __shfl_xor_sync(0xFFFFFFFFu, sq0, 16);
        sq1 += __shfl_xor_sync(0xFFFFFFFFu, sq1, 4);
        sq1 += __shfl_xor_sync(0xFFFFFFFFu, sq1, 8);
        sq1 += __shfl_xor_sync(0xFFFFFFFFu, sq1, 16);
        if (lr == 0) {
            int k0 = wn * 32 + nt * 8 + lc;
            redk[k0 * 4 + wm]       = sq0;
            redk[(k0 + 1) * 4 + wm] = sq1;
        }
    }
    __syncthreads();
    if (tid < 32) {
        float q0 = redk[lane * 4] + redk[lane * 4 + 1] + redk[lane * 4 + 2] + redk[lane * 4 + 3];
        int l2 = lane + 32;
        float q1 = redk[l2 * 4] + redk[l2 * 4 + 1] + redk[l2 * 4 + 2] + redk[l2 * 4 + 3];
        float i0 = 1.f / (sqrtf(q0) + 1e-12f);
        float i1 = 1.f / (sqrtf(q1) + 1e-12f);
        invk[lane] = i0; invk[l2] = i1;
        float tt = q0 * i0 * i0 + q1 * i1 * i1;
#pragma unroll
        for (int off = 16; off; off >>= 1) tt += __shfl_xor_sync(0xFFFFFFFFu, tt, off);
        if (lane == 0) invts[0] = 1.f / (sqrtf(tt) + 1e-12f);
    }
    __syncthreads();
    float invt = invts[0];

    // ---- split-bf16 into staging (pitch 66, in xT region), coalesced out ----
#pragma unroll
    for (int mt = 0; mt < 4; mt++)
#pragma unroll
        for (int nt = 0; nt < 4; nt++)
#pragma unroll
            for (int q = 0; q < 4; q++) {
                int d = wm * 64 + mt * 16 + lr + ((q >> 1) * 8);
                int k = wn * 32 + nt * 8 + lc + (q & 1);
                float val = accv[mt][nt][q] * invk[k] * invt;
                __nv_bfloat16 h = __float2bfloat16(val);
                *(__nv_bfloat16*)(sm + O_XTH + (d * 66 + k) * 2) = h;
                *(__nv_bfloat16*)(sm + O_XTL + (d * 66 + k) * 2) =
                    __float2bfloat16(val - __bfloat162float(h));
            }
    __syncthreads();
    for (int i = tid; i < 8192; i += 256) {
        int d = i >> 5, kp = i & 31;
        uint32_t vh = lds32(xth_s + (uint32_t)(d * 66 + kp * 2) * 2);
        uint32_t vl = lds32(xtl_s + (uint32_t)(d * 66 + kp * 2) * 2);
        size_t go = (size_t)b * VLAD_DIM + d * 64 + kp * 2;
        *(uint32_t*)((char*)g_Ah + go * 2) = vh;
        *(uint32_t*)((char*)g_Al + go * 2) = vl;
    }
}

// ---------------------------------------------------------------------------
// Transpose + split: src[k][n] fp32 -> dh/dl[n][k] bf16 (pads zero-filled).
// ---------------------------------------------------------------------------
__global__ void __launch_bounds__(256) k_cvt_trans(
    const float* __restrict__ src, int ldsrc, int Kreal, int Nreal,
    __nv_bfloat16* __restrict__ dh, __nv_bfloat16* __restrict__ dl, int ldd)
{
    __shared__ float smt[32][33];
    int k0 = blockIdx.x * 32;
    int n0 = blockIdx.y * 32;
    int tx = threadIdx.x & 31;
    int ty = threadIdx.x >> 5;
#pragma unroll
    for (int i = 0; i < 4; i++) {
        int kk = ty + i * 8;
        int n = n0 + tx;
        float v = (k0 + kk < Kreal && n < Nreal) ? src[(size_t)(k0 + kk) * ldsrc + n] : 0.f;
        smt[kk][tx] = v;
    }
    __syncthreads();
#pragma unroll
    for (int i = 0; i < 4; i++) {
        int nn = ty + i * 8;
        float v = smt[tx][nn];
        __nv_bfloat16 h = __float2bfloat16(v);
        __nv_bfloat16 l = __float2bfloat16(v - __bfloat162float(h));
        size_t o = (size_t)(n0 + nn) * ldd + k0 + tx;
        dh[o] = h;
        dl[o] = l;
    }
}

// ---------------------------------------------------------------------------
// Split-bf16 HMMA GEMM (unchanged, passing).
// ---------------------------------------------------------------------------
#define KBLK 64
#define SPITCH 72
#define SPB (SPITCH * 2)
#define TILE_B (128 * SPB)
#define STAGE_B (4 * TILE_B)
#define MMA_SMEM_TOTAL (2 * STAGE_B)

__global__ void __launch_bounds__(256, 1) k_mma(
    const __nv_bfloat16* __restrict__ Ah, const __nv_bfloat16* __restrict__ Al,
    const __nv_bfloat16* __restrict__ Bh, const __nv_bfloat16* __restrict__ Bl,
    int K, float* __restrict__ C, int M, int N,
    const float* __restrict__ bias, int act,
    __nv_bfloat16* __restrict__ Dh, __nv_bfloat16* __restrict__ Dl, int ldd)
{
    extern __shared__ __align__(16) char smem[];
    uint32_t sb = smem_u32(smem);
    int tid = threadIdx.x;
    int wid = tid >> 5, lane = tid & 31;
    int wm = wid & 3;
    int wn = wid >> 2;
    int m0 = blockIdx.y * 128;
    int n0 = blockIdx.x * 128;

    const __nv_bfloat16* srcs[4] = {
        Ah + (size_t)m0 * K, Al + (size_t)m0 * K,
        Bh + (size_t)n0 * K, Bl + (size_t)n0 * K };

    int lrow = tid >> 3;
    int lchk = tid & 7;

    float acc[2][8][4];
#pragma unroll
    for (int i = 0; i < 2; i++)
#pragma unroll
        for (int j = 0; j < 8; j++)
#pragma unroll
            for (int q = 0; q < 4; q++) acc[i][j][q] = 0.f;

    auto load_stage = [&](int s, int kb) {
        uint32_t sd = sb + s * STAGE_B;
        size_t kOff = (size_t)kb * KBLK;
#pragma unroll
        for (int v = 0; v < 4; v++) {
            const __nv_bfloat16* g = srcs[v] + kOff;
#pragma unroll
            for (int p = 0; p < 4; p++) {
                int rr = lrow + p * 32;
                uint32_t d = sd + v * TILE_B + rr * SPB + lchk * 16;
                const void* sptr = (const char*)(g + (size_t)rr * K) + lchk * 16;
                CP_ASYNC16(d, sptr);
            }
        }
        CP_COMMIT();
    };

    load_stage(0, 0);

    int lr = lane >> 2;
    int lc = (lane & 3) * 2;
    int nkb = K / KBLK;

    for (int kb = 0; kb < nkb; kb++) {
        int s = kb & 1;
        CP_WAIT0();
        __syncthreads();
        if (kb + 1 < nkb) load_stage(s ^ 1, kb + 1);

        uint32_t sAh = sb + s * STAGE_B;
        uint32_t sAl = sAh + TILE_B;
        uint32_t sBh = sAh + 2 * TILE_B;
        uint32_t sBl = sAh + 3 * TILE_B;

#pragma unroll
        for (int ks = 0; ks < 4; ks++) {
            int kl = ks * 16;
            uint32_t ah[2][4], al_[2][4];
#pragma unroll
            for (int mt = 0; mt < 2; mt++) {
                uint32_t base = (uint32_t)((wm * 32 + mt * 16 + lr) * SPB + (kl + lc) * 2);
                ah[mt][0]  = lds32(sAh + base);
                ah[mt][1]  = lds32(sAh + base + 8 * SPB);
                ah[mt][2]  = lds32(sAh + base + 16);
                ah[mt][3]  = lds32(sAh + base + 8 * SPB + 16);
                al_[mt][0] = lds32(sAl + base);
                al_[mt][1] = lds32(sAl + base + 8 * SPB);
                al_[mt][2] = lds32(sAl + base + 16);
                al_[mt][3] = lds32(sAl + base + 8 * SPB + 16);
            }
            uint32_t bh[8][2], bl_[8][2];
#pragma unroll
            for (int nt = 0; nt < 8; nt++) {
                uint32_t base = (uint32_t)((wn * 64 + nt * 8 + lr) * SPB + (kl + lc) * 2);
                bh[nt][0]  = lds32(sBh + base);
                bh[nt][1]  = lds32(sBh + base + 16);
                bl_[nt][0] = lds32(sBl + base);
                bl_[nt][1] = lds32(sBl + base + 16);
            }
#pragma unroll
            for (int mt = 0; mt < 2; mt++)
#pragma unroll
                for (int nt = 0; nt < 8; nt++) {
                    mma16816(acc[mt][nt], ah[mt], bh[nt]);
                    mma16816(acc[mt][nt], ah[mt], bl_[nt]);
                    mma16816(acc[mt][nt], al_[mt], bh[nt]);
                }
        }
    }

    auto emit = [&](int r, int c, float v) {
        bool in = (r < M && c < N);
        float val = 0.f;
        if (in) {
            val = v + (bias ? bias[c] : 0.f);
            if (act == 1) val = fmaxf(val, 0.f);
            if (C) C[(size_t)r * N + c] = val;
        }
        if (Dh) {
            __nv_bfloat16 h = __float2bfloat16(val);
            Dh[(size_t)r * ldd + c] = h;
            Dl[(size_t)r * ldd + c] = __float2bfloat16(val - __bfloat162float(h));
        }
    };
#pragma unroll
    for (int mt = 0; mt < 2; mt++) {
#pragma unroll
        for (int nt = 0; nt < 8; nt++) {
            int r = m0 + wm * 32 + mt * 16 + lr;
            int c = n0 + wn * 64 + nt * 8 + lc;
            emit(r,     c,     acc[mt][nt][0]);
            emit(r,     c + 1, acc[mt][nt][1]);
            emit(r + 8, c,     acc[mt][nt][2]);
            emit(r + 8, c + 1, acc[mt][nt][3]);
        }
    }
}

// ---------------------------------------------------------------------------
// Small SGEMM (64x64x16) for G3.
// ---------------------------------------------------------------------------
__global__ void __launch_bounds__(256) k_sgemm(
    const float* __restrict__ A, const float* __restrict__ B,
    const float* __restrict__ bias, float* __restrict__ C,
    int M, int N, int K, int act)
{
    __shared__ __align__(16) float As[16][64];
    __shared__ __align__(16) float Bs[16][64];

    int tid = threadIdx.x;
    int tx = tid & 15, ty = tid >> 4;
    int row0 = blockIdx.y * 64, col0 = blockIdx.x * 64;

    float c[4][4];
#pragma unroll
    for (int i = 0; i < 4; i++)
#pragma unroll
        for (int j = 0; j < 4; j++) c[i][j] = 0.f;

    int am = tid >> 2;
    int ak = (tid & 3) * 4;
    int bk = tid >> 4;
    int bn = (tid & 15) * 4;

    for (int k0 = 0; k0 < K; k0 += 16) {
        int arow = row0 + am;
        if (arow < M && k0 + ak + 3 < K) {
            float4 v = *reinterpret_cast<const float4*>(&A[(size_t)arow * K + k0 + ak]);
            As[ak + 0][am] = v.x; As[ak + 1][am] = v.y;
            As[ak + 2][am] = v.z; As[ak + 3][am] = v.w;
        } else {
#pragma unroll
            for (int i = 0; i < 4; i++) {
                int kk = k0 + ak + i;
                As[ak + i][am] = (arow < M && kk < K) ? A[(size_t)arow * K + kk] : 0.f;
            }
        }
        int brow = k0 + bk;
        if (brow < K && col0 + bn + 3 < N) {
            float4 v = *reinterpret_cast<const float4*>(&B[(size_t)brow * N + col0 + bn]);
            *reinterpret_cast<float4*>(&Bs[bk][bn]) = v;
        } else {
#pragma unroll
            for (int i = 0; i < 4; i++) {
                int nn = col0 + bn + i;
                Bs[bk][bn + i] = (brow < K && nn < N) ? B[(size_t)brow * N + nn] : 0.f;
            }
        }
        __syncthreads();
#pragma unroll
        for (int kk = 0; kk < 16; kk++) {
            float4 av = *reinterpret_cast<const float4*>(&As[kk][ty * 4]);
            float4 bv = *reinterpret_cast<const float4*>(&Bs[kk][tx * 4]);
            float a[4] = {av.x, av.y, av.z, av.w};
            float bb[4] = {bv.x, bv.y, bv.z, bv.w};
#pragma unroll
            for (int i = 0; i < 4; i++)
#pragma unroll
                for (int j = 0; j < 4; j++) c[i][j] = fmaf(a[i], bb[j], c[i][j]);
        }
        __syncthreads();
    }

#pragma unroll
    for (int i = 0; i < 4; i++) {
        int r = row0 + ty * 4 + i;
        if (r >= M) continue;
#pragma unroll
        for (int j = 0; j < 4; j++) {
            int cc = col0 + tx * 4 + j;
            if (cc >= N) continue;
            float v = c[i][j];
            if (bias) v += bias[cc];
            if (act == 1) v = fmaxf(v, 0.f);
            C[(size_t)r * N + cc] = v;
        }
    }
}

// ---------------------------------------------------------------------------
// GAT kernels
// ---------------------------------------------------------------------------
__global__ void __launch_bounds__(128) k_gat_h(
    const float* __restrict__ W, const float* __restrict__ a_s,
    const float* __restrict__ a_d)
{
    int b = blockIdx.x, t = threadIdx.x;
    __shared__ float xsm[NODE_D];
    __shared__ float rs[8];
    xsm[t] = g_x[b * NODE_D + t];
    __syncthreads();
    float acc = 0.f;
#pragma unroll 8
    for (int d = 0; d < NODE_D; d++) acc = fmaf(xsm[d], __ldg(&W[d * NODE_D + t]), acc);
    g_h[b * NODE_D + t] = acc;
    float ps = acc * __ldg(&a_s[t]);
    float pd = acc * __ldg(&a_d[t]);
#pragma unroll
    for (int off = 16; off; off >>= 1) {
        ps += __shfl_xor_sync(0xFFFFFFFFu, ps, off);
        pd += __shfl_xor_sync(0xFFFFFFFFu, pd, off);
    }
    if ((t & 31) == 0) { rs[t >> 5] = ps; rs[4 + (t >> 5)] = pd; }
    __syncthreads();
    if (t == 0) g_es[b] = rs[0] + rs[1] + rs[2] + rs[3];
    if (t == 1) g_ed[b] = rs[4] + rs[5] + rs[6] + rs[7];
}

__global__ void k_init()
{
    int i = blockIdx.x * blockDim.x + threadIdx.x;
    if (i < N_NODES) g_den[i] = 0.f;
    if (i < N_NODES * NODE_D) g_aggr[i] = 0.f;
}

__global__ void k_edge12(const int* __restrict__ ei)
{
    int e = blockIdx.x * blockDim.x + threadIdx.x;
    if (e >= E_EXT) return;
    int s, d;
    if (e < N_EDGES) { s = ei[e]; d = ei[N_EDGES + e]; }
    else { s = e - N_EDGES; d = s; }
    float v = g_es[s] + g_ed[d];
    v = (v > 0.f) ? v : 0.2f * v;
    float ex = __expf(v);
    g_ex[e] = ex;
    atomicAdd(&g_den[d], ex);
}

__global__ void k_edge3(const int* __restrict__ ei)
{
    int gt = blockIdx.x * blockDim.x + threadIdx.x;
    int w = gt >> 5, lane = gt & 31;
    if (w >= E_EXT) return;
    int s, d;
    if (w < N_EDGES) { s = ei[w]; d = ei[N_EDGES + w]; }
    else { s = w - N_EDGES; d = s; }
    float alpha = g_ex[w] / g_den[d];
#pragma unroll
    for (int i = 0; i < 4; i++) {
        int c = lane + 32 * i;
        atomicAdd(&g_aggr[d * NODE_D + c], g_h[s * NODE_D + c] * alpha);
    }
}

__global__ void k_gat_fin(const float* __restrict__ b)
{
    int i = blockIdx.x * blockDim.x + threadIdx.x;
    if (i >= N_NODES * NODE_D) return;
    float v = g_aggr[i] + __ldg(&b[i & (NODE_D - 1)]);
    g_x[i] = (v > 0.f) ? v : (__expf(v) - 1.f);
}

// ---------------------------------------------------------------------------
// Edge-attr MLP: 1 -> 8 -> 16 -> 32
// ---------------------------------------------------------------------------
__global__ void __launch_bounds__(256) k_ef(
    const float* __restrict__ ea,
    const float* __restrict__ w1, const float* __restrict__ b1,
    const float* __restrict__ w2, const float* __restrict__ b2,
    const float* __restrict__ w3, const float* __restrict__ b3)
{
    __shared__ float w1s[8], b1s[8], w2s[128], b2s[16], w3s[512], b3s[32];
    int t = threadIdx.x;
    if (t < 8)   { w1s[t] = w1[t]; b1s[t] = b1[t]; }
    if (t < 128) w2s[t] = w2[t];
    if (t < 16)  b2s[t] = b2[t];
    if (t < 32)  b3s[t] = b3[t];
    for (int i = t; i < 512; i += blockDim.x) w3s[i] = w3[i];
    __syncthreads();
    int e = blockIdx.x * blockDim.x + t;
    if (e >= N_EDGES) return;
    float a = ea[e];
    float t8[8];
#pragma unroll
    for (int j = 0; j < 8; j++) t8[j] = fmaxf(fmaf(a, w1s[j], b1s[j]), 0.f);
    float t16[16];
#pragma unroll
    for (int c = 0; c < 16; c++) {
        float acc = b2s[c];
#pragma unroll
        for (int j = 0; j < 8; j++) acc = fmaf(t8[j], w2s[j * 16 + c], acc);
        t16[c] = fmaxf(acc, 0.f);
    }
#pragma unroll
    for (int c = 0; c < 32; c++) {
        float acc = b3s[c];
#pragma unroll
        for (int j = 0; j < 16; j++) acc = fmaf(t16[j], w3s[j * 32 + c], acc);
        g_ef2[e * EDGE_D + c] = acc;
    }
}

// ---------------------------------------------------------------------------
// Final fused edge classifier.
// ---------------------------------------------------------------------------
__global__ void __launch_bounds__(128) k_final(
    const int* __restrict__ ei,
    const float* __restrict__ dp_w, const float* __restrict__ dp_b,
    const float* __restrict__ ec_w1, const float* __restrict__ ec_b1,
    const float* __restrict__ ec_w2, const float* __restrict__ ec_b2,
    float* __restrict__ out)
{
    __shared__ float dpw_s[288 * 32];
    __shared__ float ecw1_s[32 * 16];
    __shared__ float dpb_s[32];
    __shared__ float ecb1_s[16];
    __shared__ float ecw2_s[16];
    __shared__ float vec_s[4][292];
    __shared__ float o32_s[4][32];

    int tid = threadIdx.x;
    for (int i = tid; i < 288 * 32; i += 128) dpw_s[i] = dp_w[i];
    for (int i = tid; i < 512; i += 128) ecw1_s[i] = ec_w1[i];
    if (tid < 32) dpb_s[tid] = dp_b[tid];
    if (tid < 16) { ecb1_s[tid] = ec_b1[tid]; ecw2_s[tid] = ec_w2[tid]; }
    __syncthreads();

    float b2 = __ldg(ec_b2);
    int warp = tid >> 5, lane = tid & 31;
    int gw = blockIdx.x * 4 + warp;
    int nw = gridDim.x * 4;

    for (int e = gw; e < N_EDGES; e += nw) {
        int s = ei[e], d = ei[N_EDGES + e];
        const float* xsp = g_x + s * NODE_D;
        const float* xdp = g_x + d * NODE_D;
#pragma unroll
        for (int i = 0; i < 4; i++) {
            vec_s[warp][lane + 32 * i]       = xsp[lane + 32 * i];
            vec_s[warp][128 + lane + 32 * i] = xdp[lane + 32 * i];
        }
        vec_s[warp][256 + lane] = g_ef2[e * EDGE_D + lane];
        __syncwarp();

        float acc = dpb_s[lane];
#pragma unroll 4
        for (int i = 0; i < 288; i++) acc = fmaf(vec_s[warp][i], dpw_s[i * 32 + lane], acc);
        o32_s[warp][lane] = acc;
        __syncwarp();

        float hh = 0.f;
        if (lane < 16) {
            hh = ecb1_s[lane];
#pragma unroll 4
            for (int j = 0; j < 32; j++) hh = fmaf(o32_s[warp][j], ecw1_s[j * 16 + lane], hh);
            hh = fmaxf(hh, 0.f) * ecw2_s[lane];
        }
#pragma unroll
        for (int off = 8; off; off >>= 1) hh += __shfl_xor_sync(0xFFFFFFFFu, hh, off);
        if (lane == 0) out[e] = 1.f / (1.f + __expf(-(hh + b2)));
        __syncwarp();
    }
}

// ---------------------------------------------------------------------------
extern "C" void kernel_launch(void* const* d_in, const int* in_sizes, int n_in,
                              void* d_out, int out_size)
{
    (void)in_sizes; (void)n_in; (void)out_size;
    const float* node_feats = (const float*)d_in[0];
    const float* edge_attr  = (const float*)d_in[1];
    const float* nv_cw      = (const float*)d_in[2];
    const float* nv_cb      = (const float*)d_in[3];
    const float* nv_cw2     = (const float*)d_in[4];
    const float* nv_hw      = (const float*)d_in[5];
    const float* ne_w1      = (const float*)d_in[6];
    const float* ne_b1      = (const float*)d_in[7];
    const float* ne_w2      = (const float*)d_in[8];
    const float* ne_b2      = (const float*)d_in[9];
    const float* ee_w1      = (const float*)d_in[10];
    const float* ee_b1      = (const float*)d_in[11];
    const float* ee_w2      = (const float*)d_in[12];
    const float* ee_b2      = (const float*)d_in[13];
    const float* ee_w3      = (const float*)d_in[14];
    const float* ee_b3      = (const float*)d_in[15];
    const float* gat_w      = (const float*)d_in[16];
    const float* gat_as     = (const float*)d_in[17];
    const float* gat_ad     = (const float*)d_in[18];
    const float* gat_b      = (const float*)d_in[19];
    const float* dp_w       = (const float*)d_in[20];
    const float* dp_b       = (const float*)d_in[21];
    const float* ec_w1      = (const float*)d_in[22];
    const float* ec_b1      = (const float*)d_in[23];
    const float* ec_w2      = (const float*)d_in[24];
    const float* ec_b2      = (const float*)d_in[25];
    const int*   edge_index = (const int*)d_in[26];
    float* out = (float*)d_out;

    float *p_h1, *p_x;
    __nv_bfloat16 *p_Ah, *p_Al, *p_Bh, *p_Bl, *p_Ah2, *p_Al2, *p_Bh2, *p_Bl2;
    cudaGetSymbolAddress((void**)&p_h1, g_h1);
    cudaGetSymbolAddress((void**)&p_x, g_x);
    cudaGetSymbolAddress((void**)&p_Ah, g_Ah);
    cudaGetSymbolAddress((void**)&p_Al, g_Al);
    cudaGetSymbolAddress((void**)&p_Bh, g_Bh);
    cudaGetSymbolAddress((void**)&p_Bl, g_Bl);
    cudaGetSymbolAddress((void**)&p_Ah2, g_Ah2);
    cudaGetSymbolAddress((void**)&p_Al2, g_Al2);
    cudaGetSymbolAddress((void**)&p_Bh2, g_Bh2);
    cudaGetSymbolAddress((void**)&p_Bl2, g_Bl2);

    cudaFuncSetAttribute(k_mma, cudaFuncAttributeMaxDynamicSharedMemorySize, MMA_SMEM_TOTAL);
    cudaFuncSetAttribute(k_nv, cudaFuncAttributeMaxDynamicSharedMemorySize, NV_SMEM);

    // 0) prep: cw^T split + B operand conversions
    k_prep_cw<<<64, 256>>>(nv_cw);
    {
        dim3 g(VLAD_DIM / 32, N_PAD / 32);
        k_cvt_trans<<<g, 256>>>(nv_hw, H0D, VLAD_DIM, H0D, p_Bh, p_Bl, VLAD_DIM);
    }
    {
        dim3 g(K2PAD / 32, N2PAD / 32);
        k_cvt_trans<<<g, 256>>>(ne_w1, H1D, H0D, H1D, p_Bh2, p_Bl2, K2PAD);
    }

    // 1) FUSED NetVLAD -> g_Ah/g_Al
    k_nv<<<N_NODES, 256, NV_SMEM>>>(node_feats, nv_cb, nv_cw2);

    // 2) G1 HMMA: h0 = vlad @ hw -> split-bf16 A operand of G2
    {
        dim3 g(N_PAD / 128, M_PAD / 128);
        k_mma<<<g, 256, MMA_SMEM_TOTAL>>>(p_Ah, p_Al, p_Bh, p_Bl, VLAD_DIM,
                                          nullptr, N_NODES, H0D, nullptr, 0,
                                          p_Ah2, p_Al2, K2PAD);
    }
    // 3) G2 HMMA: h1 = relu(h0 @ ne_w1 + b1)
    {
        dim3 g(N2PAD / 128, M_PAD / 128);
        k_mma<<<g, 256, MMA_SMEM_TOTAL>>>(p_Ah2, p_Al2, p_Bh2, p_Bl2, K2PAD,
                                          p_h1, N_NODES, H1D, ne_b1, 1,
                                          nullptr, nullptr, 0);
    }
    // 4) G3: x = h1 @ ne_w2 + b2
    {
        dim3 g((NODE_D + 63) / 64, (N_NODES + 63) / 64);
        k_sgemm<<<g, 256>>>(p_h1, ne_w2, ne_b2, p_x, N_NODES, NODE_D, H1D, 0);
    }

    // 5) edge-attr MLP
    k_ef<<<(N_EDGES + 255) / 256, 256>>>(edge_attr, ee_w1, ee_b1, ee_w2, ee_b2, ee_w3, ee_b3);

    // 6) 3 GAT layers
    for (int l = 0; l < DEPTH; l++) {
        k_gat_h<<<N_NODES, 128>>>(gat_w + l * NODE_D * NODE_D,
                                  gat_as + l * NODE_D, gat_ad + l * NODE_D);
        k_init<<<(N_NODES * NODE_D + 255) / 256, 256>>>();
        k_edge12<<<(E_EXT + 255) / 256, 256>>>(edge_index);
        k_edge3<<<((E_EXT * 32) + 255) / 256, 256>>>(edge_index);
        k_gat_fin<<<(N_NODES * NODE_D + 255) / 256, 256>>>(gat_b + l * NODE_D);
    }

    // 7) fused edge classifier -> out
    k_final<<<512, 128>>>(edge_index, dp_w, dp_b, ec_w1, ec_b1, ec_w2, ec_b2, out);
}

// round 9
// speedup vs baseline: 4.3280x; 1.2309x over previous
#include <cuda_runtime.h>
#include <cuda_bf16.h>
#include <math.h>
#include <stdint.h>

#define N_NODES 2000
#define NUM_KP 500
#define DESC 256
#define NVK 64
#define VLAD_DIM (DESC*NVK)        // 16384
#define H0D (NUM_KP*2)             // 1000
#define H1D NUM_KP                 // 500
#define NODE_D 128
#define EDGE_D 32
#define N_EDGES 64000
#define E_EXT (N_EDGES + N_NODES)  // 66000
#define DEPTH 3

#define M_PAD 2048
#define N_PAD 1024
#define K2PAD 1024
#define N2PAD 512

typedef unsigned long long u64;

// ---------------- scratch (device globals; no runtime allocation) ----------
__device__ float    g_h1[N_NODES * H1D];
__device__ float    g_x[N_NODES * NODE_D];
__device__ float    g_h[N_NODES * NODE_D];
__device__ float    g_es[N_NODES];
__device__ float    g_ed[N_NODES];
__device__ float    g_ex[E_EXT];
__device__ float    g_den[N_NODES];
__device__ float    g_aggr[N_NODES * NODE_D];
__device__ float    g_ef2[N_EDGES * EDGE_D];
// split-bf16 operands (pad regions stay zero: static zero-init, never written)
__device__ __nv_bfloat16 g_Ah[(size_t)M_PAD * VLAD_DIM];
__device__ __nv_bfloat16 g_Al[(size_t)M_PAD * VLAD_DIM];
__device__ __nv_bfloat16 g_Bh[(size_t)N_PAD * VLAD_DIM];
__device__ __nv_bfloat16 g_Bl[(size_t)N_PAD * VLAD_DIM];
__device__ __nv_bfloat16 g_Ah2[(size_t)M_PAD * K2PAD];
__device__ __nv_bfloat16 g_Al2[(size_t)M_PAD * K2PAD];
__device__ __nv_bfloat16 g_Bh2[(size_t)N2PAD * K2PAD];
__device__ __nv_bfloat16 g_Bl2[(size_t)N2PAD * K2PAD];
__device__ __nv_bfloat16 g_cwTh[NVK * DESC];
__device__ __nv_bfloat16 g_cwTl[NVK * DESC];

// ---------------- helpers ---------------------------------------------------
__device__ __forceinline__ uint32_t smem_u32(const void* p) {
    uint32_t a;
    asm("{ .reg .u64 t; cvta.to.shared.u64 t, %1; cvt.u32.u64 %0, t; }" : "=r"(a) : "l"(p));
    return a;
}
__device__ __forceinline__ uint32_t lds32(uint32_t addr) {
    uint32_t v;
    asm volatile("ld.shared.b32 %0, [%1];" : "=r"(v) : "r"(addr));
    return v;
}
__device__ __forceinline__ void ldm_x4(uint32_t* r, uint32_t addr) {
    asm volatile("ldmatrix.sync.aligned.m8n8.x4.shared.b16 {%0,%1,%2,%3}, [%4];"
        : "=r"(r[0]), "=r"(r[1]), "=r"(r[2]), "=r"(r[3]) : "r"(addr));
}
__device__ __forceinline__ void ldm_x4_t(uint32_t* r, uint32_t addr) {
    asm volatile("ldmatrix.sync.aligned.m8n8.x4.trans.shared.b16 {%0,%1,%2,%3}, [%4];"
        : "=r"(r[0]), "=r"(r[1]), "=r"(r[2]), "=r"(r[3]) : "r"(addr));
}
__device__ __forceinline__ void mma16816(float* c, const uint32_t* a, const uint32_t* b) {
    asm volatile(
        "mma.sync.aligned.m16n8k16.row.col.f32.bf16.bf16.f32 "
        "{%0,%1,%2,%3}, {%4,%5,%6,%7}, {%8,%9}, {%0,%1,%2,%3};"
        : "+f"(c[0]), "+f"(c[1]), "+f"(c[2]), "+f"(c[3])
        : "r"(a[0]), "r"(a[1]), "r"(a[2]), "r"(a[3]), "r"(b[0]), "r"(b[1]));
}
#define CP_ASYNC16(dst, src) \
    asm volatile("cp.async.cg.shared.global [%0], [%1], 16;" :: "r"(dst), "l"(src) : "memory")
#define CP_COMMIT()  asm volatile("cp.async.commit_group;" ::: "memory")
#define CP_WAIT0()   asm volatile("cp.async.wait_group 0;" ::: "memory")

__device__ __forceinline__ float sanit(float v) {
    if (!isfinite(v)) v = (v != v) ? 0.f : (v > 0.f ? 3.402823466e38f : -3.402823466e38f);
    return v;
}

// ---------------------------------------------------------------------------
// Prep: cw [256][64] fp32 -> cw^T split-bf16 [64][256]
// ---------------------------------------------------------------------------
__global__ void k_prep_cw(const float* __restrict__ cw)
{
    int i = blockIdx.x * 256 + threadIdx.x;    // 0..16383
    int k = i >> 8, d = i & 255;
    float v = cw[d * 64 + k];
    __nv_bfloat16 h = __float2bfloat16(v);
    g_cwTh[k * 256 + d] = h;
    g_cwTl[k * 256 + d] = __float2bfloat16(v - __bfloat162float(h));
}

// ---------------------------------------------------------------------------
// FUSED NetVLAD with ldmatrix fragment loads. One CTA per node.
// x kept ONLY row-major; vlad-A fragments via ldmatrix.trans (free transpose).
// ---------------------------------------------------------------------------
#define O_CWH 0          // cwT hi [64 k][264 d] bf16 (pitch 528B), 33792B
#define O_CWL 33792
#define O_XH  67584      // x hi [64 n][264 d], 33792B
#define O_XL  101376
#define O_LOG 135168     // logits [64][68] f32 (17408B); reused as actT after
#define O_ACTH 135168    // actT hi [64 k][72 n] bf16 pitch 144B (9216B)
#define O_ACTL 144384
#define O_RED 153600     // [8][64] f32 (2048B)
#define O_ASUM 155648    // [64] f32
#define O_REDK 155904    // [64][4] f32
#define O_INVK 156928    // [64] f32
#define O_INVT 157184
#define NV_SMEM 157200

__global__ void __launch_bounds__(256, 1) k_nv(
    const float* __restrict__ feats, const float* __restrict__ cb,
    const float* __restrict__ cw2)
{
    extern __shared__ __align__(16) char sm[];
    int b = blockIdx.x;
    int tid = threadIdx.x, lane = tid & 31, wid = tid >> 5;
    int wm = wid & 3, wn = wid >> 2;
    int lr = lane >> 2, lc = (lane & 3) * 2;

    uint32_t cwh_s = smem_u32(sm + O_CWH), cwl_s = smem_u32(sm + O_CWL);
    uint32_t xh_s  = smem_u32(sm + O_XH),  xl_s  = smem_u32(sm + O_XL);
    uint32_t ah_s  = smem_u32(sm + O_ACTH), al_s = smem_u32(sm + O_ACTL);
    float* logit = (float*)(sm + O_LOG);
    float* red   = (float*)(sm + O_RED);
    float* asums = (float*)(sm + O_ASUM);
    float* redk  = (float*)(sm + O_REDK);
    float* invk  = (float*)(sm + O_INVK);
    float* invts = (float*)(sm + O_INVT);

    // ldmatrix lane-address components (canonical m16n16 x4 mapping)
    int l7  = lane & 7;
    int s8  = (lane & 8) ? 8 : 0;     // selects +8 in one dim
    int s16 = (lane & 16) ? 8 : 0;    // selects +8 in the other
    // logits A (non-trans, row-major x): rows = warp m-tile, cols = k-chunk
    int rowA_log = wm * 16 + l7 + s8;     // s8 -> +8 rows, s16 -> +8 cols
    // B (non-trans, row-major over K): pairs of nt tiles per x4
    int rowB_nt  = l7 + s16;              // +8 rows selects next nt
    // vlad A (TRANS from row-major x): x rows = n (K dim), cols = d
    int rowX_n   = l7 + s16;              // n within 16-chunk
    // cw2 etc.

    // stage cwT once (pre-split, pitch 528B)
    for (int i = tid; i < 2048; i += 256) {
        int k = i >> 5, c = i & 31;
        *(uint4*)(sm + O_CWH + k * 528 + c * 16) = ((const uint4*)g_cwTh)[i];
        *(uint4*)(sm + O_CWL + k * 528 + c * 16) = ((const uint4*)g_cwTl)[i];
    }

    float accv[4][4][4];
#pragma unroll
    for (int mt = 0; mt < 4; mt++)
#pragma unroll
        for (int nt = 0; nt < 4; nt++)
#pragma unroll
            for (int q = 0; q < 4; q++) accv[mt][nt][q] = 0.f;
    float s0 = 0.f, s1 = 0.f;
    float cb0 = cb[lane], cb1 = cb[lane + 32];

    for (int kb = 0; kb < 8; kb++) {
        __syncthreads();
        int n0 = kb * 64;
        // ---- stage x row-major only ----
        for (int i = tid; i < 4096; i += 256) {
            int row = i >> 6, c4 = i & 63;
            int gn = n0 + row;
            float4 v = make_float4(0.f, 0.f, 0.f, 0.f);
            if (gn < NUM_KP) v = ((const float4*)feats)[((size_t)b * NUM_KP + gn) * 64 + c4];
            float vv[4] = { sanit(v.x), sanit(v.y), sanit(v.z), sanit(v.w) };
            __nv_bfloat16 hh[4], ll[4];
#pragma unroll
            for (int j = 0; j < 4; j++) {
                hh[j] = __float2bfloat16(vv[j]);
                ll[j] = __float2bfloat16(vv[j] - __bfloat162float(hh[j]));
            }
            char* pxh = sm + O_XH + row * 528 + c4 * 8;
            char* pxl = sm + O_XL + row * 528 + c4 * 8;
            *(__nv_bfloat162*)pxh       = __nv_bfloat162(hh[0], hh[1]);
            *(__nv_bfloat162*)(pxh + 4) = __nv_bfloat162(hh[2], hh[3]);
            *(__nv_bfloat162*)pxl       = __nv_bfloat162(ll[0], ll[1]);
            *(__nv_bfloat162*)(pxl + 4) = __nv_bfloat162(ll[2], ll[3]);
        }
        __syncthreads();

        // ---- logits GEMM: C[n=64][k=64], K=d=256 (warp tile 16x32) ----
        float acc[4][4];
#pragma unroll
        for (int nt = 0; nt < 4; nt++)
#pragma unroll
            for (int q = 0; q < 4; q++) acc[nt][q] = 0.f;
#pragma unroll
        for (int ks = 0; ks < 16; ks++) {
            int kl = ks * 16;
            uint32_t aoff = (uint32_t)(rowA_log * 528 + (kl + s16) * 2);
            uint32_t a[4], al_[4];
            ldm_x4(a,  xh_s + aoff);
            ldm_x4(al_, xl_s + aoff);
#pragma unroll
            for (int ntp = 0; ntp < 2; ntp++) {
                uint32_t boff = (uint32_t)((wn * 32 + ntp * 16 + rowB_nt) * 528 + (kl + s8) * 2);
                uint32_t bh4[4], bl4[4];
                ldm_x4(bh4, cwh_s + boff);
                ldm_x4(bl4, cwl_s + boff);
                mma16816(acc[2 * ntp],     a,   bh4);
                mma16816(acc[2 * ntp],     a,   bl4);
                mma16816(acc[2 * ntp],     al_, bh4);
                mma16816(acc[2 * ntp + 1], a,   bh4 + 2);
                mma16816(acc[2 * ntp + 1], a,   bl4 + 2);
                mma16816(acc[2 * ntp + 1], al_, bh4 + 2);
            }
        }
#pragma unroll
        for (int nt = 0; nt < 4; nt++)
#pragma unroll
            for (int q = 0; q < 4; q++) {
                int row = wm * 16 + lr + ((q >> 1) * 8);
                int col = wn * 32 + nt * 8 + lc + (q & 1);
                logit[row * 68 + col] = acc[nt][q];
            }
        __syncthreads();

        // ---- softmax ----
        float l0r[8], l1r[8];
#pragma unroll
        for (int rr = 0; rr < 8; rr++) {
            int row = wid * 8 + rr;
            l0r[rr] = logit[row * 68 + lane] + cb0;
            l1r[rr] = logit[row * 68 + lane + 32] + cb1;
        }
        __syncthreads();    // all logits read before act overwrites the region
#pragma unroll
        for (int rr = 0; rr < 8; rr++) {
            int row = wid * 8 + rr;
            int gn = n0 + row;
            float m = fmaxf(l0r[rr], l1r[rr]);
#pragma unroll
            for (int off = 16; off; off >>= 1) m = fmaxf(m, __shfl_xor_sync(0xFFFFFFFFu, m, off));
            float e0 = __expf(l0r[rr] - m), e1 = __expf(l1r[rr] - m);
            float ss = e0 + e1;
#pragma unroll
            for (int off = 16; off; off >>= 1) ss += __shfl_xor_sync(0xFFFFFFFFu, ss, off);
            float inv = 1.f / ss;
            if (gn < NUM_KP) { e0 *= inv; e1 *= inv; s0 += e0; s1 += e1; }
            else             { e0 = 0.f;  e1 = 0.f; }
            __nv_bfloat16 h0 = __float2bfloat16(e0);
            __nv_bfloat16 h1 = __float2bfloat16(e1);
            *(__nv_bfloat16*)(sm + O_ACTH + lane * 144 + row * 2)        = h0;
            *(__nv_bfloat16*)(sm + O_ACTH + (lane + 32) * 144 + row * 2) = h1;
            *(__nv_bfloat16*)(sm + O_ACTL + lane * 144 + row * 2) =
                __float2bfloat16(e0 - __bfloat162float(h0));
            *(__nv_bfloat16*)(sm + O_ACTL + (lane + 32) * 144 + row * 2) =
                __float2bfloat16(e1 - __bfloat162float(h1));
        }
        __syncthreads();

        // ---- vlad GEMM: C[d=256][k=64] += xT @ actT', K=n=64 ----
#pragma unroll
        for (int ks = 0; ks < 4; ks++) {
            int kl = ks * 16;
            uint32_t bh4[2][4], bl4[2][4];
#pragma unroll
            for (int ntp = 0; ntp < 2; ntp++) {
                uint32_t boff = (uint32_t)((wn * 32 + ntp * 16 + rowB_nt) * 144 + (kl + s8) * 2);
                ldm_x4(bh4[ntp], ah_s + boff);
                ldm_x4(bl4[ntp], al_s + boff);
            }
#pragma unroll
            for (int mt = 0; mt < 4; mt++) {
                // A = xT tile (d rows, n cols) loaded TRANSPOSED from row-major x
                uint32_t aoff = (uint32_t)((kl + rowX_n) * 528 + (wm * 64 + mt * 16 + s8) * 2);
                uint32_t a[4], al2[4];
                ldm_x4_t(a,   xh_s + aoff);
                ldm_x4_t(al2, xl_s + aoff);
#pragma unroll
                for (int ntp = 0; ntp < 2; ntp++) {
                    mma16816(accv[mt][2 * ntp],     a,   bh4[ntp]);
                    mma16816(accv[mt][2 * ntp],     a,   bl4[ntp]);
                    mma16816(accv[mt][2 * ntp],     al2, bh4[ntp]);
                    mma16816(accv[mt][2 * ntp + 1], a,   bh4[ntp] + 2);
                    mma16816(accv[mt][2 * ntp + 1], a,   bl4[ntp] + 2);
                    mma16816(accv[mt][2 * ntp + 1], al2, bh4[ntp] + 2);
                }
            }
        }
    }

    // ---- asum reduce + cw2 load (x regions now dead) ----
    red[wid * 64 + lane]      = s0;
    red[wid * 64 + lane + 32] = s1;
    __syncthreads();
    if (tid < 32) {
        float t0 = 0.f, t1 = 0.f;
#pragma unroll
        for (int w = 0; w < 8; w++) { t0 += red[w * 64 + lane]; t1 += red[w * 64 + lane + 32]; }
        asums[lane] = t0; asums[lane + 32] = t1;
    }
    float* cw2s = (float*)(sm + O_XH);        // 64 KB, overwrites xh/xl
    for (int i = tid; i < 4096; i += 256)
        ((float4*)cw2s)[i] = ((const float4*)cw2)[i];
    __syncthreads();

    // ---- epilogue: v = C - asum[k]*cw2[d][k]; intra + total norms ----
#pragma unroll
    for (int mt = 0; mt < 4; mt++)
#pragma unroll
        for (int nt = 0; nt < 4; nt++)
#pragma unroll
            for (int q = 0; q < 4; q++) {
                int d = wm * 64 + mt * 16 + lr + ((q >> 1) * 8);
                int k = wn * 32 + nt * 8 + lc + (q & 1);
                accv[mt][nt][q] -= asums[k] * cw2s[d * 64 + k];
            }
#pragma unroll
    for (int nt = 0; nt < 4; nt++) {
        float sq0 = 0.f, sq1 = 0.f;
#pragma unroll
        for (int mt = 0; mt < 4; mt++) {
            sq0 += accv[mt][nt][0] * accv[mt][nt][0] + accv[mt][nt][2] * accv[mt][nt][2];
            sq1 += accv[mt][nt][1] * accv[mt][nt][1] + accv[mt][nt][3] * accv[mt][nt][3];
        }
        sq0 += __shfl_xor_sync(0xFFFFFFFFu, sq0, 4);
        sq0 += __shfl_xor_sync(0xFFFFFFFFu, sq0, 8);
        sq0 += __shfl_xor_sync(0xFFFFFFFFu, sq0, 16);
        sq1 += __shfl_xor_sync(0xFFFFFFFFu, sq1, 4);
        sq1 += __shfl_xor_sync(0xFFFFFFFFu, sq1, 8);
        sq1 += __shfl_xor_sync(0xFFFFFFFFu, sq1, 16);
        if (lr == 0) {
            int k0 = wn * 32 + nt * 8 + lc;
            redk[k0 * 4 + wm]       = sq0;
            redk[(k0 + 1) * 4 + wm] = sq1;
        }
    }
    __syncthreads();
    if (tid < 32) {
        float q0 = redk[lane * 4] + redk[lane * 4 + 1] + redk[lane * 4 + 2] + redk[lane * 4 + 3];
        int l2 = lane + 32;
        float q1 = redk[l2 * 4] + redk[l2 * 4 + 1] + redk[l2 * 4 + 2] + redk[l2 * 4 + 3];
        float i0 = 1.f / (sqrtf(q0) + 1e-12f);
        float i1 = 1.f / (sqrtf(q1) + 1e-12f);
        invk[lane] = i0; invk[l2] = i1;
        float tt = q0 * i0 * i0 + q1 * i1 * i1;
#pragma unroll
        for (int off = 16; off; off >>= 1) tt += __shfl_xor_sync(0xFFFFFFFFu, tt, off);
        if (lane == 0) invts[0] = 1.f / (sqrtf(tt) + 1e-12f);
    }
    __syncthreads();
    float invt = invts[0];

    // ---- split-bf16 into staging (pitch 66, reusing x regions), out ----
#pragma unroll
    for (int mt = 0; mt < 4; mt++)
#pragma unroll
        for (int nt = 0; nt < 4; nt++)
#pragma unroll
            for (int q = 0; q < 4; q++) {
                int d = wm * 64 + mt * 16 + lr + ((q >> 1) * 8);
                int k = wn * 32 + nt * 8 + lc + (q & 1);
                float val = accv[mt][nt][q] * invk[k] * invt;
                __nv_bfloat16 h = __float2bfloat16(val);
                *(__nv_bfloat16*)(sm + O_XH + (d * 66 + k) * 2) = h;
                *(__nv_bfloat16*)(sm + O_XL + (d * 66 + k) * 2) =
                    __float2bfloat16(val - __bfloat162float(h));
            }
    __syncthreads();
    for (int i = tid; i < 8192; i += 256) {
        int d = i >> 5, kp = i & 31;
        uint32_t vh = lds32(xh_s + (uint32_t)(d * 66 + kp * 2) * 2);
        uint32_t vl = lds32(xl_s + (uint32_t)(d * 66 + kp * 2) * 2);
        size_t go = (size_t)b * VLAD_DIM + d * 64 + kp * 2;
        *(uint32_t*)((char*)g_Ah + go * 2) = vh;
        *(uint32_t*)((char*)g_Al + go * 2) = vl;
    }
}

// ---------------------------------------------------------------------------
// Transpose + split: src[k][n] fp32 -> dh/dl[n][k] bf16 (pads zero-filled).
// ---------------------------------------------------------------------------
__global__ void __launch_bounds__(256) k_cvt_trans(
    const float* __restrict__ src, int ldsrc, int Kreal, int Nreal,
    __nv_bfloat16* __restrict__ dh, __nv_bfloat16* __restrict__ dl, int ldd)
{
    __shared__ float smt[32][33];
    int k0 = blockIdx.x * 32;
    int n0 = blockIdx.y * 32;
    int tx = threadIdx.x & 31;
    int ty = threadIdx.x >> 5;
#pragma unroll
    for (int i = 0; i < 4; i++) {
        int kk = ty + i * 8;
        int n = n0 + tx;
        float v = (k0 + kk < Kreal && n < Nreal) ? src[(size_t)(k0 + kk) * ldsrc + n] : 0.f;
        smt[kk][tx] = v;
    }
    __syncthreads();
#pragma unroll
    for (int i = 0; i < 4; i++) {
        int nn = ty + i * 8;
        float v = smt[tx][nn];
        __nv_bfloat16 h = __float2bfloat16(v);
        __nv_bfloat16 l = __float2bfloat16(v - __bfloat162float(h));
        size_t o = (size_t)(n0 + nn) * ldd + k0 + tx;
        dh[o] = h;
        dl[o] = l;
    }
}

// ---------------------------------------------------------------------------
// Split-bf16 HMMA GEMM (unchanged, passing).
// ---------------------------------------------------------------------------
#define KBLK 64
#define SPITCH 72
#define SPB (SPITCH * 2)
#define TILE_B (128 * SPB)
#define STAGE_B (4 * TILE_B)
#define MMA_SMEM_TOTAL (2 * STAGE_B)

__global__ void __launch_bounds__(256, 1) k_mma(
    const __nv_bfloat16* __restrict__ Ah, const __nv_bfloat16* __restrict__ Al,
    const __nv_bfloat16* __restrict__ Bh, const __nv_bfloat16* __restrict__ Bl,
    int K, float* __restrict__ C, int M, int N,
    const float* __restrict__ bias, int act,
    __nv_bfloat16* __restrict__ Dh, __nv_bfloat16* __restrict__ Dl, int ldd)
{
    extern __shared__ __align__(16) char smem[];
    uint32_t sb = smem_u32(smem);
    int tid = threadIdx.x;
    int wid = tid >> 5, lane = tid & 31;
    int wm = wid & 3;
    int wn = wid >> 2;
    int m0 = blockIdx.y * 128;
    int n0 = blockIdx.x * 128;

    const __nv_bfloat16* srcs[4] = {
        Ah + (size_t)m0 * K, Al + (size_t)m0 * K,
        Bh + (size_t)n0 * K, Bl + (size_t)n0 * K };

    int lrow = tid >> 3;
    int lchk = tid & 7;

    float acc[2][8][4];
#pragma unroll
    for (int i = 0; i < 2; i++)
#pragma unroll
        for (int j = 0; j < 8; j++)
#pragma unroll
            for (int q = 0; q < 4; q++) acc[i][j][q] = 0.f;

    auto load_stage = [&](int s, int kb) {
        uint32_t sd = sb + s * STAGE_B;
        size_t kOff = (size_t)kb * KBLK;
#pragma unroll
        for (int v = 0; v < 4; v++) {
            const __nv_bfloat16* g = srcs[v] + kOff;
#pragma unroll
            for (int p = 0; p < 4; p++) {
                int rr = lrow + p * 32;
                uint32_t d = sd + v * TILE_B + rr * SPB + lchk * 16;
                const void* sptr = (const char*)(g + (size_t)rr * K) + lchk * 16;
                CP_ASYNC16(d, sptr);
            }
        }
        CP_COMMIT();
    };

    load_stage(0, 0);

    int lr = lane >> 2;
    int lc = (lane & 3) * 2;
    int nkb = K / KBLK;

    for (int kb = 0; kb < nkb; kb++) {
        int s = kb & 1;
        CP_WAIT0();
        __syncthreads();
        if (kb + 1 < nkb) load_stage(s ^ 1, kb + 1);

        uint32_t sAh = sb + s * STAGE_B;
        uint32_t sAl = sAh + TILE_B;
        uint32_t sBh = sAh + 2 * TILE_B;
        uint32_t sBl = sAh + 3 * TILE_B;

#pragma unroll
        for (int ks = 0; ks < 4; ks++) {
            int kl = ks * 16;
            uint32_t ah[2][4], al_[2][4];
#pragma unroll
            for (int mt = 0; mt < 2; mt++) {
                uint32_t base = (uint32_t)((wm * 32 + mt * 16 + lr) * SPB + (kl + lc) * 2);
                ah[mt][0]  = lds32(sAh + base);
                ah[mt][1]  = lds32(sAh + base + 8 * SPB);
                ah[mt][2]  = lds32(sAh + base + 16);
                ah[mt][3]  = lds32(sAh + base + 8 * SPB + 16);
                al_[mt][0] = lds32(sAl + base);
                al_[mt][1] = lds32(sAl + base + 8 * SPB);
                al_[mt][2] = lds32(sAl + base + 16);
                al_[mt][3] = lds32(sAl + base + 8 * SPB + 16);
            }
            uint32_t bh[8][2], bl_[8][2];
#pragma unroll
            for (int nt = 0; nt < 8; nt++) {
                uint32_t base = (uint32_t)((wn * 64 + nt * 8 + lr) * SPB + (kl + lc) * 2);
                bh[nt][0]  = lds32(sBh + base);
                bh[nt][1]  = lds32(sBh + base + 16);
                bl_[nt][0] = lds32(sBl + base);
                bl_[nt][1] = lds32(sBl + base + 16);
            }
#pragma unroll
            for (int mt = 0; mt < 2; mt++)
#pragma unroll
                for (int nt = 0; nt < 8; nt++) {
                    mma16816(acc[mt][nt], ah[mt], bh[nt]);
                    mma16816(acc[mt][nt], ah[mt], bl_[nt]);
                    mma16816(acc[mt][nt], al_[mt], bh[nt]);
                }
        }
    }

    auto emit = [&](int r, int c, float v) {
        bool in = (r < M && c < N);
        float val = 0.f;
        if (in) {
            val = v + (bias ? bias[c] : 0.f);
            if (act == 1) val = fmaxf(val, 0.f);
            if (C) C[(size_t)r * N + c] = val;
        }
        if (Dh) {
            __nv_bfloat16 h = __float2bfloat16(val);
            Dh[(size_t)r * ldd + c] = h;
            Dl[(size_t)r * ldd + c] = __float2bfloat16(val - __bfloat162float(h));
        }
    };
#pragma unroll
    for (int mt = 0; mt < 2; mt++) {
#pragma unroll
        for (int nt = 0; nt < 8; nt++) {
            int r = m0 + wm * 32 + mt * 16 + lr;
            int c = n0 + wn * 64 + nt * 8 + lc;
            emit(r,     c,     acc[mt][nt][0]);
            emit(r,     c + 1, acc[mt][nt][1]);
            emit(r + 8, c,     acc[mt][nt][2]);
            emit(r + 8, c + 1, acc[mt][nt][3]);
        }
    }
}

// ---------------------------------------------------------------------------
// Small SGEMM (64x64x16) for G3.
// ---------------------------------------------------------------------------
__global__ void __launch_bounds__(256) k_sgemm(
    const float* __restrict__ A, const float* __restrict__ B,
    const float* __restrict__ bias, float* __restrict__ C,
    int M, int N, int K, int act)
{
    __shared__ __align__(16) float As[16][64];
    __shared__ __align__(16) float Bs[16][64];

    int tid = threadIdx.x;
    int tx = tid & 15, ty = tid >> 4;
    int row0 = blockIdx.y * 64, col0 = blockIdx.x * 64;

    float c[4][4];
#pragma unroll
    for (int i = 0; i < 4; i++)
#pragma unroll
        for (int j = 0; j < 4; j++) c[i][j] = 0.f;

    int am = tid >> 2;
    int ak = (tid & 3) * 4;
    int bk = tid >> 4;
    int bn = (tid & 15) * 4;

    for (int k0 = 0; k0 < K; k0 += 16) {
        int arow = row0 + am;
        if (arow < M && k0 + ak + 3 < K) {
            float4 v = *reinterpret_cast<const float4*>(&A[(size_t)arow * K + k0 + ak]);
            As[ak + 0][am] = v.x; As[ak + 1][am] = v.y;
            As[ak + 2][am] = v.z; As[ak + 3][am] = v.w;
        } else {
#pragma unroll
            for (int i = 0; i < 4; i++) {
                int kk = k0 + ak + i;
                As[ak + i][am] = (arow < M && kk < K) ? A[(size_t)arow * K + kk] : 0.f;
            }
        }
        int brow = k0 + bk;
        if (brow < K && col0 + bn + 3 < N) {
            float4 v = *reinterpret_cast<const float4*>(&B[(size_t)brow * N + col0 + bn]);
            *reinterpret_cast<float4*>(&Bs[bk][bn]) = v;
        } else {
#pragma unroll
            for (int i = 0; i < 4; i++) {
                int nn = col0 + bn + i;
                Bs[bk][bn + i] = (brow < K && nn < N) ? B[(size_t)brow * N + nn] : 0.f;
            }
        }
        __syncthreads();
#pragma unroll
        for (int kk = 0; kk < 16; kk++) {
            float4 av = *reinterpret_cast<const float4*>(&As[kk][ty * 4]);
            float4 bv = *reinterpret_cast<const float4*>(&Bs[kk][tx * 4]);
            float a[4] = {av.x, av.y, av.z, av.w};
            float bb[4] = {bv.x, bv.y, bv.z, bv.w};
#pragma unroll
            for (int i = 0; i < 4; i++)
#pragma unroll
                for (int j = 0; j < 4; j++) c[i][j] = fmaf(a[i], bb[j], c[i][j]);
        }
        __syncthreads();
    }

#pragma unroll
    for (int i = 0; i < 4; i++) {
        int r = row0 + ty * 4 + i;
        if (r >= M) continue;
#pragma unroll
        for (int j = 0; j < 4; j++) {
            int cc = col0 + tx * 4 + j;
            if (cc >= N) continue;
            float v = c[i][j];
            if (bias) v += bias[cc];
            if (act == 1) v = fmaxf(v, 0.f);
            C[(size_t)r * N + cc] = v;
        }
    }
}

// ---------------------------------------------------------------------------
// GAT kernels
// ---------------------------------------------------------------------------
__global__ void __launch_bounds__(128) k_gat_h(
    const float* __restrict__ W, const float* __restrict__ a_s,
    const float* __restrict__ a_d)
{
    int b = blockIdx.x, t = threadIdx.x;
    __shared__ float xsm[NODE_D];
    __shared__ float rs[8];
    xsm[t] = g_x[b * NODE_D + t];
    __syncthreads();
    float acc = 0.f;
#pragma unroll 8
    for (int d = 0; d < NODE_D; d++) acc = fmaf(xsm[d], __ldg(&W[d * NODE_D + t]), acc);
    g_h[b * NODE_D + t] = acc;
    float ps = acc * __ldg(&a_s[t]);
    float pd = acc * __ldg(&a_d[t]);
#pragma unroll
    for (int off = 16; off; off >>= 1) {
        ps += __shfl_xor_sync(0xFFFFFFFFu, ps, off);
        pd += __shfl_xor_sync(0xFFFFFFFFu, pd, off);
    }
    if ((t & 31) == 0) { rs[t >> 5] = ps; rs[4 + (t >> 5)] = pd; }
    __syncthreads();
    if (t == 0) g_es[b] = rs[0] + rs[1] + rs[2] + rs[3];
    if (t == 1) g_ed[b] = rs[4] + rs[5] + rs[6] + rs[7];
}

__global__ void k_init()
{
    int i = blockIdx.x * blockDim.x + threadIdx.x;
    if (i < N_NODES) g_den[i] = 0.f;
    if (i < N_NODES * NODE_D) g_aggr[i] = 0.f;
}

__global__ void k_edge12(const int* __restrict__ ei)
{
    int e = blockIdx.x * blockDim.x + threadIdx.x;
    if (e >= E_EXT) return;
    int s, d;
    if (e < N_EDGES) { s = ei[e]; d = ei[N_EDGES + e]; }
    else { s = e - N_EDGES; d = s; }
    float v = g_es[s] + g_ed[d];
    v = (v > 0.f) ? v : 0.2f * v;
    float ex = __expf(v);
    g_ex[e] = ex;
    atomicAdd(&g_den[d], ex);
}

__global__ void k_edge3(const int* __restrict__ ei)
{
    int gt = blockIdx.x * blockDim.x + threadIdx.x;
    int w = gt >> 5, lane = gt & 31;
    if (w >= E_EXT) return;
    int s, d;
    if (w < N_EDGES) { s = ei[w]; d = ei[N_EDGES + w]; }
    else { s = w - N_EDGES; d = s; }
    float alpha = g_ex[w] / g_den[d];
#pragma unroll
    for (int i = 0; i < 4; i++) {
        int c = lane + 32 * i;
        atomicAdd(&g_aggr[d * NODE_D + c], g_h[s * NODE_D + c] * alpha);
    }
}

__global__ void k_gat_fin(const float* __restrict__ b)
{
    int i = blockIdx.x * blockDim.x + threadIdx.x;
    if (i >= N_NODES * NODE_D) return;
    float v = g_aggr[i] + __ldg(&b[i & (NODE_D - 1)]);
    g_x[i] = (v > 0.f) ? v : (__expf(v) - 1.f);
}

// ---------------------------------------------------------------------------
// Edge-attr MLP: 1 -> 8 -> 16 -> 32
// ---------------------------------------------------------------------------
__global__ void __launch_bounds__(256) k_ef(
    const float* __restrict__ ea,
    const float* __restrict__ w1, const float* __restrict__ b1,
    const float* __restrict__ w2, const float* __restrict__ b2,
    const float* __restrict__ w3, const float* __restrict__ b3)
{
    __shared__ float w1s[8], b1s[8], w2s[128], b2s[16], w3s[512], b3s[32];
    int t = threadIdx.x;
    if (t < 8)   { w1s[t] = w1[t]; b1s[t] = b1[t]; }
    if (t < 128) w2s[t] = w2[t];
    if (t < 16)  b2s[t] = b2[t];
    if (t < 32)  b3s[t] = b3[t];
    for (int i = t; i < 512; i += blockDim.x) w3s[i] = w3[i];
    __syncthreads();
    int e = blockIdx.x * blockDim.x + t;
    if (e >= N_EDGES) return;
    float a = ea[e];
    float t8[8];
#pragma unroll
    for (int j = 0; j < 8; j++) t8[j] = fmaxf(fmaf(a, w1s[j], b1s[j]), 0.f);
    float t16[16];
#pragma unroll
    for (int c = 0; c < 16; c++) {
        float acc = b2s[c];
#pragma unroll
        for (int j = 0; j < 8; j++) acc = fmaf(t8[j], w2s[j * 16 + c], acc);
        t16[c] = fmaxf(acc, 0.f);
    }
#pragma unroll
    for (int c = 0; c < 32; c++) {
        float acc = b3s[c];
#pragma unroll
        for (int j = 0; j < 16; j++) acc = fmaf(t16[j], w3s[j * 32 + c], acc);
        g_ef2[e * EDGE_D + c] = acc;
    }
}

// ---------------------------------------------------------------------------
// Final fused edge classifier.
// ---------------------------------------------------------------------------
__global__ void __launch_bounds__(128) k_final(
    const int* __restrict__ ei,
    const float* __restrict__ dp_w, const float* __restrict__ dp_b,
    const float* __restrict__ ec_w1, const float* __restrict__ ec_b1,
    const float* __restrict__ ec_w2, const float* __restrict__ ec_b2,
    float* __restrict__ out)
{
    __shared__ float dpw_s[288 * 32];
    __shared__ float ecw1_s[32 * 16];
    __shared__ float dpb_s[32];
    __shared__ float ecb1_s[16];
    __shared__ float ecw2_s[16];
    __shared__ float vec_s[4][292];
    __shared__ float o32_s[4][32];

    int tid = threadIdx.x;
    for (int i = tid; i < 288 * 32; i += 128) dpw_s[i] = dp_w[i];
    for (int i = tid; i < 512; i += 128) ecw1_s[i] = ec_w1[i];
    if (tid < 32) dpb_s[tid] = dp_b[tid];
    if (tid < 16) { ecb1_s[tid] = ec_b1[tid]; ecw2_s[tid] = ec_w2[tid]; }
    __syncthreads();

    float b2 = __ldg(ec_b2);
    int warp = tid >> 5, lane = tid & 31;
    int gw = blockIdx.x * 4 + warp;
    int nw = gridDim.x * 4;

    for (int e = gw; e < N_EDGES; e += nw) {
        int s = ei[e], d = ei[N_EDGES + e];
        const float* xsp = g_x + s * NODE_D;
        const float* xdp = g_x + d * NODE_D;
#pragma unroll
        for (int i = 0; i < 4; i++) {
            vec_s[warp][lane + 32 * i]       = xsp[lane + 32 * i];
            vec_s[warp][128 + lane + 32 * i] = xdp[lane + 32 * i];
        }
        vec_s[warp][256 + lane] = g_ef2[e * EDGE_D + lane];
        __syncwarp();

        float acc = dpb_s[lane];
#pragma unroll 4
        for (int i = 0; i < 288; i++) acc = fmaf(vec_s[warp][i], dpw_s[i * 32 + lane], acc);
        o32_s[warp][lane] = acc;
        __syncwarp();

        float hh = 0.f;
        if (lane < 16) {
            hh = ecb1_s[lane];
#pragma unroll 4
            for (int j = 0; j < 32; j++) hh = fmaf(o32_s[warp][j], ecw1_s[j * 16 + lane], hh);
            hh = fmaxf(hh, 0.f) * ecw2_s[lane];
        }
#pragma unroll
        for (int off = 8; off; off >>= 1) hh += __shfl_xor_sync(0xFFFFFFFFu, hh, off);
        if (lane == 0) out[e] = 1.f / (1.f + __expf(-(hh + b2)));
        __syncwarp();
    }
}

// ---------------------------------------------------------------------------
extern "C" void kernel_launch(void* const* d_in, const int* in_sizes, int n_in,
                              void* d_out, int out_size)
{
    (void)in_sizes; (void)n_in; (void)out_size;
    const float* node_feats = (const float*)d_in[0];
    const float* edge_attr  = (const float*)d_in[1];
    const float* nv_cw      = (const float*)d_in[2];
    const float* nv_cb      = (const float*)d_in[3];
    const float* nv_cw2     = (const float*)d_in[4];
    const float* nv_hw      = (const float*)d_in[5];
    const float* ne_w1      = (const float*)d_in[6];
    const float* ne_b1      = (const float*)d_in[7];
    const float* ne_w2      = (const float*)d_in[8];
    const float* ne_b2      = (const float*)d_in[9];
    const float* ee_w1      = (const float*)d_in[10];
    const float* ee_b1      = (const float*)d_in[11];
    const float* ee_w2      = (const float*)d_in[12];
    const float* ee_b2      = (const float*)d_in[13];
    const float* ee_w3      = (const float*)d_in[14];
    const float* ee_b3      = (const float*)d_in[15];
    const float* gat_w      = (const float*)d_in[16];
    const float* gat_as     = (const float*)d_in[17];
    const float* gat_ad     = (const float*)d_in[18];
    const float* gat_b      = (const float*)d_in[19];
    const float* dp_w       = (const float*)d_in[20];
    const float* dp_b       = (const float*)d_in[21];
    const float* ec_w1      = (const float*)d_in[22];
    const float* ec_b1      = (const float*)d_in[23];
    const float* ec_w2      = (const float*)d_in[24];
    const float* ec_b2      = (const float*)d_in[25];
    const int*   edge_index = (const int*)d_in[26];
    float* out = (float*)d_out;

    float *p_h1, *p_x;
    __nv_bfloat16 *p_Ah, *p_Al, *p_Bh, *p_Bl, *p_Ah2, *p_Al2, *p_Bh2, *p_Bl2;
    cudaGetSymbolAddress((void**)&p_h1, g_h1);
    cudaGetSymbolAddress((void**)&p_x, g_x);
    cudaGetSymbolAddress((void**)&p_Ah, g_Ah);
    cudaGetSymbolAddress((void**)&p_Al, g_Al);
    cudaGetSymbolAddress((void**)&p_Bh, g_Bh);
    cudaGetSymbolAddress((void**)&p_Bl, g_Bl);
    cudaGetSymbolAddress((void**)&p_Ah2, g_Ah2);
    cudaGetSymbolAddress((void**)&p_Al2, g_Al2);
    cudaGetSymbolAddress((void**)&p_Bh2, g_Bh2);
    cudaGetSymbolAddress((void**)&p_Bl2, g_Bl2);

    cudaFuncSetAttribute(k_mma, cudaFuncAttributeMaxDynamicSharedMemorySize, MMA_SMEM_TOTAL);
    cudaFuncSetAttribute(k_nv, cudaFuncAttributeMaxDynamicSharedMemorySize, NV_SMEM);

    // 0) prep: cw^T split + B operand conversions
    k_prep_cw<<<64, 256>>>(nv_cw);
    {
        dim3 g(VLAD_DIM / 32, N_PAD / 32);
        k_cvt_trans<<<g, 256>>>(nv_hw, H0D, VLAD_DIM, H0D, p_Bh, p_Bl, VLAD_DIM);
    }
    {
        dim3 g(K2PAD / 32, N2PAD / 32);
        k_cvt_trans<<<g, 256>>>(ne_w1, H1D, H0D, H1D, p_Bh2, p_Bl2, K2PAD);
    }

    // 1) FUSED NetVLAD -> g_Ah/g_Al
    k_nv<<<N_NODES, 256, NV_SMEM>>>(node_feats, nv_cb, nv_cw2);

    // 2) G1 HMMA: h0 = vlad @ hw -> split-bf16 A operand of G2
    {
        dim3 g(N_PAD / 128, M_PAD / 128);
        k_mma<<<g, 256, MMA_SMEM_TOTAL>>>(p_Ah, p_Al, p_Bh, p_Bl, VLAD_DIM,
                                          nullptr, N_NODES, H0D, nullptr, 0,
                                          p_Ah2, p_Al2, K2PAD);
    }
    // 3) G2 HMMA: h1 = relu(h0 @ ne_w1 + b1)
    {
        dim3 g(N2PAD / 128, M_PAD / 128);
        k_mma<<<g, 256, MMA_SMEM_TOTAL>>>(p_Ah2, p_Al2, p_Bh2, p_Bl2, K2PAD,
                                          p_h1, N_NODES, H1D, ne_b1, 1,
                                          nullptr, nullptr, 0);
    }
    // 4) G3: x = h1 @ ne_w2 + b2
    {
        dim3 g((NODE_D + 63) / 64, (N_NODES + 63) / 64);
        k_sgemm<<<g, 256>>>(p_h1, ne_w2, ne_b2, p_x, N_NODES, NODE_D, H1D, 0);
    }

    // 5) edge-attr MLP
    k_ef<<<(N_EDGES + 255) / 256, 256>>>(edge_attr, ee_w1, ee_b1, ee_w2, ee_b2, ee_w3, ee_b3);

    // 6) 3 GAT layers
    for (int l = 0; l < DEPTH; l++) {
        k_gat_h<<<N_NODES, 128>>>(gat_w + l * NODE_D * NODE_D,
                                  gat_as + l * NODE_D, gat_ad + l * NODE_D);
        k_init<<<(N_NODES * NODE_D + 255) / 256, 256>>>();
        k_edge12<<<(E_EXT + 255) / 256, 256>>>(edge_index);
        k_edge3<<<((E_EXT * 32) + 255) / 256, 256>>>(edge_index);
        k_gat_fin<<<(N_NODES * NODE_D + 255) / 256, 256>>>(gat_b + l * NODE_D);
    }

    // 7) fused edge classifier -> out
    k_final<<<512, 128>>>(edge_index, dp_w, dp_b, ec_w1, ec_b1, ec_w2, ec_b2, out);
}

// round 10
// speedup vs baseline: 4.3509x; 1.0053x over previous
#include <cuda_runtime.h>
#include <cuda_bf16.h>
#include <math.h>
#include <stdint.h>

#define N_NODES 2000
#define NUM_KP 500
#define DESC 256
#define NVK 64
#define VLAD_DIM (DESC*NVK)        // 16384
#define H0D (NUM_KP*2)             // 1000
#define H1D NUM_KP                 // 500
#define NODE_D 128
#define EDGE_D 32
#define N_EDGES 64000
#define E_EXT (N_EDGES + N_NODES)  // 66000
#define DEPTH 3

#define M_PAD 2048
#define N_PAD 1024
#define K2PAD 1024
#define N2PAD 512

typedef unsigned long long u64;

// ---------------- scratch (device globals; no runtime allocation) ----------
__device__ float    g_h1[N_NODES * H1D];
__device__ float    g_x[N_NODES * NODE_D];
__device__ float    g_h[N_NODES * NODE_D];
__device__ float    g_es[N_NODES];
__device__ float    g_ed[N_NODES];
__device__ float    g_ex[E_EXT];
__device__ float    g_den[N_NODES];
__device__ float    g_aggr[N_NODES * NODE_D];
__device__ float    g_ef2[N_EDGES * EDGE_D];
// split-bf16 operands (pad regions stay zero: static zero-init, never written)
__device__ __nv_bfloat16 g_Ah[(size_t)M_PAD * VLAD_DIM];
__device__ __nv_bfloat16 g_Al[(size_t)M_PAD * VLAD_DIM];
__device__ __nv_bfloat16 g_Bh[(size_t)N_PAD * VLAD_DIM];
__device__ __nv_bfloat16 g_Bl[(size_t)N_PAD * VLAD_DIM];
__device__ __nv_bfloat16 g_Ah2[(size_t)M_PAD * K2PAD];
__device__ __nv_bfloat16 g_Al2[(size_t)M_PAD * K2PAD];
__device__ __nv_bfloat16 g_Bh2[(size_t)N2PAD * K2PAD];
__device__ __nv_bfloat16 g_Bl2[(size_t)N2PAD * K2PAD];
__device__ __nv_bfloat16 g_cwTh[NVK * DESC];
__device__ __nv_bfloat16 g_cwTl[NVK * DESC];

// ---------------- helpers ---------------------------------------------------
__device__ __forceinline__ uint32_t smem_u32(const void* p) {
    uint32_t a;
    asm("{ .reg .u64 t; cvta.to.shared.u64 t, %1; cvt.u32.u64 %0, t; }" : "=r"(a) : "l"(p));
    return a;
}
__device__ __forceinline__ uint32_t lds32(uint32_t addr) {
    uint32_t v;
    asm volatile("ld.shared.b32 %0, [%1];" : "=r"(v) : "r"(addr));
    return v;
}
__device__ __forceinline__ void ldm_x4(uint32_t* r, uint32_t addr) {
    asm volatile("ldmatrix.sync.aligned.m8n8.x4.shared.b16 {%0,%1,%2,%3}, [%4];"
        : "=r"(r[0]), "=r"(r[1]), "=r"(r[2]), "=r"(r[3]) : "r"(addr));
}
__device__ __forceinline__ void ldm_x4_t(uint32_t* r, uint32_t addr) {
    asm volatile("ldmatrix.sync.aligned.m8n8.x4.trans.shared.b16 {%0,%1,%2,%3}, [%4];"
        : "=r"(r[0]), "=r"(r[1]), "=r"(r[2]), "=r"(r[3]) : "r"(addr));
}
__device__ __forceinline__ void mma16816(float* c, const uint32_t* a, const uint32_t* b) {
    asm volatile(
        "mma.sync.aligned.m16n8k16.row.col.f32.bf16.bf16.f32 "
        "{%0,%1,%2,%3}, {%4,%5,%6,%7}, {%8,%9}, {%0,%1,%2,%3};"
        : "+f"(c[0]), "+f"(c[1]), "+f"(c[2]), "+f"(c[3])
        : "r"(a[0]), "r"(a[1]), "r"(a[2]), "r"(a[3]), "r"(b[0]), "r"(b[1]));
}
#define CP_ASYNC16(dst, src) \
    asm volatile("cp.async.cg.shared.global [%0], [%1], 16;" :: "r"(dst), "l"(src) : "memory")
#define CP_COMMIT()  asm volatile("cp.async.commit_group;" ::: "memory")
#define CP_WAIT0()   asm volatile("cp.async.wait_group 0;" ::: "memory")

__device__ __forceinline__ float sanit(float v) {
    if (!isfinite(v)) v = (v != v) ? 0.f : (v > 0.f ? 3.402823466e38f : -3.402823466e38f);
    return v;
}

// ---------------------------------------------------------------------------
// Prep: cw [256][64] fp32 -> cw^T split-bf16 [64][256]
// ---------------------------------------------------------------------------
__global__ void k_prep_cw(const float* __restrict__ cw)
{
    int i = blockIdx.x * 256 + threadIdx.x;    // 0..16383
    int k = i >> 8, d = i & 255;
    float v = cw[d * 64 + k];
    __nv_bfloat16 h = __float2bfloat16(v);
    g_cwTh[k * 256 + d] = h;
    g_cwTl[k * 256 + d] = __float2bfloat16(v - __bfloat162float(h));
}

// ---------------------------------------------------------------------------
// FUSED NetVLAD with ldmatrix fragment loads. One CTA per node. (R9, passing)
// ---------------------------------------------------------------------------
#define O_CWH 0          // cwT hi [64 k][264 d] bf16 (pitch 528B), 33792B
#define O_CWL 33792
#define O_XH  67584      // x hi [64 n][264 d], 33792B
#define O_XL  101376
#define O_LOG 135168     // logits [64][68] f32 (17408B); reused as actT after
#define O_ACTH 135168    // actT hi [64 k][72 n] bf16 pitch 144B (9216B)
#define O_ACTL 144384
#define O_RED 153600     // [8][64] f32 (2048B)
#define O_ASUM 155648    // [64] f32
#define O_REDK 155904    // [64][4] f32
#define O_INVK 156928    // [64] f32
#define O_INVT 157184
#define NV_SMEM 157200

__global__ void __launch_bounds__(256, 1) k_nv(
    const float* __restrict__ feats, const float* __restrict__ cb,
    const float* __restrict__ cw2)
{
    extern __shared__ __align__(16) char sm[];
    int b = blockIdx.x;
    int tid = threadIdx.x, lane = tid & 31, wid = tid >> 5;
    int wm = wid & 3, wn = wid >> 2;
    int lr = lane >> 2, lc = (lane & 3) * 2;

    uint32_t cwh_s = smem_u32(sm + O_CWH), cwl_s = smem_u32(sm + O_CWL);
    uint32_t xh_s  = smem_u32(sm + O_XH),  xl_s  = smem_u32(sm + O_XL);
    uint32_t ah_s  = smem_u32(sm + O_ACTH), al_s = smem_u32(sm + O_ACTL);
    float* logit = (float*)(sm + O_LOG);
    float* red   = (float*)(sm + O_RED);
    float* asums = (float*)(sm + O_ASUM);
    float* redk  = (float*)(sm + O_REDK);
    float* invk  = (float*)(sm + O_INVK);
    float* invts = (float*)(sm + O_INVT);

    int l7  = lane & 7;
    int s8  = (lane & 8) ? 8 : 0;
    int s16 = (lane & 16) ? 8 : 0;
    int rowA_log = wm * 16 + l7 + s8;
    int rowB_nt  = l7 + s16;
    int rowX_n   = l7 + s16;

    for (int i = tid; i < 2048; i += 256) {
        int k = i >> 5, c = i & 31;
        *(uint4*)(sm + O_CWH + k * 528 + c * 16) = ((const uint4*)g_cwTh)[i];
        *(uint4*)(sm + O_CWL + k * 528 + c * 16) = ((const uint4*)g_cwTl)[i];
    }

    float accv[4][4][4];
#pragma unroll
    for (int mt = 0; mt < 4; mt++)
#pragma unroll
        for (int nt = 0; nt < 4; nt++)
#pragma unroll
            for (int q = 0; q < 4; q++) accv[mt][nt][q] = 0.f;
    float s0 = 0.f, s1 = 0.f;
    float cb0 = cb[lane], cb1 = cb[lane + 32];

    for (int kb = 0; kb < 8; kb++) {
        __syncthreads();
        int n0 = kb * 64;
        for (int i = tid; i < 4096; i += 256) {
            int row = i >> 6, c4 = i & 63;
            int gn = n0 + row;
            float4 v = make_float4(0.f, 0.f, 0.f, 0.f);
            if (gn < NUM_KP) v = ((const float4*)feats)[((size_t)b * NUM_KP + gn) * 64 + c4];
            float vv[4] = { sanit(v.x), sanit(v.y), sanit(v.z), sanit(v.w) };
            __nv_bfloat16 hh[4], ll[4];
#pragma unroll
            for (int j = 0; j < 4; j++) {
                hh[j] = __float2bfloat16(vv[j]);
                ll[j] = __float2bfloat16(vv[j] - __bfloat162float(hh[j]));
            }
            char* pxh = sm + O_XH + row * 528 + c4 * 8;
            char* pxl = sm + O_XL + row * 528 + c4 * 8;
            *(__nv_bfloat162*)pxh       = __nv_bfloat162(hh[0], hh[1]);
            *(__nv_bfloat162*)(pxh + 4) = __nv_bfloat162(hh[2], hh[3]);
            *(__nv_bfloat162*)pxl       = __nv_bfloat162(ll[0], ll[1]);
            *(__nv_bfloat162*)(pxl + 4) = __nv_bfloat162(ll[2], ll[3]);
        }
        __syncthreads();

        // ---- logits GEMM ----
        float acc[4][4];
#pragma unroll
        for (int nt = 0; nt < 4; nt++)
#pragma unroll
            for (int q = 0; q < 4; q++) acc[nt][q] = 0.f;
#pragma unroll
        for (int ks = 0; ks < 16; ks++) {
            int kl = ks * 16;
            uint32_t aoff = (uint32_t)(rowA_log * 528 + (kl + s16) * 2);
            uint32_t a[4], al_[4];
            ldm_x4(a,  xh_s + aoff);
            ldm_x4(al_, xl_s + aoff);
#pragma unroll
            for (int ntp = 0; ntp < 2; ntp++) {
                uint32_t boff = (uint32_t)((wn * 32 + ntp * 16 + rowB_nt) * 528 + (kl + s8) * 2);
                uint32_t bh4[4], bl4[4];
                ldm_x4(bh4, cwh_s + boff);
                ldm_x4(bl4, cwl_s + boff);
                mma16816(acc[2 * ntp],     a,   bh4);
                mma16816(acc[2 * ntp],     a,   bl4);
                mma16816(acc[2 * ntp],     al_, bh4);
                mma16816(acc[2 * ntp + 1], a,   bh4 + 2);
                mma16816(acc[2 * ntp + 1], a,   bl4 + 2);
                mma16816(acc[2 * ntp + 1], al_, bh4 + 2);
            }
        }
#pragma unroll
        for (int nt = 0; nt < 4; nt++)
#pragma unroll
            for (int q = 0; q < 4; q++) {
                int row = wm * 16 + lr + ((q >> 1) * 8);
                int col = wn * 32 + nt * 8 + lc + (q & 1);
                logit[row * 68 + col] = acc[nt][q];
            }
        __syncthreads();

        // ---- softmax ----
        float l0r[8], l1r[8];
#pragma unroll
        for (int rr = 0; rr < 8; rr++) {
            int row = wid * 8 + rr;
            l0r[rr] = logit[row * 68 + lane] + cb0;
            l1r[rr] = logit[row * 68 + lane + 32] + cb1;
        }
        __syncthreads();
#pragma unroll
        for (int rr = 0; rr < 8; rr++) {
            int row = wid * 8 + rr;
            int gn = n0 + row;
            float m = fmaxf(l0r[rr], l1r[rr]);
#pragma unroll
            for (int off = 16; off; off >>= 1) m = fmaxf(m, __shfl_xor_sync(0xFFFFFFFFu, m, off));
            float e0 = __expf(l0r[rr] - m), e1 = __expf(l1r[rr] - m);
            float ss = e0 + e1;
#pragma unroll
            for (int off = 16; off; off >>= 1) ss += __shfl_xor_sync(0xFFFFFFFFu, ss, off);
            float inv = 1.f / ss;
            if (gn < NUM_KP) { e0 *= inv; e1 *= inv; s0 += e0; s1 += e1; }
            else             { e0 = 0.f;  e1 = 0.f; }
            __nv_bfloat16 h0 = __float2bfloat16(e0);
            __nv_bfloat16 h1 = __float2bfloat16(e1);
            *(__nv_bfloat16*)(sm + O_ACTH + lane * 144 + row * 2)        = h0;
            *(__nv_bfloat16*)(sm + O_ACTH + (lane + 32) * 144 + row * 2) = h1;
            *(__nv_bfloat16*)(sm + O_ACTL + lane * 144 + row * 2) =
                __float2bfloat16(e0 - __bfloat162float(h0));
            *(__nv_bfloat16*)(sm + O_ACTL + (lane + 32) * 144 + row * 2) =
                __float2bfloat16(e1 - __bfloat162float(h1));
        }
        __syncthreads();

        // ---- vlad GEMM ----
#pragma unroll
        for (int ks = 0; ks < 4; ks++) {
            int kl = ks * 16;
            uint32_t bh4[2][4], bl4[2][4];
#pragma unroll
            for (int ntp = 0; ntp < 2; ntp++) {
                uint32_t boff = (uint32_t)((wn * 32 + ntp * 16 + rowB_nt) * 144 + (kl + s8) * 2);
                ldm_x4(bh4[ntp], ah_s + boff);
                ldm_x4(bl4[ntp], al_s + boff);
            }
#pragma unroll
            for (int mt = 0; mt < 4; mt++) {
                uint32_t aoff = (uint32_t)((kl + rowX_n) * 528 + (wm * 64 + mt * 16 + s8) * 2);
                uint32_t a[4], al2[4];
                ldm_x4_t(a,   xh_s + aoff);
                ldm_x4_t(al2, xl_s + aoff);
#pragma unroll
                for (int ntp = 0; ntp < 2; ntp++) {
                    mma16816(accv[mt][2 * ntp],     a,   bh4[ntp]);
                    mma16816(accv[mt][2 * ntp],     a,   bl4[ntp]);
                    mma16816(accv[mt][2 * ntp],     al2, bh4[ntp]);
                    mma16816(accv[mt][2 * ntp + 1], a,   bh4[ntp] + 2);
                    mma16816(accv[mt][2 * ntp + 1], a,   bl4[ntp] + 2);
                    mma16816(accv[mt][2 * ntp + 1], al2, bh4[ntp] + 2);
                }
            }
        }
    }

    // ---- asum reduce + cw2 load ----
    red[wid * 64 + lane]      = s0;
    red[wid * 64 + lane + 32] = s1;
    __syncthreads();
    if (tid < 32) {
        float t0 = 0.f, t1 = 0.f;
#pragma unroll
        for (int w = 0; w < 8; w++) { t0 += red[w * 64 + lane]; t1 += red[w * 64 + lane + 32]; }
        asums[lane] = t0; asums[lane + 32] = t1;
    }
    float* cw2s = (float*)(sm + O_XH);
    for (int i = tid; i < 4096; i += 256)
        ((float4*)cw2s)[i] = ((const float4*)cw2)[i];
    __syncthreads();

#pragma unroll
    for (int mt = 0; mt < 4; mt++)
#pragma unroll
        for (int nt = 0; nt < 4; nt++)
#pragma unroll
            for (int q = 0; q < 4; q++) {
                int d = wm * 64 + mt * 16 + lr + ((q >> 1) * 8);
                int k = wn * 32 + nt * 8 + lc + (q & 1);
                accv[mt][nt][q] -= asums[k] * cw2s[d * 64 + k];
            }
#pragma unroll
    for (int nt = 0; nt < 4; nt++) {
        float sq0 = 0.f, sq1 = 0.f;
#pragma unroll
        for (int mt = 0; mt < 4; mt++) {
            sq0 += accv[mt][nt][0] * accv[mt][nt][0] + accv[mt][nt][2] * accv[mt][nt][2];
            sq1 += accv[mt][nt][1] * accv[mt][nt][1] + accv[mt][nt][3] * accv[mt][nt][3];
        }
        sq0 += __shfl_xor_sync(0xFFFFFFFFu, sq0, 4);
        sq0 += __shfl_xor_sync(0xFFFFFFFFu, sq0, 8);
        sq0 += __shfl_xor_sync(0xFFFFFFFFu, sq0, 16);
        sq1 += __shfl_xor_sync(0xFFFFFFFFu, sq1, 4);
        sq1 += __shfl_xor_sync(0xFFFFFFFFu, sq1, 8);
        sq1 += __shfl_xor_sync(0xFFFFFFFFu, sq1, 16);
        if (lr == 0) {
            int k0 = wn * 32 + nt * 8 + lc;
            redk[k0 * 4 + wm]       = sq0;
            redk[(k0 + 1) * 4 + wm] = sq1;
        }
    }
    __syncthreads();
    if (tid < 32) {
        float q0 = redk[lane * 4] + redk[lane * 4 + 1] + redk[lane * 4 + 2] + redk[lane * 4 + 3];
        int l2 = lane + 32;
        float q1 = redk[l2 * 4] + redk[l2 * 4 + 1] + redk[l2 * 4 + 2] + redk[l2 * 4 + 3];
        float i0 = 1.f / (sqrtf(q0) + 1e-12f);
        float i1 = 1.f / (sqrtf(q1) + 1e-12f);
        invk[lane] = i0; invk[l2] = i1;
        float tt = q0 * i0 * i0 + q1 * i1 * i1;
#pragma unroll
        for (int off = 16; off; off >>= 1) tt += __shfl_xor_sync(0xFFFFFFFFu, tt, off);
        if (lane == 0) invts[0] = 1.f / (sqrtf(tt) + 1e-12f);
    }
    __syncthreads();
    float invt = invts[0];

#pragma unroll
    for (int mt = 0; mt < 4; mt++)
#pragma unroll
        for (int nt = 0; nt < 4; nt++)
#pragma unroll
            for (int q = 0; q < 4; q++) {
                int d = wm * 64 + mt * 16 + lr + ((q >> 1) * 8);
                int k = wn * 32 + nt * 8 + lc + (q & 1);
                float val = accv[mt][nt][q] * invk[k] * invt;
                __nv_bfloat16 h = __float2bfloat16(val);
                *(__nv_bfloat16*)(sm + O_XH + (d * 66 + k) * 2) = h;
                *(__nv_bfloat16*)(sm + O_XL + (d * 66 + k) * 2) =
                    __float2bfloat16(val - __bfloat162float(h));
            }
    __syncthreads();
    for (int i = tid; i < 8192; i += 256) {
        int d = i >> 5, kp = i & 31;
        uint32_t vh = lds32(xh_s + (uint32_t)(d * 66 + kp * 2) * 2);
        uint32_t vl = lds32(xl_s + (uint32_t)(d * 66 + kp * 2) * 2);
        size_t go = (size_t)b * VLAD_DIM + d * 64 + kp * 2;
        *(uint32_t*)((char*)g_Ah + go * 2) = vh;
        *(uint32_t*)((char*)g_Al + go * 2) = vl;
    }
}

// ---------------------------------------------------------------------------
// Transpose + split: src[k][n] fp32 -> dh/dl[n][k] bf16 (pads zero-filled).
// ---------------------------------------------------------------------------
__global__ void __launch_bounds__(256) k_cvt_trans(
    const float* __restrict__ src, int ldsrc, int Kreal, int Nreal,
    __nv_bfloat16* __restrict__ dh, __nv_bfloat16* __restrict__ dl, int ldd)
{
    __shared__ float smt[32][33];
    int k0 = blockIdx.x * 32;
    int n0 = blockIdx.y * 32;
    int tx = threadIdx.x & 31;
    int ty = threadIdx.x >> 5;
#pragma unroll
    for (int i = 0; i < 4; i++) {
        int kk = ty + i * 8;
        int n = n0 + tx;
        float v = (k0 + kk < Kreal && n < Nreal) ? src[(size_t)(k0 + kk) * ldsrc + n] : 0.f;
        smt[kk][tx] = v;
    }
    __syncthreads();
#pragma unroll
    for (int i = 0; i < 4; i++) {
        int nn = ty + i * 8;
        float v = smt[tx][nn];
        __nv_bfloat16 h = __float2bfloat16(v);
        __nv_bfloat16 l = __float2bfloat16(v - __bfloat162float(h));
        size_t o = (size_t)(n0 + nn) * ldd + k0 + tx;
        dh[o] = h;
        dl[o] = l;
    }
}

// ---------------------------------------------------------------------------
// Split-bf16 HMMA GEMM with ldmatrix fragment loads.
// ---------------------------------------------------------------------------
#define KBLK 64
#define SPITCH 72
#define SPB (SPITCH * 2)
#define TILE_B (128 * SPB)
#define STAGE_B (4 * TILE_B)
#define MMA_SMEM_TOTAL (2 * STAGE_B)

__global__ void __launch_bounds__(256, 1) k_mma(
    const __nv_bfloat16* __restrict__ Ah, const __nv_bfloat16* __restrict__ Al,
    const __nv_bfloat16* __restrict__ Bh, const __nv_bfloat16* __restrict__ Bl,
    int K, float* __restrict__ C, int M, int N,
    const float* __restrict__ bias, int act,
    __nv_bfloat16* __restrict__ Dh, __nv_bfloat16* __restrict__ Dl, int ldd)
{
    extern __shared__ __align__(16) char smem[];
    uint32_t sb = smem_u32(smem);
    int tid = threadIdx.x;
    int wid = tid >> 5, lane = tid & 31;
    int wm = wid & 3;
    int wn = wid >> 2;
    int m0 = blockIdx.y * 128;
    int n0 = blockIdx.x * 128;

    const __nv_bfloat16* srcs[4] = {
        Ah + (size_t)m0 * K, Al + (size_t)m0 * K,
        Bh + (size_t)n0 * K, Bl + (size_t)n0 * K };

    int lrow = tid >> 3;
    int lchk = tid & 7;

    // ldmatrix lane addressing (same mapping as k_nv, validated)
    int l7  = lane & 7;
    int s8  = (lane & 8) ? 8 : 0;
    int s16 = (lane & 16) ? 8 : 0;

    float acc[2][8][4];
#pragma unroll
    for (int i = 0; i < 2; i++)
#pragma unroll
        for (int j = 0; j < 8; j++)
#pragma unroll
            for (int q = 0; q < 4; q++) acc[i][j][q] = 0.f;

    auto load_stage = [&](int s, int kb) {
        uint32_t sd = sb + s * STAGE_B;
        size_t kOff = (size_t)kb * KBLK;
#pragma unroll
        for (int v = 0; v < 4; v++) {
            const __nv_bfloat16* g = srcs[v] + kOff;
#pragma unroll
            for (int p = 0; p < 4; p++) {
                int rr = lrow + p * 32;
                uint32_t d = sd + v * TILE_B + rr * SPB + lchk * 16;
                const void* sptr = (const char*)(g + (size_t)rr * K) + lchk * 16;
                CP_ASYNC16(d, sptr);
            }
        }
        CP_COMMIT();
    };

    load_stage(0, 0);

    int lr = lane >> 2;
    int lc = (lane & 3) * 2;
    int nkb = K / KBLK;

    for (int kb = 0; kb < nkb; kb++) {
        int s = kb & 1;
        CP_WAIT0();
        __syncthreads();
        if (kb + 1 < nkb) load_stage(s ^ 1, kb + 1);

        uint32_t sAh = sb + s * STAGE_B;
        uint32_t sAl = sAh + TILE_B;
        uint32_t sBh = sAh + 2 * TILE_B;
        uint32_t sBl = sAh + 3 * TILE_B;

#pragma unroll
        for (int ks = 0; ks < 4; ks++) {
            int kl = ks * 16;
            // A fragments: 2 mt x (hi,lo), m16k16 via ldmatrix.x4
            uint32_t ah4[2][4], al4[2][4];
#pragma unroll
            for (int mt = 0; mt < 2; mt++) {
                uint32_t aoff = (uint32_t)((wm * 32 + mt * 16 + l7 + s8) * SPB + (kl + s16) * 2);
                ldm_x4(ah4[mt], sAh + aoff);
                ldm_x4(al4[mt], sAl + aoff);
            }
            // B fragments: 4 ntp pairs x (hi,lo), two n8k16 tiles per x4
            uint32_t bh4[4][4], bl4[4][4];
#pragma unroll
            for (int ntp = 0; ntp < 4; ntp++) {
                uint32_t boff = (uint32_t)((wn * 64 + ntp * 16 + l7 + s16) * SPB + (kl + s8) * 2);
                ldm_x4(bh4[ntp], sBh + boff);
                ldm_x4(bl4[ntp], sBl + boff);
            }
#pragma unroll
            for (int mt = 0; mt < 2; mt++)
#pragma unroll
                for (int ntp = 0; ntp < 4; ntp++) {
                    mma16816(acc[mt][2 * ntp],     ah4[mt], bh4[ntp]);
                    mma16816(acc[mt][2 * ntp],     ah4[mt], bl4[ntp]);
                    mma16816(acc[mt][2 * ntp],     al4[mt], bh4[ntp]);
                    mma16816(acc[mt][2 * ntp + 1], ah4[mt], bh4[ntp] + 2);
                    mma16816(acc[mt][2 * ntp + 1], ah4[mt], bl4[ntp] + 2);
                    mma16816(acc[mt][2 * ntp + 1], al4[mt], bh4[ntp] + 2);
                }
        }
    }

    auto emit = [&](int r, int c, float v) {
        bool in = (r < M && c < N);
        float val = 0.f;
        if (in) {
            val = v + (bias ? bias[c] : 0.f);
            if (act == 1) val = fmaxf(val, 0.f);
            if (C) C[(size_t)r * N + c] = val;
        }
        if (Dh) {
            __nv_bfloat16 h = __float2bfloat16(val);
            Dh[(size_t)r * ldd + c] = h;
            Dl[(size_t)r * ldd + c] = __float2bfloat16(val - __bfloat162float(h));
        }
    };
#pragma unroll
    for (int mt = 0; mt < 2; mt++) {
#pragma unroll
        for (int nt = 0; nt < 8; nt++) {
            int r = m0 + wm * 32 + mt * 16 + lr;
            int c = n0 + wn * 64 + nt * 8 + lc;
            emit(r,     c,     acc[mt][nt][0]);
            emit(r,     c + 1, acc[mt][nt][1]);
            emit(r + 8, c,     acc[mt][nt][2]);
            emit(r + 8, c + 1, acc[mt][nt][3]);
        }
    }
}

// ---------------------------------------------------------------------------
// Small SGEMM (64x64x16) for G3.
// ---------------------------------------------------------------------------
__global__ void __launch_bounds__(256) k_sgemm(
    const float* __restrict__ A, const float* __restrict__ B,
    const float* __restrict__ bias, float* __restrict__ C,
    int M, int N, int K, int act)
{
    __shared__ __align__(16) float As[16][64];
    __shared__ __align__(16) float Bs[16][64];

    int tid = threadIdx.x;
    int tx = tid & 15, ty = tid >> 4;
    int row0 = blockIdx.y * 64, col0 = blockIdx.x * 64;

    float c[4][4];
#pragma unroll
    for (int i = 0; i < 4; i++)
#pragma unroll
        for (int j = 0; j < 4; j++) c[i][j] = 0.f;

    int am = tid >> 2;
    int ak = (tid & 3) * 4;
    int bk = tid >> 4;
    int bn = (tid & 15) * 4;

    for (int k0 = 0; k0 < K; k0 += 16) {
        int arow = row0 + am;
        if (arow < M && k0 + ak + 3 < K) {
            float4 v = *reinterpret_cast<const float4*>(&A[(size_t)arow * K + k0 + ak]);
            As[ak + 0][am] = v.x; As[ak + 1][am] = v.y;
            As[ak + 2][am] = v.z; As[ak + 3][am] = v.w;
        } else {
#pragma unroll
            for (int i = 0; i < 4; i++) {
                int kk = k0 + ak + i;
                As[ak + i][am] = (arow < M && kk < K) ? A[(size_t)arow * K + kk] : 0.f;
            }
        }
        int brow = k0 + bk;
        if (brow < K && col0 + bn + 3 < N) {
            float4 v = *reinterpret_cast<const float4*>(&B[(size_t)brow * N + col0 + bn]);
            *reinterpret_cast<float4*>(&Bs[bk][bn]) = v;
        } else {
#pragma unroll
            for (int i = 0; i < 4; i++) {
                int nn = col0 + bn + i;
                Bs[bk][bn + i] = (brow < K && nn < N) ? B[(size_t)brow * N + nn] : 0.f;
            }
        }
        __syncthreads();
#pragma unroll
        for (int kk = 0; kk < 16; kk++) {
            float4 av = *reinterpret_cast<const float4*>(&As[kk][ty * 4]);
            float4 bv = *reinterpret_cast<const float4*>(&Bs[kk][tx * 4]);
            float a[4] = {av.x, av.y, av.z, av.w};
            float bb[4] = {bv.x, bv.y, bv.z, bv.w};
#pragma unroll
            for (int i = 0; i < 4; i++)
#pragma unroll
                for (int j = 0; j < 4; j++) c[i][j] = fmaf(a[i], bb[j], c[i][j]);
        }
        __syncthreads();
    }

#pragma unroll
    for (int i = 0; i < 4; i++) {
        int r = row0 + ty * 4 + i;
        if (r >= M) continue;
#pragma unroll
        for (int j = 0; j < 4; j++) {
            int cc = col0 + tx * 4 + j;
            if (cc >= N) continue;
            float v = c[i][j];
            if (bias) v += bias[cc];
            if (act == 1) v = fmaxf(v, 0.f);
            C[(size_t)r * N + cc] = v;
        }
    }
}

// ---------------------------------------------------------------------------
// GAT kernels. k_gat_h also zeroes den/aggr for the current layer (fused init).
// ---------------------------------------------------------------------------
__global__ void __launch_bounds__(128) k_gat_h(
    const float* __restrict__ W, const float* __restrict__ a_s,
    const float* __restrict__ a_d)
{
    int b = blockIdx.x, t = threadIdx.x;
    __shared__ float xsm[NODE_D];
    __shared__ float rs[8];
    xsm[t] = g_x[b * NODE_D + t];
    g_aggr[b * NODE_D + t] = 0.f;            // fused k_init
    if (t == 0) g_den[b] = 0.f;
    __syncthreads();
    float acc = 0.f;
#pragma unroll 8
    for (int d = 0; d < NODE_D; d++) acc = fmaf(xsm[d], __ldg(&W[d * NODE_D + t]), acc);
    g_h[b * NODE_D + t] = acc;
    float ps = acc * __ldg(&a_s[t]);
    float pd = acc * __ldg(&a_d[t]);
#pragma unroll
    for (int off = 16; off; off >>= 1) {
        ps += __shfl_xor_sync(0xFFFFFFFFu, ps, off);
        pd += __shfl_xor_sync(0xFFFFFFFFu, pd, off);
    }
    if ((t & 31) == 0) { rs[t >> 5] = ps; rs[4 + (t >> 5)] = pd; }
    __syncthreads();
    if (t == 0) g_es[b] = rs[0] + rs[1] + rs[2] + rs[3];
    if (t == 1) g_ed[b] = rs[4] + rs[5] + rs[6] + rs[7];
}

__global__ void k_edge12(const int* __restrict__ ei)
{
    int e = blockIdx.x * blockDim.x + threadIdx.x;
    if (e >= E_EXT) return;
    int s, d;
    if (e < N_EDGES) { s = ei[e]; d = ei[N_EDGES + e]; }
    else { s = e - N_EDGES; d = s; }
    float v = g_es[s] + g_ed[d];
    v = (v > 0.f) ? v : 0.2f * v;
    float ex = __expf(v);
    g_ex[e] = ex;
    atomicAdd(&g_den[d], ex);
}

__global__ void k_edge3(const int* __restrict__ ei)
{
    int gt = blockIdx.x * blockDim.x + threadIdx.x;
    int w = gt >> 5, lane = gt & 31;
    if (w >= E_EXT) return;
    int s, d;
    if (w < N_EDGES) { s = ei[w]; d = ei[N_EDGES + w]; }
    else { s = w - N_EDGES; d = s; }
    float alpha = g_ex[w] / g_den[d];
#pragma unroll
    for (int i = 0; i < 4; i++) {
        int c = lane + 32 * i;
        atomicAdd(&g_aggr[d * NODE_D + c], g_h[s * NODE_D + c] * alpha);
    }
}

__global__ void k_gat_fin(const float* __restrict__ b)
{
    int i = blockIdx.x * blockDim.x + threadIdx.x;
    if (i >= N_NODES * NODE_D) return;
    float v = g_aggr[i] + __ldg(&b[i & (NODE_D - 1)]);
    g_x[i] = (v > 0.f) ? v : (__expf(v) - 1.f);
}

// ---------------------------------------------------------------------------
// Edge-attr MLP: 1 -> 8 -> 16 -> 32
// ---------------------------------------------------------------------------
__global__ void __launch_bounds__(256) k_ef(
    const float* __restrict__ ea,
    const float* __restrict__ w1, const float* __restrict__ b1,
    const float* __restrict__ w2, const float* __restrict__ b2,
    const float* __restrict__ w3, const float* __restrict__ b3)
{
    __shared__ float w1s[8], b1s[8], w2s[128], b2s[16], w3s[512], b3s[32];
    int t = threadIdx.x;
    if (t < 8)   { w1s[t] = w1[t]; b1s[t] = b1[t]; }
    if (t < 128) w2s[t] = w2[t];
    if (t < 16)  b2s[t] = b2[t];
    if (t < 32)  b3s[t] = b3[t];
    for (int i = t; i < 512; i += blockDim.x) w3s[i] = w3[i];
    __syncthreads();
    int e = blockIdx.x * blockDim.x + t;
    if (e >= N_EDGES) return;
    float a = ea[e];
    float t8[8];
#pragma unroll
    for (int j = 0; j < 8; j++) t8[j] = fmaxf(fmaf(a, w1s[j], b1s[j]), 0.f);
    float t16[16];
#pragma unroll
    for (int c = 0; c < 16; c++) {
        float acc = b2s[c];
#pragma unroll
        for (int j = 0; j < 8; j++) acc = fmaf(t8[j], w2s[j * 16 + c], acc);
        t16[c] = fmaxf(acc, 0.f);
    }
#pragma unroll
    for (int c = 0; c < 32; c++) {
        float acc = b3s[c];
#pragma unroll
        for (int j = 0; j < 16; j++) acc = fmaf(t16[j], w3s[j * 32 + c], acc);
        g_ef2[e * EDGE_D + c] = acc;
    }
}

// ---------------------------------------------------------------------------
// Final fused edge classifier.
// ---------------------------------------------------------------------------
__global__ void __launch_bounds__(128) k_final(
    const int* __restrict__ ei,
    const float* __restrict__ dp_w, const float* __restrict__ dp_b,
    const float* __restrict__ ec_w1, const float* __restrict__ ec_b1,
    const float* __restrict__ ec_w2, const float* __restrict__ ec_b2,
    float* __restrict__ out)
{
    __shared__ float dpw_s[288 * 32];
    __shared__ float ecw1_s[32 * 16];
    __shared__ float dpb_s[32];
    __shared__ float ecb1_s[16];
    __shared__ float ecw2_s[16];
    __shared__ float vec_s[4][292];
    __shared__ float o32_s[4][32];

    int tid = threadIdx.x;
    for (int i = tid; i < 288 * 32; i += 128) dpw_s[i] = dp_w[i];
    for (int i = tid; i < 512; i += 128) ecw1_s[i] = ec_w1[i];
    if (tid < 32) dpb_s[tid] = dp_b[tid];
    if (tid < 16) { ecb1_s[tid] = ec_b1[tid]; ecw2_s[tid] = ec_w2[tid]; }
    __syncthreads();

    float b2 = __ldg(ec_b2);
    int warp = tid >> 5, lane = tid & 31;
    int gw = blockIdx.x * 4 + warp;
    int nw = gridDim.x * 4;

    for (int e = gw; e < N_EDGES; e += nw) {
        int s = ei[e], d = ei[N_EDGES + e];
        const float* xsp = g_x + s * NODE_D;
        const float* xdp = g_x + d * NODE_D;
#pragma unroll
        for (int i = 0; i < 4; i++) {
            vec_s[warp][lane + 32 * i]       = xsp[lane + 32 * i];
            vec_s[warp][128 + lane + 32 * i] = xdp[lane + 32 * i];
        }
        vec_s[warp][256 + lane] = g_ef2[e * EDGE_D + lane];
        __syncwarp();

        float acc = dpb_s[lane];
#pragma unroll 4
        for (int i = 0; i < 288; i++) acc = fmaf(vec_s[warp][i], dpw_s[i * 32 + lane], acc);
        o32_s[warp][lane] = acc;
        __syncwarp();

        float hh = 0.f;
        if (lane < 16) {
            hh = ecb1_s[lane];
#pragma unroll 4
            for (int j = 0; j < 32; j++) hh = fmaf(o32_s[warp][j], ecw1_s[j * 16 + lane], hh);
            hh = fmaxf(hh, 0.f) * ecw2_s[lane];
        }
#pragma unroll
        for (int off = 8; off; off >>= 1) hh += __shfl_xor_sync(0xFFFFFFFFu, hh, off);
        if (lane == 0) out[e] = 1.f / (1.f + __expf(-(hh + b2)));
        __syncwarp();
    }
}

// ---------------------------------------------------------------------------
extern "C" void kernel_launch(void* const* d_in, const int* in_sizes, int n_in,
                              void* d_out, int out_size)
{
    (void)in_sizes; (void)n_in; (void)out_size;
    const float* node_feats = (const float*)d_in[0];
    const float* edge_attr  = (const float*)d_in[1];
    const float* nv_cw      = (const float*)d_in[2];
    const float* nv_cb      = (const float*)d_in[3];
    const float* nv_cw2     = (const float*)d_in[4];
    const float* nv_hw      = (const float*)d_in[5];
    const float* ne_w1      = (const float*)d_in[6];
    const float* ne_b1      = (const float*)d_in[7];
    const float* ne_w2      = (const float*)d_in[8];
    const float* ne_b2      = (const float*)d_in[9];
    const float* ee_w1      = (const float*)d_in[10];
    const float* ee_b1      = (const float*)d_in[11];
    const float* ee_w2      = (const float*)d_in[12];
    const float* ee_b2      = (const float*)d_in[13];
    const float* ee_w3      = (const float*)d_in[14];
    const float* ee_b3      = (const float*)d_in[15];
    const float* gat_w      = (const float*)d_in[16];
    const float* gat_as     = (const float*)d_in[17];
    const float* gat_ad     = (const float*)d_in[18];
    const float* gat_b      = (const float*)d_in[19];
    const float* dp_w       = (const float*)d_in[20];
    const float* dp_b       = (const float*)d_in[21];
    const float* ec_w1      = (const float*)d_in[22];
    const float* ec_b1      = (const float*)d_in[23];
    const float* ec_w2      = (const float*)d_in[24];
    const float* ec_b2      = (const float*)d_in[25];
    const int*   edge_index = (const int*)d_in[26];
    float* out = (float*)d_out;

    float *p_h1, *p_x;
    __nv_bfloat16 *p_Ah, *p_Al, *p_Bh, *p_Bl, *p_Ah2, *p_Al2, *p_Bh2, *p_Bl2;
    cudaGetSymbolAddress((void**)&p_h1, g_h1);
    cudaGetSymbolAddress((void**)&p_x, g_x);
    cudaGetSymbolAddress((void**)&p_Ah, g_Ah);
    cudaGetSymbolAddress((void**)&p_Al, g_Al);
    cudaGetSymbolAddress((void**)&p_Bh, g_Bh);
    cudaGetSymbolAddress((void**)&p_Bl, g_Bl);
    cudaGetSymbolAddress((void**)&p_Ah2, g_Ah2);
    cudaGetSymbolAddress((void**)&p_Al2, g_Al2);
    cudaGetSymbolAddress((void**)&p_Bh2, g_Bh2);
    cudaGetSymbolAddress((void**)&p_Bl2, g_Bl2);

    cudaFuncSetAttribute(k_mma, cudaFuncAttributeMaxDynamicSharedMemorySize, MMA_SMEM_TOTAL);
    cudaFuncSetAttribute(k_nv, cudaFuncAttributeMaxDynamicSharedMemorySize, NV_SMEM);

    // 0) prep: cw^T split + B operand conversions
    k_prep_cw<<<64, 256>>>(nv_cw);
    {
        dim3 g(VLAD_DIM / 32, N_PAD / 32);
        k_cvt_trans<<<g, 256>>>(nv_hw, H0D, VLAD_DIM, H0D, p_Bh, p_Bl, VLAD_DIM);
    }
    {
        dim3 g(K2PAD / 32, N2PAD / 32);
        k_cvt_trans<<<g, 256>>>(ne_w1, H1D, H0D, H1D, p_Bh2, p_Bl2, K2PAD);
    }

    // 1) FUSED NetVLAD -> g_Ah/g_Al
    k_nv<<<N_NODES, 256, NV_SMEM>>>(node_feats, nv_cb, nv_cw2);

    // 2) G1 HMMA: h0 = vlad @ hw -> split-bf16 A operand of G2
    {
        dim3 g(N_PAD / 128, M_PAD / 128);
        k_mma<<<g, 256, MMA_SMEM_TOTAL>>>(p_Ah, p_Al, p_Bh, p_Bl, VLAD_DIM,
                                          nullptr, N_NODES, H0D, nullptr, 0,
                                          p_Ah2, p_Al2, K2PAD);
    }
    // 3) G2 HMMA: h1 = relu(h0 @ ne_w1 + b1)
    {
        dim3 g(N2PAD / 128, M_PAD / 128);
        k_mma<<<g, 256, MMA_SMEM_TOTAL>>>(p_Ah2, p_Al2, p_Bh2, p_Bl2, K2PAD,
                                          p_h1, N_NODES, H1D, ne_b1, 1,
                                          nullptr, nullptr, 0);
    }
    // 4) G3: x = h1 @ ne_w2 + b2
    {
        dim3 g((NODE_D + 63) / 64, (N_NODES + 63) / 64);
        k_sgemm<<<g, 256>>>(p_h1, ne_w2, ne_b2, p_x, N_NODES, NODE_D, H1D, 0);
    }

    // 5) edge-attr MLP
    k_ef<<<(N_EDGES + 255) / 256, 256>>>(edge_attr, ee_w1, ee_b1, ee_w2, ee_b2, ee_w3, ee_b3);

    // 6) 3 GAT layers (init fused into k_gat_h)
    for (int l = 0; l < DEPTH; l++) {
        k_gat_h<<<N_NODES, 128>>>(gat_w + l * NODE_D * NODE_D,
                                  gat_as + l * NODE_D, gat_ad + l * NODE_D);
        k_edge12<<<(E_EXT + 255) / 256, 256>>>(edge_index);
        k_edge3<<<((E_EXT * 32) + 255) / 256, 256>>>(edge_index);
        k_gat_fin<<<(N_NODES * NODE_D + 255) / 256, 256>>>(gat_b + l * NODE_D);
    }

    // 7) fused edge classifier -> out
    k_final<<<512, 128>>>(edge_index, dp_w, dp_b, ec_w1, ec_b1, ec_w2, ec_b2, out);
}

// round 11
// speedup vs baseline: 4.9580x; 1.1395x over previous
#include <cuda_runtime.h>
#include <cuda_bf16.h>
#include <math.h>
#include <stdint.h>

#define N_NODES 2000
#define NUM_KP 500
#define DESC 256
#define NVK 64
#define VLAD_DIM (DESC*NVK)        // 16384
#define H0D (NUM_KP*2)             // 1000
#define H1D NUM_KP                 // 500
#define NODE_D 128
#define EDGE_D 32
#define N_EDGES 64000
#define E_EXT (N_EDGES + N_NODES)  // 66000
#define DEPTH 3

#define M_PAD 2048
#define N_PAD 1024
#define K2PAD 1024
#define N2PAD 512

typedef unsigned long long u64;

// ---------------- scratch (device globals; no runtime allocation) ----------
__device__ float    g_h1[N_NODES * H1D];
__device__ float    g_x[N_NODES * NODE_D];
__device__ float    g_h[N_NODES * NODE_D];
__device__ float    g_es[N_NODES];
__device__ float    g_ed[N_NODES];
__device__ float    g_ex[E_EXT];
__device__ float    g_den[N_NODES];
__device__ float    g_aggr[N_NODES * NODE_D];
__device__ float    g_ef2[N_EDGES * EDGE_D];
// split-bf16 operands (pad regions stay zero: static zero-init, never written)
__device__ __nv_bfloat16 g_Ah[(size_t)M_PAD * VLAD_DIM];
__device__ __nv_bfloat16 g_Al[(size_t)M_PAD * VLAD_DIM];
__device__ __nv_bfloat16 g_Bh[(size_t)N_PAD * VLAD_DIM];
__device__ __nv_bfloat16 g_Bl[(size_t)N_PAD * VLAD_DIM];
__device__ __nv_bfloat16 g_Ah2[(size_t)M_PAD * K2PAD];
__device__ __nv_bfloat16 g_Al2[(size_t)M_PAD * K2PAD];
__device__ __nv_bfloat16 g_Bh2[(size_t)N2PAD * K2PAD];
__device__ __nv_bfloat16 g_Bl2[(size_t)N2PAD * K2PAD];
__device__ __nv_bfloat16 g_cwTh[NVK * DESC];
__device__ __nv_bfloat16 g_cwTl[NVK * DESC];

// ---------------- helpers ---------------------------------------------------
__device__ __forceinline__ uint32_t smem_u32(const void* p) {
    uint32_t a;
    asm("{ .reg .u64 t; cvta.to.shared.u64 t, %1; cvt.u32.u64 %0, t; }" : "=r"(a) : "l"(p));
    return a;
}
__device__ __forceinline__ uint32_t lds32(uint32_t addr) {
    uint32_t v;
    asm volatile("ld.shared.b32 %0, [%1];" : "=r"(v) : "r"(addr));
    return v;
}
__device__ __forceinline__ void ldm_x4(uint32_t* r, uint32_t addr) {
    asm volatile("ldmatrix.sync.aligned.m8n8.x4.shared.b16 {%0,%1,%2,%3}, [%4];"
        : "=r"(r[0]), "=r"(r[1]), "=r"(r[2]), "=r"(r[3]) : "r"(addr));
}
__device__ __forceinline__ void ldm_x4_t(uint32_t* r, uint32_t addr) {
    asm volatile("ldmatrix.sync.aligned.m8n8.x4.trans.shared.b16 {%0,%1,%2,%3}, [%4];"
        : "=r"(r[0]), "=r"(r[1]), "=r"(r[2]), "=r"(r[3]) : "r"(addr));
}
__device__ __forceinline__ void mma16816(float* c, const uint32_t* a, const uint32_t* b) {
    asm volatile(
        "mma.sync.aligned.m16n8k16.row.col.f32.bf16.bf16.f32 "
        "{%0,%1,%2,%3}, {%4,%5,%6,%7}, {%8,%9}, {%0,%1,%2,%3};"
        : "+f"(c[0]), "+f"(c[1]), "+f"(c[2]), "+f"(c[3])
        : "r"(a[0]), "r"(a[1]), "r"(a[2]), "r"(a[3]), "r"(b[0]), "r"(b[1]));
}
#define CP_ASYNC16(dst, src) \
    asm volatile("cp.async.cg.shared.global [%0], [%1], 16;" :: "r"(dst), "l"(src) : "memory")
#define CP_COMMIT()  asm volatile("cp.async.commit_group;" ::: "memory")
#define CP_WAIT0()   asm volatile("cp.async.wait_group 0;" ::: "memory")

__device__ __forceinline__ float sanit(float v) {
    if (!isfinite(v)) v = (v != v) ? 0.f : (v > 0.f ? 3.402823466e38f : -3.402823466e38f);
    return v;
}

// ---------------------------------------------------------------------------
// Prep: cw [256][64] fp32 -> cw^T split-bf16 [64][256]
// ---------------------------------------------------------------------------
__global__ void k_prep_cw(const float* __restrict__ cw)
{
    int i = blockIdx.x * 256 + threadIdx.x;    // 0..16383
    int k = i >> 8, d = i & 255;
    float v = cw[d * 64 + k];
    __nv_bfloat16 h = __float2bfloat16(v);
    g_cwTh[k * 256 + d] = h;
    g_cwTl[k * 256 + d] = __float2bfloat16(v - __bfloat162float(h));
}

// ---------------------------------------------------------------------------
// FUSED NetVLAD with ldmatrix fragment loads + cp.async x staging pipeline.
// Single fp32 staging buffer: consumed entirely in the conversion phase, then
// refilled (for kb+1) right after — the copy overlaps the GEMM phase.
// ---------------------------------------------------------------------------
#define O_CWH 0          // cwT hi [64 k][264 d] bf16 (pitch 528B), 33792B
#define O_CWL 33792
#define O_XH  67584      // x hi [64 n][264 d], 33792B
#define O_XL  101376
#define O_LOG 135168     // logits [64][68] f32 (17408B); reused as actT after
#define O_ACTH 135168    // actT hi [64 k][72 n] bf16 pitch 144B (9216B)
#define O_ACTL 144384
#define O_RED 153600     // [8][64] f32 (2048B)
#define O_ASUM 155648    // [64] f32
#define O_REDK 155904    // [64][4] f32
#define O_INVK 156928    // [64] f32
#define O_INVT 157184
#define O_XF  157200     // fp32 x staging [64 n][256 d] = 65536B
#define NV_SMEM 222736

__global__ void __launch_bounds__(256, 1) k_nv(
    const float* __restrict__ feats, const float* __restrict__ cb,
    const float* __restrict__ cw2)
{
    extern __shared__ __align__(16) char sm[];
    int b = blockIdx.x;
    int tid = threadIdx.x, lane = tid & 31, wid = tid >> 5;
    int wm = wid & 3, wn = wid >> 2;
    int lr = lane >> 2, lc = (lane & 3) * 2;

    uint32_t cwh_s = smem_u32(sm + O_CWH), cwl_s = smem_u32(sm + O_CWL);
    uint32_t xh_s  = smem_u32(sm + O_XH),  xl_s  = smem_u32(sm + O_XL);
    uint32_t ah_s  = smem_u32(sm + O_ACTH), al_s = smem_u32(sm + O_ACTL);
    uint32_t xf_s  = smem_u32(sm + O_XF);
    float* logit = (float*)(sm + O_LOG);
    float* red   = (float*)(sm + O_RED);
    float* asums = (float*)(sm + O_ASUM);
    float* redk  = (float*)(sm + O_REDK);
    float* invk  = (float*)(sm + O_INVK);
    float* invts = (float*)(sm + O_INVT);
    const float* xf = (const float*)(sm + O_XF);

    int l7  = lane & 7;
    int s8  = (lane & 8) ? 8 : 0;
    int s16 = (lane & 16) ? 8 : 0;
    int rowA_log = wm * 16 + l7 + s8;
    int rowB_nt  = l7 + s16;
    int rowX_n   = l7 + s16;

    // issue cp.async for x block kbi into the fp32 staging buffer
    auto issue_xf = [&](int kbi) {
        int n0 = kbi * 64;
#pragma unroll
        for (int p = 0; p < 16; p++) {
            int idx = tid + p * 256;      // 0..4095 16B-chunks
            int row = idx >> 6;           // 64 chunks per 1024B row
            int c16 = idx & 63;
            int gn = n0 + row;
            if (gn < NUM_KP) {
                uint32_t d = xf_s + (uint32_t)(row * 1024 + c16 * 16);
                const char* src = (const char*)(feats + ((size_t)b * NUM_KP + gn) * DESC) + c16 * 16;
                CP_ASYNC16(d, src);
            }
        }
        CP_COMMIT();
    };

    for (int i = tid; i < 2048; i += 256) {
        int k = i >> 5, c = i & 31;
        *(uint4*)(sm + O_CWH + k * 528 + c * 16) = ((const uint4*)g_cwTh)[i];
        *(uint4*)(sm + O_CWL + k * 528 + c * 16) = ((const uint4*)g_cwTl)[i];
    }
    issue_xf(0);   // prologue

    float accv[4][4][4];
#pragma unroll
    for (int mt = 0; mt < 4; mt++)
#pragma unroll
        for (int nt = 0; nt < 4; nt++)
#pragma unroll
            for (int q = 0; q < 4; q++) accv[mt][nt][q] = 0.f;
    float s0 = 0.f, s1 = 0.f;
    float cb0 = cb[lane], cb1 = cb[lane + 32];

    for (int kb = 0; kb < 8; kb++) {
        CP_WAIT0();
        __syncthreads();                 // staging buffer ready; prior GEMM done
        int n0 = kb * 64;
        // ---- convert fp32 staging -> split-bf16 row-major x tile ----
        for (int i = tid; i < 4096; i += 256) {
            int row = i >> 6, c4 = i & 63;
            int gn = n0 + row;
            float4 v = make_float4(0.f, 0.f, 0.f, 0.f);
            if (gn < NUM_KP) v = *(const float4*)(xf + row * 256 + c4 * 4);
            float vv[4] = { sanit(v.x), sanit(v.y), sanit(v.z), sanit(v.w) };
            __nv_bfloat16 hh[4], ll[4];
#pragma unroll
            for (int j = 0; j < 4; j++) {
                hh[j] = __float2bfloat16(vv[j]);
                ll[j] = __float2bfloat16(vv[j] - __bfloat162float(hh[j]));
            }
            char* pxh = sm + O_XH + row * 528 + c4 * 8;
            char* pxl = sm + O_XL + row * 528 + c4 * 8;
            *(__nv_bfloat162*)pxh       = __nv_bfloat162(hh[0], hh[1]);
            *(__nv_bfloat162*)(pxh + 4) = __nv_bfloat162(hh[2], hh[3]);
            *(__nv_bfloat162*)pxl       = __nv_bfloat162(ll[0], ll[1]);
            *(__nv_bfloat162*)(pxl + 4) = __nv_bfloat162(ll[2], ll[3]);
        }
        __syncthreads();                 // conversion done (staging fully read)
        if (kb + 1 < 8) issue_xf(kb + 1);  // refill overlaps the GEMM phase

        // ---- logits GEMM ----
        float acc[4][4];
#pragma unroll
        for (int nt = 0; nt < 4; nt++)
#pragma unroll
            for (int q = 0; q < 4; q++) acc[nt][q] = 0.f;
#pragma unroll
        for (int ks = 0; ks < 16; ks++) {
            int kl = ks * 16;
            uint32_t aoff = (uint32_t)(rowA_log * 528 + (kl + s16) * 2);
            uint32_t a[4], al_[4];
            ldm_x4(a,  xh_s + aoff);
            ldm_x4(al_, xl_s + aoff);
#pragma unroll
            for (int ntp = 0; ntp < 2; ntp++) {
                uint32_t boff = (uint32_t)((wn * 32 + ntp * 16 + rowB_nt) * 528 + (kl + s8) * 2);
                uint32_t bh4[4], bl4[4];
                ldm_x4(bh4, cwh_s + boff);
                ldm_x4(bl4, cwl_s + boff);
                mma16816(acc[2 * ntp],     a,   bh4);
                mma16816(acc[2 * ntp],     a,   bl4);
                mma16816(acc[2 * ntp],     al_, bh4);
                mma16816(acc[2 * ntp + 1], a,   bh4 + 2);
                mma16816(acc[2 * ntp + 1], a,   bl4 + 2);
                mma16816(acc[2 * ntp + 1], al_, bh4 + 2);
            }
        }
#pragma unroll
        for (int nt = 0; nt < 4; nt++)
#pragma unroll
            for (int q = 0; q < 4; q++) {
                int row = wm * 16 + lr + ((q >> 1) * 8);
                int col = wn * 32 + nt * 8 + lc + (q & 1);
                logit[row * 68 + col] = acc[nt][q];
            }
        __syncthreads();

        // ---- softmax ----
        float l0r[8], l1r[8];
#pragma unroll
        for (int rr = 0; rr < 8; rr++) {
            int row = wid * 8 + rr;
            l0r[rr] = logit[row * 68 + lane] + cb0;
            l1r[rr] = logit[row * 68 + lane + 32] + cb1;
        }
        __syncthreads();
#pragma unroll
        for (int rr = 0; rr < 8; rr++) {
            int row = wid * 8 + rr;
            int gn = n0 + row;
            float m = fmaxf(l0r[rr], l1r[rr]);
#pragma unroll
            for (int off = 16; off; off >>= 1) m = fmaxf(m, __shfl_xor_sync(0xFFFFFFFFu, m, off));
            float e0 = __expf(l0r[rr] - m), e1 = __expf(l1r[rr] - m);
            float ss = e0 + e1;
#pragma unroll
            for (int off = 16; off; off >>= 1) ss += __shfl_xor_sync(0xFFFFFFFFu, ss, off);
            float inv = 1.f / ss;
            if (gn < NUM_KP) { e0 *= inv; e1 *= inv; s0 += e0; s1 += e1; }
            else             { e0 = 0.f;  e1 = 0.f; }
            __nv_bfloat16 h0 = __float2bfloat16(e0);
            __nv_bfloat16 h1 = __float2bfloat16(e1);
            *(__nv_bfloat16*)(sm + O_ACTH + lane * 144 + row * 2)        = h0;
            *(__nv_bfloat16*)(sm + O_ACTH + (lane + 32) * 144 + row * 2) = h1;
            *(__nv_bfloat16*)(sm + O_ACTL + lane * 144 + row * 2) =
                __float2bfloat16(e0 - __bfloat162float(h0));
            *(__nv_bfloat16*)(sm + O_ACTL + (lane + 32) * 144 + row * 2) =
                __float2bfloat16(e1 - __bfloat162float(h1));
        }
        __syncthreads();

        // ---- vlad GEMM ----
#pragma unroll
        for (int ks = 0; ks < 4; ks++) {
            int kl = ks * 16;
            uint32_t bh4[2][4], bl4[2][4];
#pragma unroll
            for (int ntp = 0; ntp < 2; ntp++) {
                uint32_t boff = (uint32_t)((wn * 32 + ntp * 16 + rowB_nt) * 144 + (kl + s8) * 2);
                ldm_x4(bh4[ntp], ah_s + boff);
                ldm_x4(bl4[ntp], al_s + boff);
            }
#pragma unroll
            for (int mt = 0; mt < 4; mt++) {
                uint32_t aoff = (uint32_t)((kl + rowX_n) * 528 + (wm * 64 + mt * 16 + s8) * 2);
                uint32_t a[4], al2[4];
                ldm_x4_t(a,   xh_s + aoff);
                ldm_x4_t(al2, xl_s + aoff);
#pragma unroll
                for (int ntp = 0; ntp < 2; ntp++) {
                    mma16816(accv[mt][2 * ntp],     a,   bh4[ntp]);
                    mma16816(accv[mt][2 * ntp],     a,   bl4[ntp]);
                    mma16816(accv[mt][2 * ntp],     al2, bh4[ntp]);
                    mma16816(accv[mt][2 * ntp + 1], a,   bh4[ntp] + 2);
                    mma16816(accv[mt][2 * ntp + 1], a,   bl4[ntp] + 2);
                    mma16816(accv[mt][2 * ntp + 1], al2, bh4[ntp] + 2);
                }
            }
        }
    }

    // ---- asum reduce + cw2 load ----
    red[wid * 64 + lane]      = s0;
    red[wid * 64 + lane + 32] = s1;
    __syncthreads();
    if (tid < 32) {
        float t0 = 0.f, t1 = 0.f;
#pragma unroll
        for (int w = 0; w < 8; w++) { t0 += red[w * 64 + lane]; t1 += red[w * 64 + lane + 32]; }
        asums[lane] = t0; asums[lane + 32] = t1;
    }
    float* cw2s = (float*)(sm + O_XH);
    for (int i = tid; i < 4096; i += 256)
        ((float4*)cw2s)[i] = ((const float4*)cw2)[i];
    __syncthreads();

#pragma unroll
    for (int mt = 0; mt < 4; mt++)
#pragma unroll
        for (int nt = 0; nt < 4; nt++)
#pragma unroll
            for (int q = 0; q < 4; q++) {
                int d = wm * 64 + mt * 16 + lr + ((q >> 1) * 8);
                int k = wn * 32 + nt * 8 + lc + (q & 1);
                accv[mt][nt][q] -= asums[k] * cw2s[d * 64 + k];
            }
#pragma unroll
    for (int nt = 0; nt < 4; nt++) {
        float sq0 = 0.f, sq1 = 0.f;
#pragma unroll
        for (int mt = 0; mt < 4; mt++) {
            sq0 += accv[mt][nt][0] * accv[mt][nt][0] + accv[mt][nt][2] * accv[mt][nt][2];
            sq1 += accv[mt][nt][1] * accv[mt][nt][1] + accv[mt][nt][3] * accv[mt][nt][3];
        }
        sq0 += __shfl_xor_sync(0xFFFFFFFFu, sq0, 4);
        sq0 += __shfl_xor_sync(0xFFFFFFFFu, sq0, 8);
        sq0 += __shfl_xor_sync(0xFFFFFFFFu, sq0, 16);
        sq1 += __shfl_xor_sync(0xFFFFFFFFu, sq1, 4);
        sq1 += __shfl_xor_sync(0xFFFFFFFFu, sq1, 8);
        sq1 += __shfl_xor_sync(0xFFFFFFFFu, sq1, 16);
        if (lr == 0) {
            int k0 = wn * 32 + nt * 8 + lc;
            redk[k0 * 4 + wm]       = sq0;
            redk[(k0 + 1) * 4 + wm] = sq1;
        }
    }
    __syncthreads();
    if (tid < 32) {
        float q0 = redk[lane * 4] + redk[lane * 4 + 1] + redk[lane * 4 + 2] + redk[lane * 4 + 3];
        int l2 = lane + 32;
        float q1 = redk[l2 * 4] + redk[l2 * 4 + 1] + redk[l2 * 4 + 2] + redk[l2 * 4 + 3];
        float i0 = 1.f / (sqrtf(q0) + 1e-12f);
        float i1 = 1.f / (sqrtf(q1) + 1e-12f);
        invk[lane] = i0; invk[l2] = i1;
        float tt = q0 * i0 * i0 + q1 * i1 * i1;
#pragma unroll
        for (int off = 16; off; off >>= 1) tt += __shfl_xor_sync(0xFFFFFFFFu, tt, off);
        if (lane == 0) invts[0] = 1.f / (sqrtf(tt) + 1e-12f);
    }
    __syncthreads();
    float invt = invts[0];

#pragma unroll
    for (int mt = 0; mt < 4; mt++)
#pragma unroll
        for (int nt = 0; nt < 4; nt++)
#pragma unroll
            for (int q = 0; q < 4; q++) {
                int d = wm * 64 + mt * 16 + lr + ((q >> 1) * 8);
                int k = wn * 32 + nt * 8 + lc + (q & 1);
                float val = accv[mt][nt][q] * invk[k] * invt;
                __nv_bfloat16 h = __float2bfloat16(val);
                *(__nv_bfloat16*)(sm + O_XH + (d * 66 + k) * 2) = h;
                *(__nv_bfloat16*)(sm + O_XL + (d * 66 + k) * 2) =
                    __float2bfloat16(val - __bfloat162float(h));
            }
    __syncthreads();
    for (int i = tid; i < 8192; i += 256) {
        int d = i >> 5, kp = i & 31;
        uint32_t vh = lds32(xh_s + (uint32_t)(d * 66 + kp * 2) * 2);
        uint32_t vl = lds32(xl_s + (uint32_t)(d * 66 + kp * 2) * 2);
        size_t go = (size_t)b * VLAD_DIM + d * 64 + kp * 2;
        *(uint32_t*)((char*)g_Ah + go * 2) = vh;
        *(uint32_t*)((char*)g_Al + go * 2) = vl;
    }
}

// ---------------------------------------------------------------------------
// Transpose + split: src[k][n] fp32 -> dh/dl[n][k] bf16 (pads zero-filled).
// ---------------------------------------------------------------------------
__global__ void __launch_bounds__(256) k_cvt_trans(
    const float* __restrict__ src, int ldsrc, int Kreal, int Nreal,
    __nv_bfloat16* __restrict__ dh, __nv_bfloat16* __restrict__ dl, int ldd)
{
    __shared__ float smt[32][33];
    int k0 = blockIdx.x * 32;
    int n0 = blockIdx.y * 32;
    int tx = threadIdx.x & 31;
    int ty = threadIdx.x >> 5;
#pragma unroll
    for (int i = 0; i < 4; i++) {
        int kk = ty + i * 8;
        int n = n0 + tx;
        float v = (k0 + kk < Kreal && n < Nreal) ? src[(size_t)(k0 + kk) * ldsrc + n] : 0.f;
        smt[kk][tx] = v;
    }
    __syncthreads();
#pragma unroll
    for (int i = 0; i < 4; i++) {
        int nn = ty + i * 8;
        float v = smt[tx][nn];
        __nv_bfloat16 h = __float2bfloat16(v);
        __nv_bfloat16 l = __float2bfloat16(v - __bfloat162float(h));
        size_t o = (size_t)(n0 + nn) * ldd + k0 + tx;
        dh[o] = h;
        dl[o] = l;
    }
}

// ---------------------------------------------------------------------------
// Split-bf16 HMMA GEMM with ldmatrix fragment loads (R10, passing).
// ---------------------------------------------------------------------------
#define KBLK 64
#define SPITCH 72
#define SPB (SPITCH * 2)
#define TILE_B (128 * SPB)
#define STAGE_B (4 * TILE_B)
#define MMA_SMEM_TOTAL (2 * STAGE_B)

__global__ void __launch_bounds__(256, 1) k_mma(
    const __nv_bfloat16* __restrict__ Ah, const __nv_bfloat16* __restrict__ Al,
    const __nv_bfloat16* __restrict__ Bh, const __nv_bfloat16* __restrict__ Bl,
    int K, float* __restrict__ C, int M, int N,
    const float* __restrict__ bias, int act,
    __nv_bfloat16* __restrict__ Dh, __nv_bfloat16* __restrict__ Dl, int ldd)
{
    extern __shared__ __align__(16) char smem[];
    uint32_t sb = smem_u32(smem);
    int tid = threadIdx.x;
    int wid = tid >> 5, lane = tid & 31;
    int wm = wid & 3;
    int wn = wid >> 2;
    int m0 = blockIdx.y * 128;
    int n0 = blockIdx.x * 128;

    const __nv_bfloat16* srcs[4] = {
        Ah + (size_t)m0 * K, Al + (size_t)m0 * K,
        Bh + (size_t)n0 * K, Bl + (size_t)n0 * K };

    int lrow = tid >> 3;
    int lchk = tid & 7;

    int l7  = lane & 7;
    int s8  = (lane & 8) ? 8 : 0;
    int s16 = (lane & 16) ? 8 : 0;

    float acc[2][8][4];
#pragma unroll
    for (int i = 0; i < 2; i++)
#pragma unroll
        for (int j = 0; j < 8; j++)
#pragma unroll
            for (int q = 0; q < 4; q++) acc[i][j][q] = 0.f;

    auto load_stage = [&](int s, int kb) {
        uint32_t sd = sb + s * STAGE_B;
        size_t kOff = (size_t)kb * KBLK;
#pragma unroll
        for (int v = 0; v < 4; v++) {
            const __nv_bfloat16* g = srcs[v] + kOff;
#pragma unroll
            for (int p = 0; p < 4; p++) {
                int rr = lrow + p * 32;
                uint32_t d = sd + v * TILE_B + rr * SPB + lchk * 16;
                const void* sptr = (const char*)(g + (size_t)rr * K) + lchk * 16;
                CP_ASYNC16(d, sptr);
            }
        }
        CP_COMMIT();
    };

    load_stage(0, 0);

    int lr = lane >> 2;
    int lc = (lane & 3) * 2;
    int nkb = K / KBLK;

    for (int kb = 0; kb < nkb; kb++) {
        int s = kb & 1;
        CP_WAIT0();
        __syncthreads();
        if (kb + 1 < nkb) load_stage(s ^ 1, kb + 1);

        uint32_t sAh = sb + s * STAGE_B;
        uint32_t sAl = sAh + TILE_B;
        uint32_t sBh = sAh + 2 * TILE_B;
        uint32_t sBl = sAh + 3 * TILE_B;

#pragma unroll
        for (int ks = 0; ks < 4; ks++) {
            int kl = ks * 16;
            uint32_t ah4[2][4], al4[2][4];
#pragma unroll
            for (int mt = 0; mt < 2; mt++) {
                uint32_t aoff = (uint32_t)((wm * 32 + mt * 16 + l7 + s8) * SPB + (kl + s16) * 2);
                ldm_x4(ah4[mt], sAh + aoff);
                ldm_x4(al4[mt], sAl + aoff);
            }
            uint32_t bh4[4][4], bl4[4][4];
#pragma unroll
            for (int ntp = 0; ntp < 4; ntp++) {
                uint32_t boff = (uint32_t)((wn * 64 + ntp * 16 + l7 + s16) * SPB + (kl + s8) * 2);
                ldm_x4(bh4[ntp], sBh + boff);
                ldm_x4(bl4[ntp], sBl + boff);
            }
#pragma unroll
            for (int mt = 0; mt < 2; mt++)
#pragma unroll
                for (int ntp = 0; ntp < 4; ntp++) {
                    mma16816(acc[mt][2 * ntp],     ah4[mt], bh4[ntp]);
                    mma16816(acc[mt][2 * ntp],     ah4[mt], bl4[ntp]);
                    mma16816(acc[mt][2 * ntp],     al4[mt], bh4[ntp]);
                    mma16816(acc[mt][2 * ntp + 1], ah4[mt], bh4[ntp] + 2);
                    mma16816(acc[mt][2 * ntp + 1], ah4[mt], bl4[ntp] + 2);
                    mma16816(acc[mt][2 * ntp + 1], al4[mt], bh4[ntp] + 2);
                }
        }
    }

    auto emit = [&](int r, int c, float v) {
        bool in = (r < M && c < N);
        float val = 0.f;
        if (in) {
            val = v + (bias ? bias[c] : 0.f);
            if (act == 1) val = fmaxf(val, 0.f);
            if (C) C[(size_t)r * N + c] = val;
        }
        if (Dh) {
            __nv_bfloat16 h = __float2bfloat16(val);
            Dh[(size_t)r * ldd + c] = h;
            Dl[(size_t)r * ldd + c] = __float2bfloat16(val - __bfloat162float(h));
        }
    };
#pragma unroll
    for (int mt = 0; mt < 2; mt++) {
#pragma unroll
        for (int nt = 0; nt < 8; nt++) {
            int r = m0 + wm * 32 + mt * 16 + lr;
            int c = n0 + wn * 64 + nt * 8 + lc;
            emit(r,     c,     acc[mt][nt][0]);
            emit(r,     c + 1, acc[mt][nt][1]);
            emit(r + 8, c,     acc[mt][nt][2]);
            emit(r + 8, c + 1, acc[mt][nt][3]);
        }
    }
}

// ---------------------------------------------------------------------------
// Small SGEMM (64x64x16) for G3.
// ---------------------------------------------------------------------------
__global__ void __launch_bounds__(256) k_sgemm(
    const float* __restrict__ A, const float* __restrict__ B,
    const float* __restrict__ bias, float* __restrict__ C,
    int M, int N, int K, int act)
{
    __shared__ __align__(16) float As[16][64];
    __shared__ __align__(16) float Bs[16][64];

    int tid = threadIdx.x;
    int tx = tid & 15, ty = tid >> 4;
    int row0 = blockIdx.y * 64, col0 = blockIdx.x * 64;

    float c[4][4];
#pragma unroll
    for (int i = 0; i < 4; i++)
#pragma unroll
        for (int j = 0; j < 4; j++) c[i][j] = 0.f;

    int am = tid >> 2;
    int ak = (tid & 3) * 4;
    int bk = tid >> 4;
    int bn = (tid & 15) * 4;

    for (int k0 = 0; k0 < K; k0 += 16) {
        int arow = row0 + am;
        if (arow < M && k0 + ak + 3 < K) {
            float4 v = *reinterpret_cast<const float4*>(&A[(size_t)arow * K + k0 + ak]);
            As[ak + 0][am] = v.x; As[ak + 1][am] = v.y;
            As[ak + 2][am] = v.z; As[ak + 3][am] = v.w;
        } else {
#pragma unroll
            for (int i = 0; i < 4; i++) {
                int kk = k0 + ak + i;
                As[ak + i][am] = (arow < M && kk < K) ? A[(size_t)arow * K + kk] : 0.f;
            }
        }
        int brow = k0 + bk;
        if (brow < K && col0 + bn + 3 < N) {
            float4 v = *reinterpret_cast<const float4*>(&B[(size_t)brow * N + col0 + bn]);
            *reinterpret_cast<float4*>(&Bs[bk][bn]) = v;
        } else {
#pragma unroll
            for (int i = 0; i < 4; i++) {
                int nn = col0 + bn + i;
                Bs[bk][bn + i] = (brow < K && nn < N) ? B[(size_t)brow * N + nn] : 0.f;
            }
        }
        __syncthreads();
#pragma unroll
        for (int kk = 0; kk < 16; kk++) {
            float4 av = *reinterpret_cast<const float4*>(&As[kk][ty * 4]);
            float4 bv = *reinterpret_cast<const float4*>(&Bs[kk][tx * 4]);
            float a[4] = {av.x, av.y, av.z, av.w};
            float bb[4] = {bv.x, bv.y, bv.z, bv.w};
#pragma unroll
            for (int i = 0; i < 4; i++)
#pragma unroll
                for (int j = 0; j < 4; j++) c[i][j] = fmaf(a[i], bb[j], c[i][j]);
        }
        __syncthreads();
    }

#pragma unroll
    for (int i = 0; i < 4; i++) {
        int r = row0 + ty * 4 + i;
        if (r >= M) continue;
#pragma unroll
        for (int j = 0; j < 4; j++) {
            int cc = col0 + tx * 4 + j;
            if (cc >= N) continue;
            float v = c[i][j];
            if (bias) v += bias[cc];
            if (act == 1) v = fmaxf(v, 0.f);
            C[(size_t)r * N + cc] = v;
        }
    }
}

// ---------------------------------------------------------------------------
// GAT kernels. k_gat_h also zeroes den/aggr for the current layer.
// ---------------------------------------------------------------------------
__global__ void __launch_bounds__(128) k_gat_h(
    const float* __restrict__ W, const float* __restrict__ a_s,
    const float* __restrict__ a_d)
{
    int b = blockIdx.x, t = threadIdx.x;
    __shared__ float xsm[NODE_D];
    __shared__ float rs[8];
    xsm[t] = g_x[b * NODE_D + t];
    g_aggr[b * NODE_D + t] = 0.f;
    if (t == 0) g_den[b] = 0.f;
    __syncthreads();
    float acc = 0.f;
#pragma unroll 8
    for (int d = 0; d < NODE_D; d++) acc = fmaf(xsm[d], __ldg(&W[d * NODE_D + t]), acc);
    g_h[b * NODE_D + t] = acc;
    float ps = acc * __ldg(&a_s[t]);
    float pd = acc * __ldg(&a_d[t]);
#pragma unroll
    for (int off = 16; off; off >>= 1) {
        ps += __shfl_xor_sync(0xFFFFFFFFu, ps, off);
        pd += __shfl_xor_sync(0xFFFFFFFFu, pd, off);
    }
    if ((t & 31) == 0) { rs[t >> 5] = ps; rs[4 + (t >> 5)] = pd; }
    __syncthreads();
    if (t == 0) g_es[b] = rs[0] + rs[1] + rs[2] + rs[3];
    if (t == 1) g_ed[b] = rs[4] + rs[5] + rs[6] + rs[7];
}

__global__ void k_edge12(const int* __restrict__ ei)
{
    int e = blockIdx.x * blockDim.x + threadIdx.x;
    if (e >= E_EXT) return;
    int s, d;
    if (e < N_EDGES) { s = ei[e]; d = ei[N_EDGES + e]; }
    else { s = e - N_EDGES; d = s; }
    float v = g_es[s] + g_ed[d];
    v = (v > 0.f) ? v : 0.2f * v;
    float ex = __expf(v);
    g_ex[e] = ex;
    atomicAdd(&g_den[d], ex);
}

__global__ void k_edge3(const int* __restrict__ ei)
{
    int gt = blockIdx.x * blockDim.x + threadIdx.x;
    int w = gt >> 5, lane = gt & 31;
    if (w >= E_EXT) return;
    int s, d;
    if (w < N_EDGES) { s = ei[w]; d = ei[N_EDGES + w]; }
    else { s = w - N_EDGES; d = s; }
    float alpha = g_ex[w] / g_den[d];
#pragma unroll
    for (int i = 0; i < 4; i++) {
        int c = lane + 32 * i;
        atomicAdd(&g_aggr[d * NODE_D + c], g_h[s * NODE_D + c] * alpha);
    }
}

__global__ void k_gat_fin(const float* __restrict__ b)
{
    int i = blockIdx.x * blockDim.x + threadIdx.x;
    if (i >= N_NODES * NODE_D) return;
    float v = g_aggr[i] + __ldg(&b[i & (NODE_D - 1)]);
    g_x[i] = (v > 0.f) ? v : (__expf(v) - 1.f);
}

// ---------------------------------------------------------------------------
// Edge-attr MLP: 1 -> 8 -> 16 -> 32
// ---------------------------------------------------------------------------
__global__ void __launch_bounds__(256) k_ef(
    const float* __restrict__ ea,
    const float* __restrict__ w1, const float* __restrict__ b1,
    const float* __restrict__ w2, const float* __restrict__ b2,
    const float* __restrict__ w3, const float* __restrict__ b3)
{
    __shared__ float w1s[8], b1s[8], w2s[128], b2s[16], w3s[512], b3s[32];
    int t = threadIdx.x;
    if (t < 8)   { w1s[t] = w1[t]; b1s[t] = b1[t]; }
    if (t < 128) w2s[t] = w2[t];
    if (t < 16)  b2s[t] = b2[t];
    if (t < 32)  b3s[t] = b3[t];
    for (int i = t; i < 512; i += blockDim.x) w3s[i] = w3[i];
    __syncthreads();
    int e = blockIdx.x * blockDim.x + t;
    if (e >= N_EDGES) return;
    float a = ea[e];
    float t8[8];
#pragma unroll
    for (int j = 0; j < 8; j++) t8[j] = fmaxf(fmaf(a, w1s[j], b1s[j]), 0.f);
    float t16[16];
#pragma unroll
    for (int c = 0; c < 16; c++) {
        float acc = b2s[c];
#pragma unroll
        for (int j = 0; j < 8; j++) acc = fmaf(t8[j], w2s[j * 16 + c], acc);
        t16[c] = fmaxf(acc, 0.f);
    }
#pragma unroll
    for (int c = 0; c < 32; c++) {
        float acc = b3s[c];
#pragma unroll
        for (int j = 0; j < 16; j++) acc = fmaf(t16[j], w3s[j * 32 + c], acc);
        g_ef2[e * EDGE_D + c] = acc;
    }
}

// ---------------------------------------------------------------------------
// Final fused edge classifier. 256 threads (8 warps) per CTA.
// ---------------------------------------------------------------------------
__global__ void __launch_bounds__(256) k_final(
    const int* __restrict__ ei,
    const float* __restrict__ dp_w, const float* __restrict__ dp_b,
    const float* __restrict__ ec_w1, const float* __restrict__ ec_b1,
    const float* __restrict__ ec_w2, const float* __restrict__ ec_b2,
    float* __restrict__ out)
{
    __shared__ float dpw_s[288 * 32];
    __shared__ float ecw1_s[32 * 16];
    __shared__ float dpb_s[32];
    __shared__ float ecb1_s[16];
    __shared__ float ecw2_s[16];
    __shared__ float vec_s[8][292];
    __shared__ float o32_s[8][32];

    int tid = threadIdx.x;
    for (int i = tid; i < 288 * 32; i += 256) dpw_s[i] = dp_w[i];
    for (int i = tid; i < 512; i += 256) ecw1_s[i] = ec_w1[i];
    if (tid < 32) dpb_s[tid] = dp_b[tid];
    if (tid < 16) { ecb1_s[tid] = ec_b1[tid]; ecw2_s[tid] = ec_w2[tid]; }
    __syncthreads();

    float b2 = __ldg(ec_b2);
    int warp = tid >> 5, lane = tid & 31;
    int gw = blockIdx.x * 8 + warp;
    int nw = gridDim.x * 8;

    for (int e = gw; e < N_EDGES; e += nw) {
        int s = ei[e], d = ei[N_EDGES + e];
        const float* xsp = g_x + s * NODE_D;
        const float* xdp = g_x + d * NODE_D;
#pragma unroll
        for (int i = 0; i < 4; i++) {
            vec_s[warp][lane + 32 * i]       = xsp[lane + 32 * i];
            vec_s[warp][128 + lane + 32 * i] = xdp[lane + 32 * i];
        }
        vec_s[warp][256 + lane] = g_ef2[e * EDGE_D + lane];
        __syncwarp();

        float acc = dpb_s[lane];
#pragma unroll 4
        for (int i = 0; i < 288; i++) acc = fmaf(vec_s[warp][i], dpw_s[i * 32 + lane], acc);
        o32_s[warp][lane] = acc;
        __syncwarp();

        float hh = 0.f;
        if (lane < 16) {
            hh = ecb1_s[lane];
#pragma unroll 4
            for (int j = 0; j < 32; j++) hh = fmaf(o32_s[warp][j], ecw1_s[j * 16 + lane], hh);
            hh = fmaxf(hh, 0.f) * ecw2_s[lane];
        }
#pragma unroll
        for (int off = 8; off; off >>= 1) hh += __shfl_xor_sync(0xFFFFFFFFu, hh, off);
        if (lane == 0) out[e] = 1.f / (1.f + __expf(-(hh + b2)));
        __syncwarp();
    }
}

// ---------------------------------------------------------------------------
extern "C" void kernel_launch(void* const* d_in, const int* in_sizes, int n_in,
                              void* d_out, int out_size)
{
    (void)in_sizes; (void)n_in; (void)out_size;
    const float* node_feats = (const float*)d_in[0];
    const float* edge_attr  = (const float*)d_in[1];
    const float* nv_cw      = (const float*)d_in[2];
    const float* nv_cb      = (const float*)d_in[3];
    const float* nv_cw2     = (const float*)d_in[4];
    const float* nv_hw      = (const float*)d_in[5];
    const float* ne_w1      = (const float*)d_in[6];
    const float* ne_b1      = (const float*)d_in[7];
    const float* ne_w2      = (const float*)d_in[8];
    const float* ne_b2      = (const float*)d_in[9];
    const float* ee_w1      = (const float*)d_in[10];
    const float* ee_b1      = (const float*)d_in[11];
    const float* ee_w2      = (const float*)d_in[12];
    const float* ee_b2      = (const float*)d_in[13];
    const float* ee_w3      = (const float*)d_in[14];
    const float* ee_b3      = (const float*)d_in[15];
    const float* gat_w      = (const float*)d_in[16];
    const float* gat_as     = (const float*)d_in[17];
    const float* gat_ad     = (const float*)d_in[18];
    const float* gat_b      = (const float*)d_in[19];
    const float* dp_w       = (const float*)d_in[20];
    const float* dp_b       = (const float*)d_in[21];
    const float* ec_w1      = (const float*)d_in[22];
    const float* ec_b1      = (const float*)d_in[23];
    const float* ec_w2      = (const float*)d_in[24];
    const float* ec_b2      = (const float*)d_in[25];
    const int*   edge_index = (const int*)d_in[26];
    float* out = (float*)d_out;

    float *p_h1, *p_x;
    __nv_bfloat16 *p_Ah, *p_Al, *p_Bh, *p_Bl, *p_Ah2, *p_Al2, *p_Bh2, *p_Bl2;
    cudaGetSymbolAddress((void**)&p_h1, g_h1);
    cudaGetSymbolAddress((void**)&p_x, g_x);
    cudaGetSymbolAddress((void**)&p_Ah, g_Ah);
    cudaGetSymbolAddress((void**)&p_Al, g_Al);
    cudaGetSymbolAddress((void**)&p_Bh, g_Bh);
    cudaGetSymbolAddress((void**)&p_Bl, g_Bl);
    cudaGetSymbolAddress((void**)&p_Ah2, g_Ah2);
    cudaGetSymbolAddress((void**)&p_Al2, g_Al2);
    cudaGetSymbolAddress((void**)&p_Bh2, g_Bh2);
    cudaGetSymbolAddress((void**)&p_Bl2, g_Bl2);

    cudaFuncSetAttribute(k_mma, cudaFuncAttributeMaxDynamicSharedMemorySize, MMA_SMEM_TOTAL);
    cudaFuncSetAttribute(k_nv, cudaFuncAttributeMaxDynamicSharedMemorySize, NV_SMEM);

    // 0) prep: cw^T split + B operand conversions
    k_prep_cw<<<64, 256>>>(nv_cw);
    {
        dim3 g(VLAD_DIM / 32, N_PAD / 32);
        k_cvt_trans<<<g, 256>>>(nv_hw, H0D, VLAD_DIM, H0D, p_Bh, p_Bl, VLAD_DIM);
    }
    {
        dim3 g(K2PAD / 32, N2PAD / 32);
        k_cvt_trans<<<g, 256>>>(ne_w1, H1D, H0D, H1D, p_Bh2, p_Bl2, K2PAD);
    }

    // 1) FUSED NetVLAD -> g_Ah/g_Al
    k_nv<<<N_NODES, 256, NV_SMEM>>>(node_feats, nv_cb, nv_cw2);

    // 2) G1 HMMA: h0 = vlad @ hw -> split-bf16 A operand of G2
    {
        dim3 g(N_PAD / 128, M_PAD / 128);
        k_mma<<<g, 256, MMA_SMEM_TOTAL>>>(p_Ah, p_Al, p_Bh, p_Bl, VLAD_DIM,
                                          nullptr, N_NODES, H0D, nullptr, 0,
                                          p_Ah2, p_Al2, K2PAD);
    }
    // 3) G2 HMMA: h1 = relu(h0 @ ne_w1 + b1)
    {
        dim3 g(N2PAD / 128, M_PAD / 128);
        k_mma<<<g, 256, MMA_SMEM_TOTAL>>>(p_Ah2, p_Al2, p_Bh2, p_Bl2, K2PAD,
                                          p_h1, N_NODES, H1D, ne_b1, 1,
                                          nullptr, nullptr, 0);
    }
    // 4) G3: x = h1 @ ne_w2 + b2
    {
        dim3 g((NODE_D + 63) / 64, (N_NODES + 63) / 64);
        k_sgemm<<<g, 256>>>(p_h1, ne_w2, ne_b2, p_x, N_NODES, NODE_D, H1D, 0);
    }

    // 5) edge-attr MLP
    k_ef<<<(N_EDGES + 255) / 256, 256>>>(edge_attr, ee_w1, ee_b1, ee_w2, ee_b2, ee_w3, ee_b3);

    // 6) 3 GAT layers
    for (int l = 0; l < DEPTH; l++) {
        k_gat_h<<<N_NODES, 128>>>(gat_w + l * NODE_D * NODE_D,
                                  gat_as + l * NODE_D, gat_ad + l * NODE_D);
        k_edge12<<<(E_EXT + 255) / 256, 256>>>(edge_index);
        k_edge3<<<((E_EXT * 32) + 255) / 256, 256>>>(edge_index);
        k_gat_fin<<<(N_NODES * NODE_D + 255) / 256, 256>>>(gat_b + l * NODE_D);
    }

    // 7) fused edge classifier -> out
    k_final<<<256, 256>>>(edge_index, dp_w, dp_b, ec_w1, ec_b1, ec_w2, ec_b2, out);
}

// round 12
// speedup vs baseline: 5.2821x; 1.0654x over previous
#include <cuda_runtime.h>
#include <cuda_bf16.h>
#include <math.h>
#include <stdint.h>

#define N_NODES 2000
#define NUM_KP 500
#define DESC 256
#define NVK 64
#define VLAD_DIM (DESC*NVK)        // 16384
#define H0D (NUM_KP*2)             // 1000
#define H1D NUM_KP                 // 500
#define NODE_D 128
#define EDGE_D 32
#define N_EDGES 64000
#define E_EXT (N_EDGES + N_NODES)  // 66000
#define DEPTH 3

#define M_PAD 2048
#define N_PAD 1024
#define K2PAD 1024
#define N2PAD 512

typedef unsigned long long u64;

// ---------------- scratch (device globals; no runtime allocation) ----------
__device__ float    g_h1[N_NODES * H1D];
__device__ float    g_x[N_NODES * NODE_D];
__device__ float    g_h[N_NODES * NODE_D];
__device__ float    g_es[N_NODES];
__device__ float    g_ed[N_NODES];
__device__ float    g_ex[E_EXT];
__device__ float    g_den[N_NODES];
__device__ float    g_aggr[N_NODES * NODE_D];
__device__ float    g_ef2[N_EDGES * EDGE_D];
// split-bf16 operands (pad regions stay zero: static zero-init, never written)
__device__ __nv_bfloat16 g_Ah[(size_t)M_PAD * VLAD_DIM];
__device__ __nv_bfloat16 g_Al[(size_t)M_PAD * VLAD_DIM];
__device__ __nv_bfloat16 g_Bh[(size_t)N_PAD * VLAD_DIM];
__device__ __nv_bfloat16 g_Bl[(size_t)N_PAD * VLAD_DIM];
__device__ __nv_bfloat16 g_Ah2[(size_t)M_PAD * K2PAD];
__device__ __nv_bfloat16 g_Al2[(size_t)M_PAD * K2PAD];
__device__ __nv_bfloat16 g_Bh2[(size_t)N2PAD * K2PAD];
__device__ __nv_bfloat16 g_Bl2[(size_t)N2PAD * K2PAD];
__device__ __nv_bfloat16 g_cwTh[NVK * DESC];
__device__ __nv_bfloat16 g_cwTl[NVK * DESC];

// ---------------- helpers ---------------------------------------------------
__device__ __forceinline__ uint32_t smem_u32(const void* p) {
    uint32_t a;
    asm("{ .reg .u64 t; cvta.to.shared.u64 t, %1; cvt.u32.u64 %0, t; }" : "=r"(a) : "l"(p));
    return a;
}
__device__ __forceinline__ uint32_t lds32(uint32_t addr) {
    uint32_t v;
    asm volatile("ld.shared.b32 %0, [%1];" : "=r"(v) : "r"(addr));
    return v;
}
__device__ __forceinline__ void ldm_x4(uint32_t* r, uint32_t addr) {
    asm volatile("ldmatrix.sync.aligned.m8n8.x4.shared.b16 {%0,%1,%2,%3}, [%4];"
        : "=r"(r[0]), "=r"(r[1]), "=r"(r[2]), "=r"(r[3]) : "r"(addr));
}
__device__ __forceinline__ void ldm_x4_t(uint32_t* r, uint32_t addr) {
    asm volatile("ldmatrix.sync.aligned.m8n8.x4.trans.shared.b16 {%0,%1,%2,%3}, [%4];"
        : "=r"(r[0]), "=r"(r[1]), "=r"(r[2]), "=r"(r[3]) : "r"(addr));
}
__device__ __forceinline__ void mma16816(float* c, const uint32_t* a, const uint32_t* b) {
    asm volatile(
        "mma.sync.aligned.m16n8k16.row.col.f32.bf16.bf16.f32 "
        "{%0,%1,%2,%3}, {%4,%5,%6,%7}, {%8,%9}, {%0,%1,%2,%3};"
        : "+f"(c[0]), "+f"(c[1]), "+f"(c[2]), "+f"(c[3])
        : "r"(a[0]), "r"(a[1]), "r"(a[2]), "r"(a[3]), "r"(b[0]), "r"(b[1]));
}
#define CP_ASYNC16(dst, src) \
    asm volatile("cp.async.cg.shared.global [%0], [%1], 16;" :: "r"(dst), "l"(src) : "memory")
#define CP_COMMIT()  asm volatile("cp.async.commit_group;" ::: "memory")
#define CP_WAIT0()   asm volatile("cp.async.wait_group 0;" ::: "memory")

__device__ __forceinline__ float sanit(float v) {
    if (!isfinite(v)) v = (v != v) ? 0.f : (v > 0.f ? 3.402823466e38f : -3.402823466e38f);
    return v;
}

// ---------------------------------------------------------------------------
// Prep: cw [256][64] fp32 -> cw^T split-bf16 [64][256]
// ---------------------------------------------------------------------------
__global__ void k_prep_cw(const float* __restrict__ cw)
{
    int i = blockIdx.x * 256 + threadIdx.x;    // 0..16383
    int k = i >> 8, d = i & 255;
    float v = cw[d * 64 + k];
    __nv_bfloat16 h = __float2bfloat16(v);
    g_cwTh[k * 256 + d] = h;
    g_cwTl[k * 256 + d] = __float2bfloat16(v - __bfloat162float(h));
}

// ---------------------------------------------------------------------------
// FUSED NetVLAD with ldmatrix fragment loads + cp.async staging pipeline.
// cw2 prefetched into the staging buffer during the final block's GEMM.
// ---------------------------------------------------------------------------
#define O_CWH 0          // cwT hi [64 k][264 d] bf16 (pitch 528B), 33792B
#define O_CWL 33792
#define O_XH  67584      // x hi [64 n][264 d], 33792B
#define O_XL  101376
#define O_LOG 135168     // logits [64][68] f32 (17408B); reused as actT after
#define O_ACTH 135168    // actT hi [64 k][72 n] bf16 pitch 144B (9216B)
#define O_ACTL 144384
#define O_RED 153600     // [8][64] f32 (2048B)
#define O_ASUM 155648    // [64] f32
#define O_REDK 155904    // [64][4] f32
#define O_INVK 156928    // [64] f32
#define O_INVT 157184
#define O_XF  157200     // fp32 staging [64 n][256 d] = 65536B (cw2 at the end)
#define NV_SMEM 222736

__global__ void __launch_bounds__(256, 1) k_nv(
    const float* __restrict__ feats, const float* __restrict__ cb,
    const float* __restrict__ cw2)
{
    extern __shared__ __align__(16) char sm[];
    int b = blockIdx.x;
    int tid = threadIdx.x, lane = tid & 31, wid = tid >> 5;
    int wm = wid & 3, wn = wid >> 2;
    int lr = lane >> 2, lc = (lane & 3) * 2;

    uint32_t cwh_s = smem_u32(sm + O_CWH), cwl_s = smem_u32(sm + O_CWL);
    uint32_t xh_s  = smem_u32(sm + O_XH),  xl_s  = smem_u32(sm + O_XL);
    uint32_t ah_s  = smem_u32(sm + O_ACTH), al_s = smem_u32(sm + O_ACTL);
    uint32_t xf_s  = smem_u32(sm + O_XF);
    float* logit = (float*)(sm + O_LOG);
    float* red   = (float*)(sm + O_RED);
    float* asums = (float*)(sm + O_ASUM);
    float* redk  = (float*)(sm + O_REDK);
    float* invk  = (float*)(sm + O_INVK);
    float* invts = (float*)(sm + O_INVT);
    const float* xf = (const float*)(sm + O_XF);

    int l7  = lane & 7;
    int s8  = (lane & 8) ? 8 : 0;
    int s16 = (lane & 16) ? 8 : 0;
    int rowA_log = wm * 16 + l7 + s8;
    int rowB_nt  = l7 + s16;
    int rowX_n   = l7 + s16;

    auto issue_xf = [&](int kbi) {
        int n0 = kbi * 64;
#pragma unroll
        for (int p = 0; p < 16; p++) {
            int idx = tid + p * 256;      // 0..4095 16B-chunks
            int row = idx >> 6;
            int c16 = idx & 63;
            int gn = n0 + row;
            if (gn < NUM_KP) {
                uint32_t d = xf_s + (uint32_t)(row * 1024 + c16 * 16);
                const char* src = (const char*)(feats + ((size_t)b * NUM_KP + gn) * DESC) + c16 * 16;
                CP_ASYNC16(d, src);
            }
        }
        CP_COMMIT();
    };
    auto issue_cw2 = [&]() {
#pragma unroll
        for (int p = 0; p < 16; p++) {
            int idx = tid + p * 256;      // 4096 chunks = 64KB
            CP_ASYNC16(xf_s + (uint32_t)idx * 16, (const char*)cw2 + (size_t)idx * 16);
        }
        CP_COMMIT();
    };

    for (int i = tid; i < 2048; i += 256) {
        int k = i >> 5, c = i & 31;
        *(uint4*)(sm + O_CWH + k * 528 + c * 16) = ((const uint4*)g_cwTh)[i];
        *(uint4*)(sm + O_CWL + k * 528 + c * 16) = ((const uint4*)g_cwTl)[i];
    }
    issue_xf(0);

    float accv[4][4][4];
#pragma unroll
    for (int mt = 0; mt < 4; mt++)
#pragma unroll
        for (int nt = 0; nt < 4; nt++)
#pragma unroll
            for (int q = 0; q < 4; q++) accv[mt][nt][q] = 0.f;
    float s0 = 0.f, s1 = 0.f;
    float cb0 = cb[lane], cb1 = cb[lane + 32];

    for (int kb = 0; kb < 8; kb++) {
        CP_WAIT0();
        __syncthreads();
        int n0 = kb * 64;
        // ---- convert fp32 staging -> split-bf16 row-major x tile ----
        for (int i = tid; i < 4096; i += 256) {
            int row = i >> 6, c4 = i & 63;
            int gn = n0 + row;
            float4 v = make_float4(0.f, 0.f, 0.f, 0.f);
            if (gn < NUM_KP) v = *(const float4*)(xf + row * 256 + c4 * 4);
            float vv[4] = { sanit(v.x), sanit(v.y), sanit(v.z), sanit(v.w) };
            __nv_bfloat16 hh[4], ll[4];
#pragma unroll
            for (int j = 0; j < 4; j++) {
                hh[j] = __float2bfloat16(vv[j]);
                ll[j] = __float2bfloat16(vv[j] - __bfloat162float(hh[j]));
            }
            char* pxh = sm + O_XH + row * 528 + c4 * 8;
            char* pxl = sm + O_XL + row * 528 + c4 * 8;
            *(__nv_bfloat162*)pxh       = __nv_bfloat162(hh[0], hh[1]);
            *(__nv_bfloat162*)(pxh + 4) = __nv_bfloat162(hh[2], hh[3]);
            *(__nv_bfloat162*)pxl       = __nv_bfloat162(ll[0], ll[1]);
            *(__nv_bfloat162*)(pxl + 4) = __nv_bfloat162(ll[2], ll[3]);
        }
        __syncthreads();                   // staging fully consumed
        if (kb + 1 < 8) issue_xf(kb + 1);  // refill overlaps the GEMM phase
        else            issue_cw2();       // prefetch cw2 for the epilogue

        // ---- logits GEMM ----
        float acc[4][4];
#pragma unroll
        for (int nt = 0; nt < 4; nt++)
#pragma unroll
            for (int q = 0; q < 4; q++) acc[nt][q] = 0.f;
#pragma unroll
        for (int ks = 0; ks < 16; ks++) {
            int kl = ks * 16;
            uint32_t aoff = (uint32_t)(rowA_log * 528 + (kl + s16) * 2);
            uint32_t a[4], al_[4];
            ldm_x4(a,  xh_s + aoff);
            ldm_x4(al_, xl_s + aoff);
#pragma unroll
            for (int ntp = 0; ntp < 2; ntp++) {
                uint32_t boff = (uint32_t)((wn * 32 + ntp * 16 + rowB_nt) * 528 + (kl + s8) * 2);
                uint32_t bh4[4], bl4[4];
                ldm_x4(bh4, cwh_s + boff);
                ldm_x4(bl4, cwl_s + boff);
                mma16816(acc[2 * ntp],     a,   bh4);
                mma16816(acc[2 * ntp],     a,   bl4);
                mma16816(acc[2 * ntp],     al_, bh4);
                mma16816(acc[2 * ntp + 1], a,   bh4 + 2);
                mma16816(acc[2 * ntp + 1], a,   bl4 + 2);
                mma16816(acc[2 * ntp + 1], al_, bh4 + 2);
            }
        }
#pragma unroll
        for (int nt = 0; nt < 4; nt++)
#pragma unroll
            for (int q = 0; q < 4; q++) {
                int row = wm * 16 + lr + ((q >> 1) * 8);
                int col = wn * 32 + nt * 8 + lc + (q & 1);
                logit[row * 68 + col] = acc[nt][q];
            }
        __syncthreads();

        // ---- softmax (no max subtraction: logits are O(1) with this model) ----
        float l0r[8], l1r[8];
#pragma unroll
        for (int rr = 0; rr < 8; rr++) {
            int row = wid * 8 + rr;
            l0r[rr] = logit[row * 68 + lane] + cb0;
            l1r[rr] = logit[row * 68 + lane + 32] + cb1;
        }
        __syncthreads();
#pragma unroll
        for (int rr = 0; rr < 8; rr++) {
            int row = wid * 8 + rr;
            int gn = n0 + row;
            float e0 = __expf(l0r[rr]), e1 = __expf(l1r[rr]);
            float ss = e0 + e1;
#pragma unroll
            for (int off = 16; off; off >>= 1) ss += __shfl_xor_sync(0xFFFFFFFFu, ss, off);
            float inv = 1.f / ss;
            if (gn < NUM_KP) { e0 *= inv; e1 *= inv; s0 += e0; s1 += e1; }
            else             { e0 = 0.f;  e1 = 0.f; }
            __nv_bfloat16 h0 = __float2bfloat16(e0);
            __nv_bfloat16 h1 = __float2bfloat16(e1);
            *(__nv_bfloat16*)(sm + O_ACTH + lane * 144 + row * 2)        = h0;
            *(__nv_bfloat16*)(sm + O_ACTH + (lane + 32) * 144 + row * 2) = h1;
            *(__nv_bfloat16*)(sm + O_ACTL + lane * 144 + row * 2) =
                __float2bfloat16(e0 - __bfloat162float(h0));
            *(__nv_bfloat16*)(sm + O_ACTL + (lane + 32) * 144 + row * 2) =
                __float2bfloat16(e1 - __bfloat162float(h1));
        }
        __syncthreads();

        // ---- vlad GEMM ----
#pragma unroll
        for (int ks = 0; ks < 4; ks++) {
            int kl = ks * 16;
            uint32_t bh4[2][4], bl4[2][4];
#pragma unroll
            for (int ntp = 0; ntp < 2; ntp++) {
                uint32_t boff = (uint32_t)((wn * 32 + ntp * 16 + rowB_nt) * 144 + (kl + s8) * 2);
                ldm_x4(bh4[ntp], ah_s + boff);
                ldm_x4(bl4[ntp], al_s + boff);
            }
#pragma unroll
            for (int mt = 0; mt < 4; mt++) {
                uint32_t aoff = (uint32_t)((kl + rowX_n) * 528 + (wm * 64 + mt * 16 + s8) * 2);
                uint32_t a[4], al2[4];
                ldm_x4_t(a,   xh_s + aoff);
                ldm_x4_t(al2, xl_s + aoff);
#pragma unroll
                for (int ntp = 0; ntp < 2; ntp++) {
                    mma16816(accv[mt][2 * ntp],     a,   bh4[ntp]);
                    mma16816(accv[mt][2 * ntp],     a,   bl4[ntp]);
                    mma16816(accv[mt][2 * ntp],     al2, bh4[ntp]);
                    mma16816(accv[mt][2 * ntp + 1], a,   bh4[ntp] + 2);
                    mma16816(accv[mt][2 * ntp + 1], a,   bl4[ntp] + 2);
                    mma16816(accv[mt][2 * ntp + 1], al2, bh4[ntp] + 2);
                }
            }
        }
    }

    // ---- asum reduce; cw2 already streaming into XF ----
    red[wid * 64 + lane]      = s0;
    red[wid * 64 + lane + 32] = s1;
    CP_WAIT0();                           // cw2 resident in XF
    __syncthreads();
    if (tid < 32) {
        float t0 = 0.f, t1 = 0.f;
#pragma unroll
        for (int w = 0; w < 8; w++) { t0 += red[w * 64 + lane]; t1 += red[w * 64 + lane + 32]; }
        asums[lane] = t0; asums[lane + 32] = t1;
    }
    __syncthreads();
    const float* cw2s = xf;

#pragma unroll
    for (int mt = 0; mt < 4; mt++)
#pragma unroll
        for (int nt = 0; nt < 4; nt++)
#pragma unroll
            for (int q = 0; q < 4; q++) {
                int d = wm * 64 + mt * 16 + lr + ((q >> 1) * 8);
                int k = wn * 32 + nt * 8 + lc + (q & 1);
                accv[mt][nt][q] -= asums[k] * cw2s[d * 64 + k];
            }
#pragma unroll
    for (int nt = 0; nt < 4; nt++) {
        float sq0 = 0.f, sq1 = 0.f;
#pragma unroll
        for (int mt = 0; mt < 4; mt++) {
            sq0 += accv[mt][nt][0] * accv[mt][nt][0] + accv[mt][nt][2] * accv[mt][nt][2];
            sq1 += accv[mt][nt][1] * accv[mt][nt][1] + accv[mt][nt][3] * accv[mt][nt][3];
        }
        sq0 += __shfl_xor_sync(0xFFFFFFFFu, sq0, 4);
        sq0 += __shfl_xor_sync(0xFFFFFFFFu, sq0, 8);
        sq0 += __shfl_xor_sync(0xFFFFFFFFu, sq0, 16);
        sq1 += __shfl_xor_sync(0xFFFFFFFFu, sq1, 4);
        sq1 += __shfl_xor_sync(0xFFFFFFFFu, sq1, 8);
        sq1 += __shfl_xor_sync(0xFFFFFFFFu, sq1, 16);
        if (lr == 0) {
            int k0 = wn * 32 + nt * 8 + lc;
            redk[k0 * 4 + wm]       = sq0;
            redk[(k0 + 1) * 4 + wm] = sq1;
        }
    }
    __syncthreads();
    if (tid < 32) {
        float q0 = redk[lane * 4] + redk[lane * 4 + 1] + redk[lane * 4 + 2] + redk[lane * 4 + 3];
        int l2 = lane + 32;
        float q1 = redk[l2 * 4] + redk[l2 * 4 + 1] + redk[l2 * 4 + 2] + redk[l2 * 4 + 3];
        float i0 = 1.f / (sqrtf(q0) + 1e-12f);
        float i1 = 1.f / (sqrtf(q1) + 1e-12f);
        invk[lane] = i0; invk[l2] = i1;
        float tt = q0 * i0 * i0 + q1 * i1 * i1;
#pragma unroll
        for (int off = 16; off; off >>= 1) tt += __shfl_xor_sync(0xFFFFFFFFu, tt, off);
        if (lane == 0) invts[0] = 1.f / (sqrtf(tt) + 1e-12f);
    }
    __syncthreads();
    float invt = invts[0];

#pragma unroll
    for (int mt = 0; mt < 4; mt++)
#pragma unroll
        for (int nt = 0; nt < 4; nt++)
#pragma unroll
            for (int q = 0; q < 4; q++) {
                int d = wm * 64 + mt * 16 + lr + ((q >> 1) * 8);
                int k = wn * 32 + nt * 8 + lc + (q & 1);
                float val = accv[mt][nt][q] * invk[k] * invt;
                __nv_bfloat16 h = __float2bfloat16(val);
                *(__nv_bfloat16*)(sm + O_XH + (d * 66 + k) * 2) = h;
                *(__nv_bfloat16*)(sm + O_XL + (d * 66 + k) * 2) =
                    __float2bfloat16(val - __bfloat162float(h));
            }
    __syncthreads();
    for (int i = tid; i < 8192; i += 256) {
        int d = i >> 5, kp = i & 31;
        uint32_t vh = lds32(xh_s + (uint32_t)(d * 66 + kp * 2) * 2);
        uint32_t vl = lds32(xl_s + (uint32_t)(d * 66 + kp * 2) * 2);
        size_t go = (size_t)b * VLAD_DIM + d * 64 + kp * 2;
        *(uint32_t*)((char*)g_Ah + go * 2) = vh;
        *(uint32_t*)((char*)g_Al + go * 2) = vl;
    }
}

// ---------------------------------------------------------------------------
// Transpose + split: src[k][n] fp32 -> dh/dl[n][k] bf16 (pads zero-filled).
// ---------------------------------------------------------------------------
__global__ void __launch_bounds__(256) k_cvt_trans(
    const float* __restrict__ src, int ldsrc, int Kreal, int Nreal,
    __nv_bfloat16* __restrict__ dh, __nv_bfloat16* __restrict__ dl, int ldd)
{
    __shared__ float smt[32][33];
    int k0 = blockIdx.x * 32;
    int n0 = blockIdx.y * 32;
    int tx = threadIdx.x & 31;
    int ty = threadIdx.x >> 5;
#pragma unroll
    for (int i = 0; i < 4; i++) {
        int kk = ty + i * 8;
        int n = n0 + tx;
        float v = (k0 + kk < Kreal && n < Nreal) ? src[(size_t)(k0 + kk) * ldsrc + n] : 0.f;
        smt[kk][tx] = v;
    }
    __syncthreads();
#pragma unroll
    for (int i = 0; i < 4; i++) {
        int nn = ty + i * 8;
        float v = smt[tx][nn];
        __nv_bfloat16 h = __float2bfloat16(v);
        __nv_bfloat16 l = __float2bfloat16(v - __bfloat162float(h));
        size_t o = (size_t)(n0 + nn) * ldd + k0 + tx;
        dh[o] = h;
        dl[o] = l;
    }
}

// ---------------------------------------------------------------------------
// Split-bf16 HMMA GEMM with ldmatrix fragment loads.
// ---------------------------------------------------------------------------
#define KBLK 64
#define SPITCH 72
#define SPB (SPITCH * 2)
#define TILE_B (128 * SPB)
#define STAGE_B (4 * TILE_B)
#define MMA_SMEM_TOTAL (2 * STAGE_B)

__global__ void __launch_bounds__(256, 1) k_mma(
    const __nv_bfloat16* __restrict__ Ah, const __nv_bfloat16* __restrict__ Al,
    const __nv_bfloat16* __restrict__ Bh, const __nv_bfloat16* __restrict__ Bl,
    int K, float* __restrict__ C, int M, int N,
    const float* __restrict__ bias, int act,
    __nv_bfloat16* __restrict__ Dh, __nv_bfloat16* __restrict__ Dl, int ldd)
{
    extern __shared__ __align__(16) char smem[];
    uint32_t sb = smem_u32(smem);
    int tid = threadIdx.x;
    int wid = tid >> 5, lane = tid & 31;
    int wm = wid & 3;
    int wn = wid >> 2;
    int m0 = blockIdx.y * 128;
    int n0 = blockIdx.x * 128;

    const __nv_bfloat16* srcs[4] = {
        Ah + (size_t)m0 * K, Al + (size_t)m0 * K,
        Bh + (size_t)n0 * K, Bl + (size_t)n0 * K };

    int lrow = tid >> 3;
    int lchk = tid & 7;

    int l7  = lane & 7;
    int s8  = (lane & 8) ? 8 : 0;
    int s16 = (lane & 16) ? 8 : 0;

    float acc[2][8][4];
#pragma unroll
    for (int i = 0; i < 2; i++)
#pragma unroll
        for (int j = 0; j < 8; j++)
#pragma unroll
            for (int q = 0; q < 4; q++) acc[i][j][q] = 0.f;

    auto load_stage = [&](int s, int kb) {
        uint32_t sd = sb + s * STAGE_B;
        size_t kOff = (size_t)kb * KBLK;
#pragma unroll
        for (int v = 0; v < 4; v++) {
            const __nv_bfloat16* g = srcs[v] + kOff;
#pragma unroll
            for (int p = 0; p < 4; p++) {
                int rr = lrow + p * 32;
                uint32_t d = sd + v * TILE_B + rr * SPB + lchk * 16;
                const void* sptr = (const char*)(g + (size_t)rr * K) + lchk * 16;
                CP_ASYNC16(d, sptr);
            }
        }
        CP_COMMIT();
    };

    load_stage(0, 0);

    int lr = lane >> 2;
    int lc = (lane & 3) * 2;
    int nkb = K / KBLK;

    for (int kb = 0; kb < nkb; kb++) {
        int s = kb & 1;
        CP_WAIT0();
        __syncthreads();
        if (kb + 1 < nkb) load_stage(s ^ 1, kb + 1);

        uint32_t sAh = sb + s * STAGE_B;
        uint32_t sAl = sAh + TILE_B;
        uint32_t sBh = sAh + 2 * TILE_B;
        uint32_t sBl = sAh + 3 * TILE_B;

#pragma unroll
        for (int ks = 0; ks < 4; ks++) {
            int kl = ks * 16;
            uint32_t ah4[2][4], al4[2][4];
#pragma unroll
            for (int mt = 0; mt < 2; mt++) {
                uint32_t aoff = (uint32_t)((wm * 32 + mt * 16 + l7 + s8) * SPB + (kl + s16) * 2);
                ldm_x4(ah4[mt], sAh + aoff);
                ldm_x4(al4[mt], sAl + aoff);
            }
            uint32_t bh4[4][4], bl4[4][4];
#pragma unroll
            for (int ntp = 0; ntp < 4; ntp++) {
                uint32_t boff = (uint32_t)((wn * 64 + ntp * 16 + l7 + s16) * SPB + (kl + s8) * 2);
                ldm_x4(bh4[ntp], sBh + boff);
                ldm_x4(bl4[ntp], sBl + boff);
            }
#pragma unroll
            for (int mt = 0; mt < 2; mt++)
#pragma unroll
                for (int ntp = 0; ntp < 4; ntp++) {
                    mma16816(acc[mt][2 * ntp],     ah4[mt], bh4[ntp]);
                    mma16816(acc[mt][2 * ntp],     ah4[mt], bl4[ntp]);
                    mma16816(acc[mt][2 * ntp],     al4[mt], bh4[ntp]);
                    mma16816(acc[mt][2 * ntp + 1], ah4[mt], bh4[ntp] + 2);
                    mma16816(acc[mt][2 * ntp + 1], ah4[mt], bl4[ntp] + 2);
                    mma16816(acc[mt][2 * ntp + 1], al4[mt], bh4[ntp] + 2);
                }
        }
    }

    auto emit = [&](int r, int c, float v) {
        bool in = (r < M && c < N);
        float val = 0.f;
        if (in) {
            val = v + (bias ? bias[c] : 0.f);
            if (act == 1) val = fmaxf(val, 0.f);
            if (C) C[(size_t)r * N + c] = val;
        }
        if (Dh) {
            __nv_bfloat16 h = __float2bfloat16(val);
            Dh[(size_t)r * ldd + c] = h;
            Dl[(size_t)r * ldd + c] = __float2bfloat16(val - __bfloat162float(h));
        }
    };
#pragma unroll
    for (int mt = 0; mt < 2; mt++) {
#pragma unroll
        for (int nt = 0; nt < 8; nt++) {
            int r = m0 + wm * 32 + mt * 16 + lr;
            int c = n0 + wn * 64 + nt * 8 + lc;
            emit(r,     c,     acc[mt][nt][0]);
            emit(r,     c + 1, acc[mt][nt][1]);
            emit(r + 8, c,     acc[mt][nt][2]);
            emit(r + 8, c + 1, acc[mt][nt][3]);
        }
    }
}

// ---------------------------------------------------------------------------
// Small SGEMM (64x64x16) for G3.
// ---------------------------------------------------------------------------
__global__ void __launch_bounds__(256) k_sgemm(
    const float* __restrict__ A, const float* __restrict__ B,
    const float* __restrict__ bias, float* __restrict__ C,
    int M, int N, int K, int act)
{
    __shared__ __align__(16) float As[16][64];
    __shared__ __align__(16) float Bs[16][64];

    int tid = threadIdx.x;
    int tx = tid & 15, ty = tid >> 4;
    int row0 = blockIdx.y * 64, col0 = blockIdx.x * 64;

    float c[4][4];
#pragma unroll
    for (int i = 0; i < 4; i++)
#pragma unroll
        for (int j = 0; j < 4; j++) c[i][j] = 0.f;

    int am = tid >> 2;
    int ak = (tid & 3) * 4;
    int bk = tid >> 4;
    int bn = (tid & 15) * 4;

    for (int k0 = 0; k0 < K; k0 += 16) {
        int arow = row0 + am;
        if (arow < M && k0 + ak + 3 < K) {
            float4 v = *reinterpret_cast<const float4*>(&A[(size_t)arow * K + k0 + ak]);
            As[ak + 0][am] = v.x; As[ak + 1][am] = v.y;
            As[ak + 2][am] = v.z; As[ak + 3][am] = v.w;
        } else {
#pragma unroll
            for (int i = 0; i < 4; i++) {
                int kk = k0 + ak + i;
                As[ak + i][am] = (arow < M && kk < K) ? A[(size_t)arow * K + kk] : 0.f;
            }
        }
        int brow = k0 + bk;
        if (brow < K && col0 + bn + 3 < N) {
            float4 v = *reinterpret_cast<const float4*>(&B[(size_t)brow * N + col0 + bn]);
            *reinterpret_cast<float4*>(&Bs[bk][bn]) = v;
        } else {
#pragma unroll
            for (int i = 0; i < 4; i++) {
                int nn = col0 + bn + i;
                Bs[bk][bn + i] = (brow < K && nn < N) ? B[(size_t)brow * N + nn] : 0.f;
            }
        }
        __syncthreads();
#pragma unroll
        for (int kk = 0; kk < 16; kk++) {
            float4 av = *reinterpret_cast<const float4*>(&As[kk][ty * 4]);
            float4 bv = *reinterpret_cast<const float4*>(&Bs[kk][tx * 4]);
            float a[4] = {av.x, av.y, av.z, av.w};
            float bb[4] = {bv.x, bv.y, bv.z, bv.w};
#pragma unroll
            for (int i = 0; i < 4; i++)
#pragma unroll
                for (int j = 0; j < 4; j++) c[i][j] = fmaf(a[i], bb[j], c[i][j]);
        }
        __syncthreads();
    }

#pragma unroll
    for (int i = 0; i < 4; i++) {
        int r = row0 + ty * 4 + i;
        if (r >= M) continue;
#pragma unroll
        for (int j = 0; j < 4; j++) {
            int cc = col0 + tx * 4 + j;
            if (cc >= N) continue;
            float v = c[i][j];
            if (bias) v += bias[cc];
            if (act == 1) v = fmaxf(v, 0.f);
            C[(size_t)r * N + cc] = v;
        }
    }
}

// ---------------------------------------------------------------------------
// GAT kernels. k_gat_h also zeroes den/aggr for the current layer.
// ---------------------------------------------------------------------------
__global__ void __launch_bounds__(128) k_gat_h(
    const float* __restrict__ W, const float* __restrict__ a_s,
    const float* __restrict__ a_d)
{
    int b = blockIdx.x, t = threadIdx.x;
    __shared__ float xsm[NODE_D];
    __shared__ float rs[8];
    xsm[t] = g_x[b * NODE_D + t];
    g_aggr[b * NODE_D + t] = 0.f;
    if (t == 0) g_den[b] = 0.f;
    __syncthreads();
    float acc = 0.f;
#pragma unroll 8
    for (int d = 0; d < NODE_D; d++) acc = fmaf(xsm[d], __ldg(&W[d * NODE_D + t]), acc);
    g_h[b * NODE_D + t] = acc;
    float ps = acc * __ldg(&a_s[t]);
    float pd = acc * __ldg(&a_d[t]);
#pragma unroll
    for (int off = 16; off; off >>= 1) {
        ps += __shfl_xor_sync(0xFFFFFFFFu, ps, off);
        pd += __shfl_xor_sync(0xFFFFFFFFu, pd, off);
    }
    if ((t & 31) == 0) { rs[t >> 5] = ps; rs[4 + (t >> 5)] = pd; }
    __syncthreads();
    if (t == 0) g_es[b] = rs[0] + rs[1] + rs[2] + rs[3];
    if (t == 1) g_ed[b] = rs[4] + rs[5] + rs[6] + rs[7];
}

__global__ void k_edge12(const int* __restrict__ ei)
{
    int e = blockIdx.x * blockDim.x + threadIdx.x;
    if (e >= E_EXT) return;
    int s, d;
    if (e < N_EDGES) { s = ei[e]; d = ei[N_EDGES + e]; }
    else { s = e - N_EDGES; d = s; }
    float v = g_es[s] + g_ed[d];
    v = (v > 0.f) ? v : 0.2f * v;
    float ex = __expf(v);
    g_ex[e] = ex;
    atomicAdd(&g_den[d], ex);
}

__global__ void k_edge3(const int* __restrict__ ei)
{
    int gt = blockIdx.x * blockDim.x + threadIdx.x;
    int w = gt >> 5, lane = gt & 31;
    if (w >= E_EXT) return;
    int s, d;
    if (w < N_EDGES) { s = ei[w]; d = ei[N_EDGES + w]; }
    else { s = w - N_EDGES; d = s; }
    float alpha = g_ex[w] / g_den[d];
#pragma unroll
    for (int i = 0; i < 4; i++) {
        int c = lane + 32 * i;
        atomicAdd(&g_aggr[d * NODE_D + c], g_h[s * NODE_D + c] * alpha);
    }
}

__global__ void k_gat_fin(const float* __restrict__ b)
{
    int i = blockIdx.x * blockDim.x + threadIdx.x;
    if (i >= N_NODES * NODE_D) return;
    float v = g_aggr[i] + __ldg(&b[i & (NODE_D - 1)]);
    g_x[i] = (v > 0.f) ? v : (__expf(v) - 1.f);
}

// ---------------------------------------------------------------------------
// Edge-attr MLP: 1 -> 8 -> 16 -> 32
// ---------------------------------------------------------------------------
__global__ void __launch_bounds__(256) k_ef(
    const float* __restrict__ ea,
    const float* __restrict__ w1, const float* __restrict__ b1,
    const float* __restrict__ w2, const float* __restrict__ b2,
    const float* __restrict__ w3, const float* __restrict__ b3)
{
    __shared__ float w1s[8], b1s[8], w2s[128], b2s[16], w3s[512], b3s[32];
    int t = threadIdx.x;
    if (t < 8)   { w1s[t] = w1[t]; b1s[t] = b1[t]; }
    if (t < 128) w2s[t] = w2[t];
    if (t < 16)  b2s[t] = b2[t];
    if (t < 32)  b3s[t] = b3[t];
    for (int i = t; i < 512; i += blockDim.x) w3s[i] = w3[i];
    __syncthreads();
    int e = blockIdx.x * blockDim.x + t;
    if (e >= N_EDGES) return;
    float a = ea[e];
    float t8[8];
#pragma unroll
    for (int j = 0; j < 8; j++) t8[j] = fmaxf(fmaf(a, w1s[j], b1s[j]), 0.f);
    float t16[16];
#pragma unroll
    for (int c = 0; c < 16; c++) {
        float acc = b2s[c];
#pragma unroll
        for (int j = 0; j < 8; j++) acc = fmaf(t8[j], w2s[j * 16 + c], acc);
        t16[c] = fmaxf(acc, 0.f);
    }
#pragma unroll
    for (int c = 0; c < 32; c++) {
        float acc = b3s[c];
#pragma unroll
        for (int j = 0; j < 16; j++) acc = fmaf(t16[j], w3s[j * 32 + c], acc);
        g_ef2[e * EDGE_D + c] = acc;
    }
}

// ---------------------------------------------------------------------------
// Final fused edge classifier. 256 threads (8 warps) per CTA.
// ---------------------------------------------------------------------------
__global__ void __launch_bounds__(256) k_final(
    const int* __restrict__ ei,
    const float* __restrict__ dp_w, const float* __restrict__ dp_b,
    const float* __restrict__ ec_w1, const float* __restrict__ ec_b1,
    const float* __restrict__ ec_w2, const float* __restrict__ ec_b2,
    float* __restrict__ out)
{
    __shared__ float dpw_s[288 * 32];
    __shared__ float ecw1_s[32 * 16];
    __shared__ float dpb_s[32];
    __shared__ float ecb1_s[16];
    __shared__ float ecw2_s[16];
    __shared__ float vec_s[8][292];
    __shared__ float o32_s[8][32];

    int tid = threadIdx.x;
    for (int i = tid; i < 288 * 32; i += 256) dpw_s[i] = dp_w[i];
    for (int i = tid; i < 512; i += 256) ecw1_s[i] = ec_w1[i];
    if (tid < 32) dpb_s[tid] = dp_b[tid];
    if (tid < 16) { ecb1_s[tid] = ec_b1[tid]; ecw2_s[tid] = ec_w2[tid]; }
    __syncthreads();

    float b2 = __ldg(ec_b2);
    int warp = tid >> 5, lane = tid & 31;
    int gw = blockIdx.x * 8 + warp;
    int nw = gridDim.x * 8;

    for (int e = gw; e < N_EDGES; e += nw) {
        int s = ei[e], d = ei[N_EDGES + e];
        const float* xsp = g_x + s * NODE_D;
        const float* xdp = g_x + d * NODE_D;
#pragma unroll
        for (int i = 0; i < 4; i++) {
            vec_s[warp][lane + 32 * i]       = xsp[lane + 32 * i];
            vec_s[warp][128 + lane + 32 * i] = xdp[lane + 32 * i];
        }
        vec_s[warp][256 + lane] = g_ef2[e * EDGE_D + lane];
        __syncwarp();

        float acc = dpb_s[lane];
#pragma unroll 4
        for (int i = 0; i < 288; i++) acc = fmaf(vec_s[warp][i], dpw_s[i * 32 + lane], acc);
        o32_s[warp][lane] = acc;
        __syncwarp();

        float hh = 0.f;
        if (lane < 16) {
            hh = ecb1_s[lane];
#pragma unroll 4
            for (int j = 0; j < 32; j++) hh = fmaf(o32_s[warp][j], ecw1_s[j * 16 + lane], hh);
            hh = fmaxf(hh, 0.f) * ecw2_s[lane];
        }
#pragma unroll
        for (int off = 8; off; off >>= 1) hh += __shfl_xor_sync(0xFFFFFFFFu, hh, off);
        if (lane == 0) out[e] = 1.f / (1.f + __expf(-(hh + b2)));
        __syncwarp();
    }
}

// ---------------------------------------------------------------------------
extern "C" void kernel_launch(void* const* d_in, const int* in_sizes, int n_in,
                              void* d_out, int out_size)
{
    (void)in_sizes; (void)n_in; (void)out_size;
    const float* node_feats = (const float*)d_in[0];
    const float* edge_attr  = (const float*)d_in[1];
    const float* nv_cw      = (const float*)d_in[2];
    const float* nv_cb      = (const float*)d_in[3];
    const float* nv_cw2     = (const float*)d_in[4];
    const float* nv_hw      = (const float*)d_in[5];
    const float* ne_w1      = (const float*)d_in[6];
    const float* ne_b1      = (const float*)d_in[7];
    const float* ne_w2      = (const float*)d_in[8];
    const float* ne_b2      = (const float*)d_in[9];
    const float* ee_w1      = (const float*)d_in[10];
    const float* ee_b1      = (const float*)d_in[11];
    const float* ee_w2      = (const float*)d_in[12];
    const float* ee_b2      = (const float*)d_in[13];
    const float* ee_w3      = (const float*)d_in[14];
    const float* ee_b3      = (const float*)d_in[15];
    const float* gat_w      = (const float*)d_in[16];
    const float* gat_as     = (const float*)d_in[17];
    const float* gat_ad     = (const float*)d_in[18];
    const float* gat_b      = (const float*)d_in[19];
    const float* dp_w       = (const float*)d_in[20];
    const float* dp_b       = (const float*)d_in[21];
    const float* ec_w1      = (const float*)d_in[22];
    const float* ec_b1      = (const float*)d_in[23];
    const float* ec_w2      = (const float*)d_in[24];
    const float* ec_b2      = (const float*)d_in[25];
    const int*   edge_index = (const int*)d_in[26];
    float* out = (float*)d_out;

    float *p_h1, *p_x;
    __nv_bfloat16 *p_Ah, *p_Al, *p_Bh, *p_Bl, *p_Ah2, *p_Al2, *p_Bh2, *p_Bl2;
    cudaGetSymbolAddress((void**)&p_h1, g_h1);
    cudaGetSymbolAddress((void**)&p_x, g_x);
    cudaGetSymbolAddress((void**)&p_Ah, g_Ah);
    cudaGetSymbolAddress((void**)&p_Al, g_Al);
    cudaGetSymbolAddress((void**)&p_Bh, g_Bh);
    cudaGetSymbolAddress((void**)&p_Bl, g_Bl);
    cudaGetSymbolAddress((void**)&p_Ah2, g_Ah2);
    cudaGetSymbolAddress((void**)&p_Al2, g_Al2);
    cudaGetSymbolAddress((void**)&p_Bh2, g_Bh2);
    cudaGetSymbolAddress((void**)&p_Bl2, g_Bl2);

    static int s_init = 0;
    static cudaStream_t s2;
    static cudaEvent_t ev1, ev2;
    if (!s_init) {
        cudaFuncSetAttribute(k_mma, cudaFuncAttributeMaxDynamicSharedMemorySize, MMA_SMEM_TOTAL);
        cudaFuncSetAttribute(k_nv, cudaFuncAttributeMaxDynamicSharedMemorySize, NV_SMEM);
        cudaStreamCreateWithFlags(&s2, cudaStreamNonBlocking);
        cudaEventCreateWithFlags(&ev1, cudaEventDisableTiming);
        cudaEventCreateWithFlags(&ev2, cudaEventDisableTiming);
        s_init = 1;
    }

    // fork: B-operand conversions + edge MLP run concurrently with NetVLAD
    cudaEventRecord(ev1, 0);
    cudaStreamWaitEvent(s2, ev1, 0);
    {
        dim3 g(VLAD_DIM / 32, N_PAD / 32);
        k_cvt_trans<<<g, 256, 0, s2>>>(nv_hw, H0D, VLAD_DIM, H0D, p_Bh, p_Bl, VLAD_DIM);
    }
    {
        dim3 g(K2PAD / 32, N2PAD / 32);
        k_cvt_trans<<<g, 256, 0, s2>>>(ne_w1, H1D, H0D, H1D, p_Bh2, p_Bl2, K2PAD);
    }
    k_ef<<<(N_EDGES + 255) / 256, 256, 0, s2>>>(edge_attr, ee_w1, ee_b1, ee_w2, ee_b2,
                                                ee_w3, ee_b3);
    cudaEventRecord(ev2, s2);

    // main stream: NetVLAD
    k_prep_cw<<<64, 256>>>(nv_cw);
    k_nv<<<N_NODES, 256, NV_SMEM>>>(node_feats, nv_cb, nv_cw2);

    // join before G1 (needs g_Bh/g_Bl; g_ef2 needed later by k_final)
    cudaStreamWaitEvent(0, ev2, 0);

    // G1 HMMA: h0 = vlad @ hw -> split-bf16 A operand of G2
    {
        dim3 g(N_PAD / 128, M_PAD / 128);
        k_mma<<<g, 256, MMA_SMEM_TOTAL>>>(p_Ah, p_Al, p_Bh, p_Bl, VLAD_DIM,
                                          nullptr, N_NODES, H0D, nullptr, 0,
                                          p_Ah2, p_Al2, K2PAD);
    }
    // G2 HMMA: h1 = relu(h0 @ ne_w1 + b1)
    {
        dim3 g(N2PAD / 128, M_PAD / 128);
        k_mma<<<g, 256, MMA_SMEM_TOTAL>>>(p_Ah2, p_Al2, p_Bh2, p_Bl2, K2PAD,
                                          p_h1, N_NODES, H1D, ne_b1, 1,
                                          nullptr, nullptr, 0);
    }
    // G3: x = h1 @ ne_w2 + b2
    {
        dim3 g((NODE_D + 63) / 64, (N_NODES + 63) / 64);
        k_sgemm<<<g, 256>>>(p_h1, ne_w2, ne_b2, p_x, N_NODES, NODE_D, H1D, 0);
    }

    // 3 GAT layers
    for (int l = 0; l < DEPTH; l++) {
        k_gat_h<<<N_NODES, 128>>>(gat_w + l * NODE_D * NODE_D,
                                  gat_as + l * NODE_D, gat_ad + l * NODE_D);
        k_edge12<<<(E_EXT + 255) / 256, 256>>>(edge_index);
        k_edge3<<<((E_EXT * 32) + 255) / 256, 256>>>(edge_index);
        k_gat_fin<<<(N_NODES * NODE_D + 255) / 256, 256>>>(gat_b + l * NODE_D);
    }

    // fused edge classifier -> out
    k_final<<<256, 256>>>(edge_index, dp_w, dp_b, ec_w1, ec_b1, ec_w2, ec_b2, out);
}